// round 6
// baseline (speedup 1.0000x reference)
#include <cuda_runtime.h>
#include <cuda_bf16.h>
#include <cstdint>

#define Nn 50000
#define Ee 800000
#define Gg 2048
#define Hh 128

extern __shared__ char dyn_smem[];

// ---------------- device scratch ----------
__device__ float g_Pa[Nn * Hh];    // nf @ e_w1[0:128]
__device__ float g_Pb[Nn * Hh];    // nf @ e_w1[128:256]
__device__ float g_Pc[Nn * Hh];    // nf @ n_w1[0:128] + n_b1
__device__ float g_Qb[Gg * Hh];    // lat @ e_w1[256:262] + e_b1
__device__ float g_agg[Nn * Hh];   // scatter-sum accumulator
__device__ int   g_cnt[Nn];        // per-node edge count

__device__ __forceinline__ float silu_f(float x) {
    return x / (1.0f + __expf(-x));
}

// bf16 hi/lo split of a pair -> packed bf16x2 (hi returned, lo via ref)
__device__ __forceinline__ uint32_t split_pack(float v0, float v1, uint32_t& lo) {
    __nv_bfloat16 h0 = __float2bfloat16_rn(v0);
    __nv_bfloat16 h1 = __float2bfloat16_rn(v1);
    float r0 = v0 - __bfloat162float(h0);
    float r1 = v1 - __bfloat162float(h1);
    __nv_bfloat16 l0 = __float2bfloat16_rn(r0);
    __nv_bfloat16 l1 = __float2bfloat16_rn(r1);
    lo = (uint32_t)__bfloat16_as_ushort(l0) | ((uint32_t)__bfloat16_as_ushort(l1) << 16);
    return (uint32_t)__bfloat16_as_ushort(h0) | ((uint32_t)__bfloat16_as_ushort(h1) << 16);
}

// warp-level bf16 MMA, fp32 accum
__device__ __forceinline__ void mma16816(float* d, const uint32_t* a, const uint32_t* b) {
    asm volatile(
        "mma.sync.aligned.m16n8k16.row.col.f32.bf16.bf16.f32 "
        "{%0,%1,%2,%3}, {%4,%5,%6,%7}, {%8,%9}, {%0,%1,%2,%3};"
        : "+f"(d[0]), "+f"(d[1]), "+f"(d[2]), "+f"(d[3])
        : "r"(a[0]), "r"(a[1]), "r"(a[2]), "r"(a[3]), "r"(b[0]), "r"(b[1]));
}

__device__ __forceinline__ void red_add_v2(float* p, float a, float b) {
    asm volatile("red.global.add.v2.f32 [%0], {%1, %2};"
                 :: "l"(p), "f"(a), "f"(b) : "memory");
}
__device__ __forceinline__ void red_add_v4(float* p, float a, float b, float c, float d) {
    asm volatile("red.global.add.v4.f32 [%0], {%1, %2, %3, %4};"
                 :: "l"(p), "f"(a), "f"(b), "f"(c), "f"(d) : "memory");
}

#define PWS 68   // plane word-stride per row (128 k = 64 pair-words + 4 pad)

// 3-chain hi/lo mma: acc += A(hi+lo) @ B(hi+lo) to ~fp32 accuracy
__device__ __forceinline__ void mma3(float* acc, const uint32_t* ah, const uint32_t* al,
                                     const uint32_t* bh, const uint32_t* bl) {
    mma16816(acc, ah, bh);
    mma16816(acc, al, bh);
    mma16816(acc, ah, bl);
}

__device__ __forceinline__ void load_afrag(uint32_t* ah, uint32_t* al,
                                           const uint32_t* AHI, const uint32_t* ALO,
                                           int ar0, int ar1, int kw) {
    ah[0] = AHI[ar0 + kw];     ah[1] = AHI[ar1 + kw];
    ah[2] = AHI[ar0 + kw + 4]; ah[3] = AHI[ar1 + kw + 4];
    al[0] = ALO[ar0 + kw];     al[1] = ALO[ar1 + kw];
    al[2] = ALO[ar0 + kw + 4]; al[3] = ALO[ar1 + kw + 4];
}

// ---------------------------------------------------------------------------
// Kernel 1 (mma): Pa/Pb/Pc precompute + zero agg/cnt. 128 rows per block.
// ---------------------------------------------------------------------------
#define P_BHI 0
#define P_BLO 8704
#define P_AHI 17408
#define P_ALO 26112
#define P_NB1 34816
#define PREP_SMEM_BYTES ((P_NB1 + 128) * 4)   // 139,776 B

__launch_bounds__(512, 1)
__global__ void prep_node_kernel(const float* __restrict__ nf,
                                 const float* __restrict__ e_w1,
                                 const float* __restrict__ n_w1,
                                 const float* __restrict__ n_b1)
{
    uint32_t* smw = (uint32_t*)dyn_smem;
    uint32_t* BHI = smw + P_BHI;
    uint32_t* BLO = smw + P_BLO;
    uint32_t* AHI = smw + P_AHI;
    uint32_t* ALO = smw + P_ALO;
    float*    NB1 = (float*)(smw + P_NB1);

    const int tid  = threadIdx.x;
    const int wid  = tid >> 5;
    const int lane = tid & 31;
    const int gid  = lane >> 2;
    const int tig  = lane & 3;
    const int row0 = blockIdx.x * 128;

    if (tid < 128) NB1[tid] = n_b1[tid];
    if (tid < 128 && row0 + tid < Nn) g_cnt[row0 + tid] = 0;

    for (int idx = tid; idx < 8192; idx += 512) {
        int m = idx >> 6, p = idx & 63, c0 = p << 1;
        int row = row0 + m;
        float v0 = 0.0f, v1 = 0.0f;
        if (row < Nn) {
            const float2 v = *(const float2*)(nf + row * 128 + c0);
            v0 = v.x; v1 = v.y;
            *(float2*)(g_agg + row * 128 + c0) = make_float2(0.0f, 0.0f);
        }
        uint32_t lo, hi = split_pack(v0, v1, lo);
        AHI[m * PWS + p] = hi;
        ALO[m * PWS + p] = lo;
    }

    const int rg  = wid >> 1;      // row-group 0..7
    const int nfh = wid & 1;       // nf half
    const int ar0 = (rg * 16 + gid) * PWS;
    const int ar1 = ar0 + 8 * PWS;
    const int m1  = rg * 16 + gid;
    const int row1 = row0 + m1, row2 = row1 + 8;

    for (int blk = 0; blk < 3; blk++) {
        __syncthreads();
        const float* bsrc = (blk == 0) ? e_w1
                          : (blk == 1) ? (e_w1 + 128 * 128)
                                       : n_w1;
        for (int idx = tid; idx < 8192; idx += 512) {
            int n = idx >> 6, p = idx & 63, k0 = p << 1;
            float v0 = bsrc[k0 * 128 + n];
            float v1 = bsrc[(k0 + 1) * 128 + n];
            uint32_t lo, hi = split_pack(v0, v1, lo);
            BHI[n * PWS + p] = hi;
            BLO[n * PWS + p] = lo;
        }
        __syncthreads();

        float acc[8][4];
#pragma unroll
        for (int j = 0; j < 8; j++)
#pragma unroll
            for (int q = 0; q < 4; q++) acc[j][q] = 0.0f;

#pragma unroll
        for (int ks = 0; ks < 8; ks++) {
            const int kw = ks * 8 + tig;
            uint32_t ah[4], al[4];
            load_afrag(ah, al, AHI, ALO, ar0, ar1, kw);
#pragma unroll
            for (int j = 0; j < 8; j++) {
                const int nr = ((nfh * 8 + j) * 8 + gid) * PWS;
                uint32_t bh[2] = {BHI[nr + kw], BHI[nr + kw + 4]};
                uint32_t bl[2] = {BLO[nr + kw], BLO[nr + kw + 4]};
                mma3(acc[j], ah, al, bh, bl);
            }
        }

        float* dst = (blk == 0) ? g_Pa : (blk == 1) ? g_Pb : g_Pc;
#pragma unroll
        for (int j = 0; j < 8; j++) {
            const int col = (nfh * 8 + j) * 8 + tig * 2;
            float b0 = 0.0f, b1 = 0.0f;
            if (blk == 2) { b0 = NB1[col]; b1 = NB1[col + 1]; }
            if (row1 < Nn)
                *(float2*)(dst + row1 * 128 + col) =
                    make_float2(acc[j][0] + b0, acc[j][1] + b1);
            if (row2 < Nn)
                *(float2*)(dst + row2 * 128 + col) =
                    make_float2(acc[j][2] + b0, acc[j][3] + b1);
        }
    }
}

// ---------------------------------------------------------------------------
// Kernel 2: per-graph lattice term + edge bias 1.
// ---------------------------------------------------------------------------
__global__ void prep_graph_kernel(const float* __restrict__ lat,
                                  const float* __restrict__ e_w1,
                                  const float* __restrict__ e_b1)
{
    const int g = blockIdx.x;
    const int c = threadIdx.x;
    float acc = e_b1[c];
#pragma unroll
    for (int k = 0; k < 6; k++)
        acc += lat[g * 6 + k] * e_w1[(256 + k) * 128 + c];
    g_Qb[g * 128 + c] = acc;
}

// ---------------------------------------------------------------------------
// Kernel 3: fused edge pipeline (mma.sync hi/lo). 256 edges/tile, 512 threads.
// MMA: 4x4 warp grid, each warp 64 rows x 32 cols (4 m-frags x 4 n-frags).
// Epilogue: shfl-pair fragments -> red.global.add.v4 (half the REDG lanes).
// ---------------------------------------------------------------------------
#define TILE_M 256
#define EDGE_NTILES (Ee / TILE_M)      // 3125

#define O_SRC   0
#define O_DST   256
#define O_GS    512
#define O_FDS   768
#define O_B2    1536
#define O_W1D   1664
#define O_AHI   2048
#define O_ALO   (O_AHI + 256 * PWS)
#define O_BHI   (O_ALO + 256 * PWS)
#define O_BLO   (O_BHI + 128 * PWS)
#define EDGE_SMEM_BYTES ((O_BLO + 128 * PWS) * 4)   // 217,088 B

__launch_bounds__(512, 1)
__global__ void edge_kernel(const float* __restrict__ frac_diff,
                            const int*   __restrict__ ei,
                            const int*   __restrict__ e2g,
                            const float* __restrict__ e_w1,
                            const float* __restrict__ e_w2,
                            const float* __restrict__ e_b2)
{
    uint32_t* smw = (uint32_t*)dyn_smem;
    int*   srcs = (int*)(smw + O_SRC);
    int*   dsts = (int*)(smw + O_DST);
    int*   gs   = (int*)(smw + O_GS);
    float* fds  = (float*)(smw + O_FDS);
    float* b2s  = (float*)(smw + O_B2);
    float* w1ds = (float*)(smw + O_W1D);
    uint32_t* AHI = smw + O_AHI;
    uint32_t* ALO = smw + O_ALO;
    uint32_t* BHI = smw + O_BHI;
    uint32_t* BLO = smw + O_BLO;

    const int tid  = threadIdx.x;
    const int wid  = tid >> 5;
    const int lane = tid & 31;
    const int gid  = lane >> 2;
    const int tig  = lane & 3;
    const int wr   = wid >> 2;      // 0..3 row-group (64 rows)
    const int wc   = wid & 3;       // 0..3 col-group (32 cols)

    // one-time: constants + B = W2^T hi/lo planes
    for (int i = tid; i < 384; i += 512) w1ds[i] = e_w1[262 * 128 + i];
    if (tid < 128) b2s[tid] = e_b2[tid];
    for (int idx = tid; idx < 8192; idx += 512) {
        int n = idx >> 6, p = idx & 63, k0 = p << 1;
        float v0 = e_w2[k0 * 128 + n];
        float v1 = e_w2[(k0 + 1) * 128 + n];
        uint32_t lo, hi = split_pack(v0, v1, lo);
        BHI[n * PWS + p] = hi;
        BLO[n * PWS + p] = lo;
    }

    for (int tile = blockIdx.x; tile < EDGE_NTILES; tile += gridDim.x) {
        __syncthreads();
        const int e0 = tile * TILE_M;
        if (tid < 256) {
            int e = e0 + tid;
            int s = ei[e];
            srcs[tid] = s;
            dsts[tid] = ei[Ee + e];
            gs[tid]   = e2g[e];
            atomicAdd(&g_cnt[s], 1);
        }
        for (int i = tid; i < 768; i += 512) fds[i] = frac_diff[e0 * 3 + i];
        __syncthreads();

        // Phase A: e1 tile -> silu -> bf16 hi/lo planes
#pragma unroll 4
        for (int idx = tid; idx < 16384; idx += 512) {
            int m = idx >> 6, p = idx & 63, c0 = p << 1;
            const float2 pa = *(const float2*)(g_Pa + srcs[m] * 128 + c0);
            const float2 pb = *(const float2*)(g_Pb + dsts[m] * 128 + c0);
            const float2 qb = *(const float2*)(g_Qb + gs[m] * 128 + c0);
            float f0 = fds[m * 3], f1 = fds[m * 3 + 1], f2 = fds[m * 3 + 2];
            float v0 = pa.x + pb.x + qb.x
                     + f0 * w1ds[c0] + f1 * w1ds[128 + c0] + f2 * w1ds[256 + c0];
            float v1 = pa.y + pb.y + qb.y
                     + f0 * w1ds[c0 + 1] + f1 * w1ds[129 + c0] + f2 * w1ds[257 + c0];
            v0 = silu_f(v0);
            v1 = silu_f(v1);
            uint32_t lo, hi = split_pack(v0, v1, lo);
            AHI[m * PWS + p] = hi;
            ALO[m * PWS + p] = lo;
        }
        __syncthreads();

        // MMA: 4 m-frags x 4 n-frags per warp
        float acc[4][4][4];
#pragma unroll
        for (int mf = 0; mf < 4; mf++)
#pragma unroll
            for (int nfr = 0; nfr < 4; nfr++)
#pragma unroll
                for (int q = 0; q < 4; q++) acc[mf][nfr][q] = 0.0f;

#pragma unroll
        for (int ks = 0; ks < 8; ks++) {
            const int kw = ks * 8 + tig;
            uint32_t bh[4][2], bl[4][2];
#pragma unroll
            for (int nfr = 0; nfr < 4; nfr++) {
                const int nr = (wc * 32 + nfr * 8 + gid) * PWS + kw;
                bh[nfr][0] = BHI[nr]; bh[nfr][1] = BHI[nr + 4];
                bl[nfr][0] = BLO[nr]; bl[nfr][1] = BLO[nr + 4];
            }
#pragma unroll
            for (int mf = 0; mf < 4; mf++) {
                const int ar0 = (wr * 64 + mf * 16 + gid) * PWS;
                const int ar1 = ar0 + 8 * PWS;
                uint32_t ah[4], al[4];
                load_afrag(ah, al, AHI, ALO, ar0, ar1, kw);
#pragma unroll
                for (int nfr = 0; nfr < 4; nfr++)
                    mma3(acc[mf][nfr], ah, al, bh[nfr], bl[nfr]);
            }
        }

        // Epilogue: bias+silu, shfl-pair into 4-col runs, red.v4 into g_agg
        const bool evn = ((tig & 1) == 0);
#pragma unroll
        for (int mf = 0; mf < 4; mf++) {
            const int m1 = wr * 64 + mf * 16 + gid;
            const int myrow = evn ? m1 : (m1 + 8);
            float* agg = g_agg + srcs[myrow] * 128;
#pragma unroll
            for (int nfr = 0; nfr < 4; nfr++) {
                const int c0 = wc * 32 + nfr * 8 + tig * 2;
                float s0 = silu_f(acc[mf][nfr][0] + b2s[c0]);
                float s1 = silu_f(acc[mf][nfr][1] + b2s[c0 + 1]);
                float s2 = silu_f(acc[mf][nfr][2] + b2s[c0]);
                float s3 = silu_f(acc[mf][nfr][3] + b2s[c0 + 1]);
                float t0 = __shfl_xor_sync(0xFFFFFFFFu, s0, 1);
                float t1 = __shfl_xor_sync(0xFFFFFFFFu, s1, 1);
                float t2 = __shfl_xor_sync(0xFFFFFFFFu, s2, 1);
                float t3 = __shfl_xor_sync(0xFFFFFFFFu, s3, 1);
                if (evn) red_add_v4(agg + c0, s0, s1, t0, t1);       // row m1
                else     red_add_v4(agg + c0 - 2, t2, t3, s2, s3);   // row m1+8
            }
        }
    }
}

// ---------------------------------------------------------------------------
// Kernel 4 (mma): node model + residual, persistent. 128 rows/tile.
// ---------------------------------------------------------------------------
#define N_B1HI 0
#define N_B1LO 8704
#define N_B2HI 17408
#define N_B2LO 26112
#define N_AHI  34816
#define N_ALO  43520
#define N_NB2  52224
#define N_CINV 52352
#define NODE_SMEM_BYTES ((N_CINV + 128) * 4)   // 209,920 B
#define NODE_NTILES ((Nn + 127) / 128)          // 391

__launch_bounds__(512, 1)
__global__ void node_out_kernel(const float* __restrict__ nf,
                                const float* __restrict__ n_w1,
                                const float* __restrict__ n_w2,
                                const float* __restrict__ n_b2,
                                float* __restrict__ out)
{
    uint32_t* smw  = (uint32_t*)dyn_smem;
    uint32_t* B1HI = smw + N_B1HI;
    uint32_t* B1LO = smw + N_B1LO;
    uint32_t* B2HI = smw + N_B2HI;
    uint32_t* B2LO = smw + N_B2LO;
    uint32_t* AHI  = smw + N_AHI;
    uint32_t* ALO  = smw + N_ALO;
    float*    NB2  = (float*)(smw + N_NB2);
    float*    cinv = (float*)(smw + N_CINV);

    const int tid  = threadIdx.x;
    const int wid  = tid >> 5;
    const int lane = tid & 31;
    const int gid  = lane >> 2;
    const int tig  = lane & 3;

    if (tid < 128) NB2[tid] = n_b2[tid];
    for (int idx = tid; idx < 8192; idx += 512) {
        int n = idx >> 6, p = idx & 63, k0 = p << 1;
        float v0 = n_w1[(128 + k0) * 128 + n];
        float v1 = n_w1[(129 + k0) * 128 + n];
        uint32_t lo, hi = split_pack(v0, v1, lo);
        B1HI[n * PWS + p] = hi;
        B1LO[n * PWS + p] = lo;
        v0 = n_w2[k0 * 128 + n];
        v1 = n_w2[(k0 + 1) * 128 + n];
        hi = split_pack(v0, v1, lo);
        B2HI[n * PWS + p] = hi;
        B2LO[n * PWS + p] = lo;
    }

    const int rg  = wid >> 1;
    const int nfh = wid & 1;
    const int ar0 = (rg * 16 + gid) * PWS;
    const int ar1 = ar0 + 8 * PWS;
    const int m1  = rg * 16 + gid;
    const int m2  = m1 + 8;

    for (int tile = blockIdx.x; tile < NODE_NTILES; tile += gridDim.x) {
        const int row0 = tile * 128;
        __syncthreads();
        if (tid < 128) {
            int row = row0 + tid;
            cinv[tid] = (row < Nn) ? 1.0f / fmaxf((float)g_cnt[row], 1.0f) : 0.0f;
        }
        __syncthreads();

        for (int idx = tid; idx < 8192; idx += 512) {
            int m = idx >> 6, p = idx & 63, c0 = p << 1;
            int row = row0 + m;
            float v0 = 0.0f, v1 = 0.0f;
            if (row < Nn) {
                const float2 v = *(const float2*)(g_agg + row * 128 + c0);
                v0 = v.x * cinv[m]; v1 = v.y * cinv[m];
            }
            uint32_t lo, hi = split_pack(v0, v1, lo);
            AHI[m * PWS + p] = hi;
            ALO[m * PWS + p] = lo;
        }
        __syncthreads();

        float acc[8][4];
#pragma unroll
        for (int j = 0; j < 8; j++)
#pragma unroll
            for (int q = 0; q < 4; q++) acc[j][q] = 0.0f;
#pragma unroll
        for (int ks = 0; ks < 8; ks++) {
            const int kw = ks * 8 + tig;
            uint32_t ah[4], al[4];
            load_afrag(ah, al, AHI, ALO, ar0, ar1, kw);
#pragma unroll
            for (int j = 0; j < 8; j++) {
                const int nr = ((nfh * 8 + j) * 8 + gid) * PWS;
                uint32_t bh[2] = {B1HI[nr + kw], B1HI[nr + kw + 4]};
                uint32_t bl[2] = {B1LO[nr + kw], B1LO[nr + kw + 4]};
                mma3(acc[j], ah, al, bh, bl);
            }
        }
        __syncthreads();

        const int row1 = row0 + m1, row2 = row0 + m2;
#pragma unroll
        for (int j = 0; j < 8; j++) {
            const int col = (nfh * 8 + j) * 8 + tig * 2;
            const int p = col >> 1;
            float2 pc1 = make_float2(0.0f, 0.0f), pc2 = make_float2(0.0f, 0.0f);
            if (row1 < Nn) pc1 = *(const float2*)(g_Pc + row1 * 128 + col);
            if (row2 < Nn) pc2 = *(const float2*)(g_Pc + row2 * 128 + col);
            float h0 = silu_f(acc[j][0] + pc1.x);
            float h1v = silu_f(acc[j][1] + pc1.y);
            float h2 = silu_f(acc[j][2] + pc2.x);
            float h3 = silu_f(acc[j][3] + pc2.y);
            uint32_t lo, hi = split_pack(h0, h1v, lo);
            AHI[m1 * PWS + p] = hi; ALO[m1 * PWS + p] = lo;
            hi = split_pack(h2, h3, lo);
            AHI[m2 * PWS + p] = hi; ALO[m2 * PWS + p] = lo;
        }
        __syncthreads();

        float acc2[8][4];
#pragma unroll
        for (int j = 0; j < 8; j++)
#pragma unroll
            for (int q = 0; q < 4; q++) acc2[j][q] = 0.0f;
#pragma unroll
        for (int ks = 0; ks < 8; ks++) {
            const int kw = ks * 8 + tig;
            uint32_t ah[4], al[4];
            load_afrag(ah, al, AHI, ALO, ar0, ar1, kw);
#pragma unroll
            for (int j = 0; j < 8; j++) {
                const int nr = ((nfh * 8 + j) * 8 + gid) * PWS;
                uint32_t bh[2] = {B2HI[nr + kw], B2HI[nr + kw + 4]};
                uint32_t bl[2] = {B2LO[nr + kw], B2LO[nr + kw + 4]};
                mma3(acc2[j], ah, al, bh, bl);
            }
        }

#pragma unroll
        for (int j = 0; j < 8; j++) {
            const int col = (nfh * 8 + j) * 8 + tig * 2;
            float b0 = NB2[col], b1 = NB2[col + 1];
            if (row1 < Nn) {
                const float2 x = *(const float2*)(nf + row1 * 128 + col);
                *(float2*)(out + row1 * 128 + col) =
                    make_float2(x.x + silu_f(acc2[j][0] + b0),
                                x.y + silu_f(acc2[j][1] + b1));
            }
            if (row2 < Nn) {
                const float2 x = *(const float2*)(nf + row2 * 128 + col);
                *(float2*)(out + row2 * 128 + col) =
                    make_float2(x.x + silu_f(acc2[j][2] + b0),
                                x.y + silu_f(acc2[j][3] + b1));
            }
        }
    }
}

// ---------------------------------------------------------------------------
extern "C" void kernel_launch(void* const* d_in, const int* in_sizes, int n_in,
                              void* d_out, int out_size)
{
    (void)in_sizes; (void)n_in; (void)out_size;
    const float* nf   = (const float*)d_in[0];
    const float* lat  = (const float*)d_in[2];
    const float* fd   = (const float*)d_in[3];
    const int*   ei   = (const int*)d_in[4];
    const int*   e2g  = (const int*)d_in[5];
    const float* e_w1 = (const float*)d_in[6];
    const float* e_b1 = (const float*)d_in[7];
    const float* e_w2 = (const float*)d_in[8];
    const float* e_b2 = (const float*)d_in[9];
    const float* n_w1 = (const float*)d_in[10];
    const float* n_b1 = (const float*)d_in[11];
    const float* n_w2 = (const float*)d_in[12];
    const float* n_b2 = (const float*)d_in[13];
    float* out = (float*)d_out;

    cudaFuncSetAttribute(prep_node_kernel,
                         cudaFuncAttributeMaxDynamicSharedMemorySize,
                         PREP_SMEM_BYTES);
    cudaFuncSetAttribute(edge_kernel,
                         cudaFuncAttributeMaxDynamicSharedMemorySize,
                         EDGE_SMEM_BYTES);
    cudaFuncSetAttribute(node_out_kernel,
                         cudaFuncAttributeMaxDynamicSharedMemorySize,
                         NODE_SMEM_BYTES);

    prep_node_kernel<<<NODE_NTILES, 512, PREP_SMEM_BYTES>>>(nf, e_w1, n_w1, n_b1);
    prep_graph_kernel<<<Gg, 128>>>(lat, e_w1, e_b1);
    edge_kernel<<<148, 512, EDGE_SMEM_BYTES>>>(fd, ei, e2g, e_w1, e_w2, e_b2);
    node_out_kernel<<<148, 512, NODE_SMEM_BYTES>>>(nf, n_w1, n_w2, n_b2, out);
}

// round 7
// speedup vs baseline: 1.0172x; 1.0172x over previous
#include <cuda_runtime.h>
#include <cuda_bf16.h>
#include <cstdint>

#define Nn 50000
#define Ee 800000
#define Gg 2048
#define Hh 128

extern __shared__ char dyn_smem[];

// ---------------- device scratch ----------
__device__ float g_Pa[Nn * Hh];    // nf @ e_w1[0:128]
__device__ float g_Pb[Nn * Hh];    // nf @ e_w1[128:256]
__device__ float g_Pc[Nn * Hh];    // nf @ n_w1[0:128] + n_b1
__device__ float g_Qb[Gg * Hh];    // lat @ e_w1[256:262] + e_b1
__device__ float g_agg[Nn * Hh];   // scatter-sum accumulator
__device__ int   g_cnt[Nn];        // per-node edge count

__device__ __forceinline__ float silu_f(float x) {
    return x / (1.0f + __expf(-x));
}

__device__ __forceinline__ uint32_t split_pack(float v0, float v1, uint32_t& lo) {
    __nv_bfloat16 h0 = __float2bfloat16_rn(v0);
    __nv_bfloat16 h1 = __float2bfloat16_rn(v1);
    float r0 = v0 - __bfloat162float(h0);
    float r1 = v1 - __bfloat162float(h1);
    __nv_bfloat16 l0 = __float2bfloat16_rn(r0);
    __nv_bfloat16 l1 = __float2bfloat16_rn(r1);
    lo = (uint32_t)__bfloat16_as_ushort(l0) | ((uint32_t)__bfloat16_as_ushort(l1) << 16);
    return (uint32_t)__bfloat16_as_ushort(h0) | ((uint32_t)__bfloat16_as_ushort(h1) << 16);
}

__device__ __forceinline__ void mma16816(float* d, const uint32_t* a, const uint32_t* b) {
    asm volatile(
        "mma.sync.aligned.m16n8k16.row.col.f32.bf16.bf16.f32 "
        "{%0,%1,%2,%3}, {%4,%5,%6,%7}, {%8,%9}, {%0,%1,%2,%3};"
        : "+f"(d[0]), "+f"(d[1]), "+f"(d[2]), "+f"(d[3])
        : "r"(a[0]), "r"(a[1]), "r"(a[2]), "r"(a[3]), "r"(b[0]), "r"(b[1]));
}

__device__ __forceinline__ void red_add_v4(float* p, float a, float b, float c, float d) {
    asm volatile("red.global.add.v4.f32 [%0], {%1, %2, %3, %4};"
                 :: "l"(p), "f"(a), "f"(b), "f"(c), "f"(d) : "memory");
}

#define PWS 68

__device__ __forceinline__ void mma3(float* acc, const uint32_t* ah, const uint32_t* al,
                                     const uint32_t* bh, const uint32_t* bl) {
    mma16816(acc, ah, bh);
    mma16816(acc, al, bh);
    mma16816(acc, ah, bl);
}

__device__ __forceinline__ void load_afrag(uint32_t* ah, uint32_t* al,
                                           const uint32_t* AHI, const uint32_t* ALO,
                                           int ar0, int ar1, int kw) {
    ah[0] = AHI[ar0 + kw];     ah[1] = AHI[ar1 + kw];
    ah[2] = AHI[ar0 + kw + 4]; ah[3] = AHI[ar1 + kw + 4];
    al[0] = ALO[ar0 + kw];     al[1] = ALO[ar1 + kw];
    al[2] = ALO[ar0 + kw + 4]; al[3] = ALO[ar1 + kw + 4];
}

// ---------------------------------------------------------------------------
// Kernel 1 (mma): Pa/Pb/Pc precompute + zero agg/cnt. 128 rows per block.
// ---------------------------------------------------------------------------
#define P_BHI 0
#define P_BLO 8704
#define P_AHI 17408
#define P_ALO 26112
#define P_NB1 34816
#define PREP_SMEM_BYTES ((P_NB1 + 128) * 4)   // 139,776 B

__launch_bounds__(512, 1)
__global__ void prep_node_kernel(const float* __restrict__ nf,
                                 const float* __restrict__ e_w1,
                                 const float* __restrict__ n_w1,
                                 const float* __restrict__ n_b1)
{
    uint32_t* smw = (uint32_t*)dyn_smem;
    uint32_t* BHI = smw + P_BHI;
    uint32_t* BLO = smw + P_BLO;
    uint32_t* AHI = smw + P_AHI;
    uint32_t* ALO = smw + P_ALO;
    float*    NB1 = (float*)(smw + P_NB1);

    const int tid  = threadIdx.x;
    const int wid  = tid >> 5;
    const int lane = tid & 31;
    const int gid  = lane >> 2;
    const int tig  = lane & 3;
    const int row0 = blockIdx.x * 128;

    if (tid < 128) NB1[tid] = n_b1[tid];
    if (tid < 128 && row0 + tid < Nn) g_cnt[row0 + tid] = 0;

    for (int idx = tid; idx < 8192; idx += 512) {
        int m = idx >> 6, p = idx & 63, c0 = p << 1;
        int row = row0 + m;
        float v0 = 0.0f, v1 = 0.0f;
        if (row < Nn) {
            const float2 v = *(const float2*)(nf + row * 128 + c0);
            v0 = v.x; v1 = v.y;
            *(float2*)(g_agg + row * 128 + c0) = make_float2(0.0f, 0.0f);
        }
        uint32_t lo, hi = split_pack(v0, v1, lo);
        AHI[m * PWS + p] = hi;
        ALO[m * PWS + p] = lo;
    }

    const int rg  = wid >> 1;
    const int nfh = wid & 1;
    const int ar0 = (rg * 16 + gid) * PWS;
    const int ar1 = ar0 + 8 * PWS;
    const int m1  = rg * 16 + gid;
    const int row1 = row0 + m1, row2 = row1 + 8;

    for (int blk = 0; blk < 3; blk++) {
        __syncthreads();
        const float* bsrc = (blk == 0) ? e_w1
                          : (blk == 1) ? (e_w1 + 128 * 128)
                                       : n_w1;
        for (int idx = tid; idx < 8192; idx += 512) {
            int n = idx >> 6, p = idx & 63, k0 = p << 1;
            float v0 = bsrc[k0 * 128 + n];
            float v1 = bsrc[(k0 + 1) * 128 + n];
            uint32_t lo, hi = split_pack(v0, v1, lo);
            BHI[n * PWS + p] = hi;
            BLO[n * PWS + p] = lo;
        }
        __syncthreads();

        float acc[8][4];
#pragma unroll
        for (int j = 0; j < 8; j++)
#pragma unroll
            for (int q = 0; q < 4; q++) acc[j][q] = 0.0f;

#pragma unroll
        for (int ks = 0; ks < 8; ks++) {
            const int kw = ks * 8 + tig;
            uint32_t ah[4], al[4];
            load_afrag(ah, al, AHI, ALO, ar0, ar1, kw);
#pragma unroll
            for (int j = 0; j < 8; j++) {
                const int nr = ((nfh * 8 + j) * 8 + gid) * PWS;
                uint32_t bh[2] = {BHI[nr + kw], BHI[nr + kw + 4]};
                uint32_t bl[2] = {BLO[nr + kw], BLO[nr + kw + 4]};
                mma3(acc[j], ah, al, bh, bl);
            }
        }

        float* dst = (blk == 0) ? g_Pa : (blk == 1) ? g_Pb : g_Pc;
#pragma unroll
        for (int j = 0; j < 8; j++) {
            const int col = (nfh * 8 + j) * 8 + tig * 2;
            float b0 = 0.0f, b1 = 0.0f;
            if (blk == 2) { b0 = NB1[col]; b1 = NB1[col + 1]; }
            if (row1 < Nn)
                *(float2*)(dst + row1 * 128 + col) =
                    make_float2(acc[j][0] + b0, acc[j][1] + b1);
            if (row2 < Nn)
                *(float2*)(dst + row2 * 128 + col) =
                    make_float2(acc[j][2] + b0, acc[j][3] + b1);
        }
    }
}

// ---------------------------------------------------------------------------
// Kernel 2: per-graph lattice term + edge bias 1.
// ---------------------------------------------------------------------------
__global__ void prep_graph_kernel(const float* __restrict__ lat,
                                  const float* __restrict__ e_w1,
                                  const float* __restrict__ e_b1)
{
    const int g = blockIdx.x;
    const int c = threadIdx.x;
    float acc = e_b1[c];
#pragma unroll
    for (int k = 0; k < 6; k++)
        acc += lat[g * 6 + k] * e_w1[(256 + k) * 128 + c];
    g_Qb[g * 128 + c] = acc;
}

// ---------------------------------------------------------------------------
// Kernel 3: fused edge pipeline. 64 edges/tile, 256 threads, 2 CTAs/SM.
// Two CTAs per SM overlap their phases: while one waits at a barrier or on
// L2-gather/REDG latency, the other issues MMA — attacks exposed latency.
// Warp grid 2x4: each warp 32 rows (2 m-frags) x 32 cols (4 n-frags).
// ---------------------------------------------------------------------------
#define TILE_M 64
#define EDGE_NTILES (Ee / TILE_M)      // 12500

#define O_SRC   0
#define O_DST   64
#define O_GS    128
#define O_FDS   192
#define O_B2    384
#define O_W1D   512
#define O_AHI   896
#define O_ALO   (O_AHI + 64 * PWS)
#define O_BHI   (O_ALO + 64 * PWS)
#define O_BLO   (O_BHI + 128 * PWS)
#define EDGE_SMEM_BYTES ((O_BLO + 128 * PWS) * 4)   // 108,032 B

__launch_bounds__(256, 2)
__global__ void edge_kernel(const float* __restrict__ frac_diff,
                            const int*   __restrict__ ei,
                            const int*   __restrict__ e2g,
                            const float* __restrict__ e_w1,
                            const float* __restrict__ e_w2,
                            const float* __restrict__ e_b2)
{
    uint32_t* smw = (uint32_t*)dyn_smem;
    int*   srcs = (int*)(smw + O_SRC);
    int*   dsts = (int*)(smw + O_DST);
    int*   gs   = (int*)(smw + O_GS);
    float* fds  = (float*)(smw + O_FDS);
    float* b2s  = (float*)(smw + O_B2);
    float* w1ds = (float*)(smw + O_W1D);
    uint32_t* AHI = smw + O_AHI;
    uint32_t* ALO = smw + O_ALO;
    uint32_t* BHI = smw + O_BHI;
    uint32_t* BLO = smw + O_BLO;

    const int tid  = threadIdx.x;
    const int wid  = tid >> 5;
    const int lane = tid & 31;
    const int gid  = lane >> 2;
    const int tig  = lane & 3;
    const int wr   = wid >> 2;      // 0..1 row-group (32 rows)
    const int wc   = wid & 3;       // 0..3 col-group (32 cols)

    // one-time: constants + B = W2^T hi/lo planes
    for (int i = tid; i < 384; i += 256) w1ds[i] = e_w1[262 * 128 + i];
    if (tid < 128) b2s[tid] = e_b2[tid];
    for (int idx = tid; idx < 8192; idx += 256) {
        int n = idx >> 6, p = idx & 63, k0 = p << 1;
        float v0 = e_w2[k0 * 128 + n];
        float v1 = e_w2[(k0 + 1) * 128 + n];
        uint32_t lo, hi = split_pack(v0, v1, lo);
        BHI[n * PWS + p] = hi;
        BLO[n * PWS + p] = lo;
    }

    for (int tile = blockIdx.x; tile < EDGE_NTILES; tile += gridDim.x) {
        __syncthreads();
        const int e0 = tile * TILE_M;
        if (tid < 64) {
            int e = e0 + tid;
            int s = ei[e];
            srcs[tid] = s;
            dsts[tid] = ei[Ee + e];
            gs[tid]   = e2g[e];
            atomicAdd(&g_cnt[s], 1);
        } else if (tid < 256) {
            int i = tid - 64;
            if (i < 192) fds[i] = frac_diff[e0 * 3 + i];
        }
        __syncthreads();

        // Phase A: e1 tile -> silu -> bf16 hi/lo planes
#pragma unroll 4
        for (int idx = tid; idx < 4096; idx += 256) {
            int m = idx >> 6, p = idx & 63, c0 = p << 1;
            const float2 pa = *(const float2*)(g_Pa + srcs[m] * 128 + c0);
            const float2 pb = *(const float2*)(g_Pb + dsts[m] * 128 + c0);
            const float2 qb = *(const float2*)(g_Qb + gs[m] * 128 + c0);
            float f0 = fds[m * 3], f1 = fds[m * 3 + 1], f2 = fds[m * 3 + 2];
            float v0 = pa.x + pb.x + qb.x
                     + f0 * w1ds[c0] + f1 * w1ds[128 + c0] + f2 * w1ds[256 + c0];
            float v1 = pa.y + pb.y + qb.y
                     + f0 * w1ds[c0 + 1] + f1 * w1ds[129 + c0] + f2 * w1ds[257 + c0];
            v0 = silu_f(v0);
            v1 = silu_f(v1);
            uint32_t lo, hi = split_pack(v0, v1, lo);
            AHI[m * PWS + p] = hi;
            ALO[m * PWS + p] = lo;
        }
        __syncthreads();

        // MMA: 2 m-frags x 4 n-frags per warp
        float acc[2][4][4];
#pragma unroll
        for (int mf = 0; mf < 2; mf++)
#pragma unroll
            for (int nfr = 0; nfr < 4; nfr++)
#pragma unroll
                for (int q = 0; q < 4; q++) acc[mf][nfr][q] = 0.0f;

#pragma unroll
        for (int ks = 0; ks < 8; ks++) {
            const int kw = ks * 8 + tig;
            uint32_t bh[4][2], bl[4][2];
#pragma unroll
            for (int nfr = 0; nfr < 4; nfr++) {
                const int nr = (wc * 32 + nfr * 8 + gid) * PWS + kw;
                bh[nfr][0] = BHI[nr]; bh[nfr][1] = BHI[nr + 4];
                bl[nfr][0] = BLO[nr]; bl[nfr][1] = BLO[nr + 4];
            }
#pragma unroll
            for (int mf = 0; mf < 2; mf++) {
                const int ar0 = (wr * 32 + mf * 16 + gid) * PWS;
                const int ar1 = ar0 + 8 * PWS;
                uint32_t ah[4], al[4];
                load_afrag(ah, al, AHI, ALO, ar0, ar1, kw);
#pragma unroll
                for (int nfr = 0; nfr < 4; nfr++)
                    mma3(acc[mf][nfr], ah, al, bh[nfr], bl[nfr]);
            }
        }

        // Epilogue: bias+silu, shfl-pair into 4-col runs, red.v4 into g_agg
        const bool evn = ((tig & 1) == 0);
#pragma unroll
        for (int mf = 0; mf < 2; mf++) {
            const int m1 = wr * 32 + mf * 16 + gid;
            const int myrow = evn ? m1 : (m1 + 8);
            float* agg = g_agg + srcs[myrow] * 128;
#pragma unroll
            for (int nfr = 0; nfr < 4; nfr++) {
                const int c0 = wc * 32 + nfr * 8 + tig * 2;
                float s0 = silu_f(acc[mf][nfr][0] + b2s[c0]);
                float s1 = silu_f(acc[mf][nfr][1] + b2s[c0 + 1]);
                float s2 = silu_f(acc[mf][nfr][2] + b2s[c0]);
                float s3 = silu_f(acc[mf][nfr][3] + b2s[c0 + 1]);
                float t0 = __shfl_xor_sync(0xFFFFFFFFu, s0, 1);
                float t1 = __shfl_xor_sync(0xFFFFFFFFu, s1, 1);
                float t2 = __shfl_xor_sync(0xFFFFFFFFu, s2, 1);
                float t3 = __shfl_xor_sync(0xFFFFFFFFu, s3, 1);
                if (evn) red_add_v4(agg + c0, s0, s1, t0, t1);       // row m1
                else     red_add_v4(agg + c0 - 2, t2, t3, s2, s3);   // row m1+8
            }
        }
    }
}

// ---------------------------------------------------------------------------
// Kernel 4 (mma): node model + residual, persistent. 128 rows/tile.
// ---------------------------------------------------------------------------
#define N_B1HI 0
#define N_B1LO 8704
#define N_B2HI 17408
#define N_B2LO 26112
#define N_AHI  34816
#define N_ALO  43520
#define N_NB2  52224
#define N_CINV 52352
#define NODE_SMEM_BYTES ((N_CINV + 128) * 4)   // 209,920 B
#define NODE_NTILES ((Nn + 127) / 128)          // 391

__launch_bounds__(512, 1)
__global__ void node_out_kernel(const float* __restrict__ nf,
                                const float* __restrict__ n_w1,
                                const float* __restrict__ n_w2,
                                const float* __restrict__ n_b2,
                                float* __restrict__ out)
{
    uint32_t* smw  = (uint32_t*)dyn_smem;
    uint32_t* B1HI = smw + N_B1HI;
    uint32_t* B1LO = smw + N_B1LO;
    uint32_t* B2HI = smw + N_B2HI;
    uint32_t* B2LO = smw + N_B2LO;
    uint32_t* AHI  = smw + N_AHI;
    uint32_t* ALO  = smw + N_ALO;
    float*    NB2  = (float*)(smw + N_NB2);
    float*    cinv = (float*)(smw + N_CINV);

    const int tid  = threadIdx.x;
    const int wid  = tid >> 5;
    const int lane = tid & 31;
    const int gid  = lane >> 2;
    const int tig  = lane & 3;

    if (tid < 128) NB2[tid] = n_b2[tid];
    for (int idx = tid; idx < 8192; idx += 512) {
        int n = idx >> 6, p = idx & 63, k0 = p << 1;
        float v0 = n_w1[(128 + k0) * 128 + n];
        float v1 = n_w1[(129 + k0) * 128 + n];
        uint32_t lo, hi = split_pack(v0, v1, lo);
        B1HI[n * PWS + p] = hi;
        B1LO[n * PWS + p] = lo;
        v0 = n_w2[k0 * 128 + n];
        v1 = n_w2[(k0 + 1) * 128 + n];
        hi = split_pack(v0, v1, lo);
        B2HI[n * PWS + p] = hi;
        B2LO[n * PWS + p] = lo;
    }

    const int rg  = wid >> 1;
    const int nfh = wid & 1;
    const int ar0 = (rg * 16 + gid) * PWS;
    const int ar1 = ar0 + 8 * PWS;
    const int m1  = rg * 16 + gid;
    const int m2  = m1 + 8;

    for (int tile = blockIdx.x; tile < NODE_NTILES; tile += gridDim.x) {
        const int row0 = tile * 128;
        __syncthreads();
        if (tid < 128) {
            int row = row0 + tid;
            cinv[tid] = (row < Nn) ? 1.0f / fmaxf((float)g_cnt[row], 1.0f) : 0.0f;
        }
        __syncthreads();

        for (int idx = tid; idx < 8192; idx += 512) {
            int m = idx >> 6, p = idx & 63, c0 = p << 1;
            int row = row0 + m;
            float v0 = 0.0f, v1 = 0.0f;
            if (row < Nn) {
                const float2 v = *(const float2*)(g_agg + row * 128 + c0);
                v0 = v.x * cinv[m]; v1 = v.y * cinv[m];
            }
            uint32_t lo, hi = split_pack(v0, v1, lo);
            AHI[m * PWS + p] = hi;
            ALO[m * PWS + p] = lo;
        }
        __syncthreads();

        float acc[8][4];
#pragma unroll
        for (int j = 0; j < 8; j++)
#pragma unroll
            for (int q = 0; q < 4; q++) acc[j][q] = 0.0f;
#pragma unroll
        for (int ks = 0; ks < 8; ks++) {
            const int kw = ks * 8 + tig;
            uint32_t ah[4], al[4];
            load_afrag(ah, al, AHI, ALO, ar0, ar1, kw);
#pragma unroll
            for (int j = 0; j < 8; j++) {
                const int nr = ((nfh * 8 + j) * 8 + gid) * PWS;
                uint32_t bh[2] = {B1HI[nr + kw], B1HI[nr + kw + 4]};
                uint32_t bl[2] = {B1LO[nr + kw], B1LO[nr + kw + 4]};
                mma3(acc[j], ah, al, bh, bl);
            }
        }
        __syncthreads();

        const int row1 = row0 + m1, row2 = row0 + m2;
#pragma unroll
        for (int j = 0; j < 8; j++) {
            const int col = (nfh * 8 + j) * 8 + tig * 2;
            const int p = col >> 1;
            float2 pc1 = make_float2(0.0f, 0.0f), pc2 = make_float2(0.0f, 0.0f);
            if (row1 < Nn) pc1 = *(const float2*)(g_Pc + row1 * 128 + col);
            if (row2 < Nn) pc2 = *(const float2*)(g_Pc + row2 * 128 + col);
            float h0 = silu_f(acc[j][0] + pc1.x);
            float h1v = silu_f(acc[j][1] + pc1.y);
            float h2 = silu_f(acc[j][2] + pc2.x);
            float h3 = silu_f(acc[j][3] + pc2.y);
            uint32_t lo, hi = split_pack(h0, h1v, lo);
            AHI[m1 * PWS + p] = hi; ALO[m1 * PWS + p] = lo;
            hi = split_pack(h2, h3, lo);
            AHI[m2 * PWS + p] = hi; ALO[m2 * PWS + p] = lo;
        }
        __syncthreads();

        float acc2[8][4];
#pragma unroll
        for (int j = 0; j < 8; j++)
#pragma unroll
            for (int q = 0; q < 4; q++) acc2[j][q] = 0.0f;
#pragma unroll
        for (int ks = 0; ks < 8; ks++) {
            const int kw = ks * 8 + tig;
            uint32_t ah[4], al[4];
            load_afrag(ah, al, AHI, ALO, ar0, ar1, kw);
#pragma unroll
            for (int j = 0; j < 8; j++) {
                const int nr = ((nfh * 8 + j) * 8 + gid) * PWS;
                uint32_t bh[2] = {B2HI[nr + kw], B2HI[nr + kw + 4]};
                uint32_t bl[2] = {B2LO[nr + kw], B2LO[nr + kw + 4]};
                mma3(acc2[j], ah, al, bh, bl);
            }
        }

#pragma unroll
        for (int j = 0; j < 8; j++) {
            const int col = (nfh * 8 + j) * 8 + tig * 2;
            float b0 = NB2[col], b1 = NB2[col + 1];
            if (row1 < Nn) {
                const float2 x = *(const float2*)(nf + row1 * 128 + col);
                *(float2*)(out + row1 * 128 + col) =
                    make_float2(x.x + silu_f(acc2[j][0] + b0),
                                x.y + silu_f(acc2[j][1] + b1));
            }
            if (row2 < Nn) {
                const float2 x = *(const float2*)(nf + row2 * 128 + col);
                *(float2*)(out + row2 * 128 + col) =
                    make_float2(x.x + silu_f(acc2[j][2] + b0),
                                x.y + silu_f(acc2[j][3] + b1));
            }
        }
    }
}

// ---------------------------------------------------------------------------
extern "C" void kernel_launch(void* const* d_in, const int* in_sizes, int n_in,
                              void* d_out, int out_size)
{
    (void)in_sizes; (void)n_in; (void)out_size;
    const float* nf   = (const float*)d_in[0];
    const float* lat  = (const float*)d_in[2];
    const float* fd   = (const float*)d_in[3];
    const int*   ei   = (const int*)d_in[4];
    const int*   e2g  = (const int*)d_in[5];
    const float* e_w1 = (const float*)d_in[6];
    const float* e_b1 = (const float*)d_in[7];
    const float* e_w2 = (const float*)d_in[8];
    const float* e_b2 = (const float*)d_in[9];
    const float* n_w1 = (const float*)d_in[10];
    const float* n_b1 = (const float*)d_in[11];
    const float* n_w2 = (const float*)d_in[12];
    const float* n_b2 = (const float*)d_in[13];
    float* out = (float*)d_out;

    cudaFuncSetAttribute(prep_node_kernel,
                         cudaFuncAttributeMaxDynamicSharedMemorySize,
                         PREP_SMEM_BYTES);
    cudaFuncSetAttribute(edge_kernel,
                         cudaFuncAttributeMaxDynamicSharedMemorySize,
                         EDGE_SMEM_BYTES);
    cudaFuncSetAttribute(node_out_kernel,
                         cudaFuncAttributeMaxDynamicSharedMemorySize,
                         NODE_SMEM_BYTES);

    prep_node_kernel<<<NODE_NTILES, 512, PREP_SMEM_BYTES>>>(nf, e_w1, n_w1, n_b1);
    prep_graph_kernel<<<Gg, 128>>>(lat, e_w1, e_b1);
    edge_kernel<<<296, 256, EDGE_SMEM_BYTES>>>(fd, ei, e2g, e_w1, e_w2, e_b2);
    node_out_kernel<<<148, 512, NODE_SMEM_BYTES>>>(nf, n_w1, n_w2, n_b2, out);
}

// round 8
// speedup vs baseline: 1.1171x; 1.0982x over previous
#include <cuda_runtime.h>
#include <cuda_fp16.h>
#include <cstdint>
#include <cstring>

#define Nn 50000
#define Ee 800000
#define Gg 2048
#define Hh 128

extern __shared__ char dyn_smem[];

// ---------------- device scratch ----------
__device__ float g_Pa[Nn * Hh];    // nf @ e_w1[0:128]
__device__ float g_Pb[Nn * Hh];    // nf @ e_w1[128:256]
__device__ float g_Pc[Nn * Hh];    // nf @ n_w1[0:128] + n_b1
__device__ float g_Qb[Gg * Hh];    // lat @ e_w1[256:262] + e_b1
__device__ float g_agg[Nn * Hh];   // scatter-sum accumulator
__device__ int   g_cnt[Nn];        // per-node edge count

__device__ __forceinline__ float silu_f(float x) {
    return x / (1.0f + __expf(-x));
}

// pack two floats -> fp16x2 word (v0 -> lo, v1 -> hi)
__device__ __forceinline__ uint32_t pack_h2(float v0, float v1) {
    __half2 h = __floats2half2_rn(v0, v1);
    uint32_t u;
    memcpy(&u, &h, 4);
    return u;
}

// fp16 hi/lo split of a pair (for weights, built once)
__device__ __forceinline__ void split_pack_h(float v0, float v1,
                                             uint32_t& hi_w, uint32_t& lo_w) {
    __half h0 = __float2half_rn(v0), h1 = __float2half_rn(v1);
    float r0 = v0 - __half2float(h0);
    float r1 = v1 - __half2float(h1);
    __half2 hh = __halves2half2(h0, h1);
    __half2 ll = __halves2half2(__float2half_rn(r0), __float2half_rn(r1));
    memcpy(&hi_w, &hh, 4);
    memcpy(&lo_w, &ll, 4);
}

// warp-level fp16 MMA, fp32 accum (sm_80+, compiles at base sm_103 target)
__device__ __forceinline__ void mma16816h(float* d, const uint32_t* a, const uint32_t* b) {
    asm volatile(
        "mma.sync.aligned.m16n8k16.row.col.f32.f16.f16.f32 "
        "{%0,%1,%2,%3}, {%4,%5,%6,%7}, {%8,%9}, {%0,%1,%2,%3};"
        : "+f"(d[0]), "+f"(d[1]), "+f"(d[2]), "+f"(d[3])
        : "r"(a[0]), "r"(a[1]), "r"(a[2]), "r"(a[3]), "r"(b[0]), "r"(b[1]));
}

__device__ __forceinline__ void red_add_v4(float* p, float a, float b, float c, float d) {
    asm volatile("red.global.add.v4.f32 [%0], {%1, %2, %3, %4};"
                 :: "l"(p), "f"(a), "f"(b), "f"(c), "f"(d) : "memory");
}

#define PWS 68   // plane word-stride per row (64 pair-words + 4 pad)

// 2-chain: acc += A @ (Bh + Bl); A exact-in-fp16, B split hi/lo
__device__ __forceinline__ void mma2(float* acc, const uint32_t* a,
                                     const uint32_t* bh, const uint32_t* bl) {
    mma16816h(acc, a, bh);
    mma16816h(acc, a, bl);
}

// single-plane A fragment load
__device__ __forceinline__ void load_afrag1(uint32_t* a, const uint32_t* A,
                                            int ar0, int ar1, int kw) {
    a[0] = A[ar0 + kw];     a[1] = A[ar1 + kw];
    a[2] = A[ar0 + kw + 4]; a[3] = A[ar1 + kw + 4];
}

// ---------------------------------------------------------------------------
// Kernel 1: Pa/Pb/Pc precompute + zero agg/cnt. 128 rows per block.
// A = nf single fp16 plane; B split hi/lo per output block; 2-chain MMA.
// ---------------------------------------------------------------------------
#define P_BH  0
#define P_BL  8704
#define P_A   17408
#define P_NB1 26112
#define PREP_SMEM_BYTES ((P_NB1 + 128) * 4)   // 104,960 B

__launch_bounds__(512, 1)
__global__ void prep_node_kernel(const float* __restrict__ nf,
                                 const float* __restrict__ e_w1,
                                 const float* __restrict__ n_w1,
                                 const float* __restrict__ n_b1)
{
    uint32_t* smw = (uint32_t*)dyn_smem;
    uint32_t* BH  = smw + P_BH;
    uint32_t* BL  = smw + P_BL;
    uint32_t* A   = smw + P_A;
    float*    NB1 = (float*)(smw + P_NB1);

    const int tid  = threadIdx.x;
    const int wid  = tid >> 5;
    const int lane = tid & 31;
    const int gid  = lane >> 2;
    const int tig  = lane & 3;
    const int row0 = blockIdx.x * 128;

    if (tid < 128) NB1[tid] = n_b1[tid];
    if (tid < 128 && row0 + tid < Nn) g_cnt[row0 + tid] = 0;

    // A plane: nf rows -> fp16; zero g_agg alongside
    for (int idx = tid; idx < 8192; idx += 512) {
        int m = idx >> 6, p = idx & 63, c0 = p << 1;
        int row = row0 + m;
        float v0 = 0.0f, v1 = 0.0f;
        if (row < Nn) {
            const float2 v = *(const float2*)(nf + row * 128 + c0);
            v0 = v.x; v1 = v.y;
            *(float2*)(g_agg + row * 128 + c0) = make_float2(0.0f, 0.0f);
        }
        A[m * PWS + p] = pack_h2(v0, v1);
    }

    const int rg  = wid >> 1;      // 0..7 row-group
    const int nfh = wid & 1;       // output-col half
    const int ar0 = (rg * 16 + gid) * PWS;
    const int ar1 = ar0 + 8 * PWS;
    const int m1  = rg * 16 + gid;
    const int row1 = row0 + m1, row2 = row1 + 8;

    for (int blk = 0; blk < 3; blk++) {
        __syncthreads();
        const float* bsrc = (blk == 0) ? e_w1
                          : (blk == 1) ? (e_w1 + 128 * 128)
                                       : n_w1;
        for (int idx = tid; idx < 8192; idx += 512) {
            int n = idx >> 6, p = idx & 63, k0 = p << 1;
            uint32_t hw, lw;
            split_pack_h(bsrc[k0 * 128 + n], bsrc[(k0 + 1) * 128 + n], hw, lw);
            BH[n * PWS + p] = hw;
            BL[n * PWS + p] = lw;
        }
        __syncthreads();

        float acc[8][4];
#pragma unroll
        for (int j = 0; j < 8; j++)
#pragma unroll
            for (int q = 0; q < 4; q++) acc[j][q] = 0.0f;

#pragma unroll
        for (int ks = 0; ks < 8; ks++) {
            const int kw = ks * 8 + tig;
            uint32_t a[4];
            load_afrag1(a, A, ar0, ar1, kw);
#pragma unroll
            for (int j = 0; j < 8; j++) {
                const int nr = ((nfh * 8 + j) * 8 + gid) * PWS;
                uint32_t bh[2] = {BH[nr + kw], BH[nr + kw + 4]};
                uint32_t bl[2] = {BL[nr + kw], BL[nr + kw + 4]};
                mma2(acc[j], a, bh, bl);
            }
        }

        float* dst = (blk == 0) ? g_Pa : (blk == 1) ? g_Pb : g_Pc;
#pragma unroll
        for (int j = 0; j < 8; j++) {
            const int col = (nfh * 8 + j) * 8 + tig * 2;
            float b0 = 0.0f, b1 = 0.0f;
            if (blk == 2) { b0 = NB1[col]; b1 = NB1[col + 1]; }
            if (row1 < Nn)
                *(float2*)(dst + row1 * 128 + col) =
                    make_float2(acc[j][0] + b0, acc[j][1] + b1);
            if (row2 < Nn)
                *(float2*)(dst + row2 * 128 + col) =
                    make_float2(acc[j][2] + b0, acc[j][3] + b1);
        }
    }
}

// ---------------------------------------------------------------------------
// Kernel 2: per-graph lattice term + edge bias 1.
// ---------------------------------------------------------------------------
__global__ void prep_graph_kernel(const float* __restrict__ lat,
                                  const float* __restrict__ e_w1,
                                  const float* __restrict__ e_b1)
{
    const int g = blockIdx.x;
    const int c = threadIdx.x;
    float acc = e_b1[c];
#pragma unroll
    for (int k = 0; k < 6; k++)
        acc += lat[g * 6 + k] * e_w1[(256 + k) * 128 + c];
    g_Qb[g * 128 + c] = acc;
}

// ---------------------------------------------------------------------------
// Kernel 3: fused edge pipeline. fp16 2-chain. 128 edges/tile, 256 threads,
// 2 CTAs/SM. Warp grid 2x4: each warp 64 rows (4 m-frags) x 32 cols (4 n-frags).
// ---------------------------------------------------------------------------
#define TILE_M 128
#define EDGE_NTILES (Ee / TILE_M)      // 6250

#define O_SRC   0
#define O_DST   128
#define O_GS    256
#define O_FDS   384
#define O_B2    768
#define O_W1D   896
#define O_A     1280
#define O_BH    (O_A + 128 * PWS)
#define O_BL    (O_BH + 128 * PWS)
#define EDGE_SMEM_BYTES ((O_BL + 128 * PWS) * 4)   // 109,568 B

__launch_bounds__(256, 2)
__global__ void edge_kernel(const float* __restrict__ frac_diff,
                            const int*   __restrict__ ei,
                            const int*   __restrict__ e2g,
                            const float* __restrict__ e_w1,
                            const float* __restrict__ e_w2,
                            const float* __restrict__ e_b2)
{
    uint32_t* smw = (uint32_t*)dyn_smem;
    int*   srcs = (int*)(smw + O_SRC);
    int*   dsts = (int*)(smw + O_DST);
    int*   gs   = (int*)(smw + O_GS);
    float* fds  = (float*)(smw + O_FDS);
    float* b2s  = (float*)(smw + O_B2);
    float* w1ds = (float*)(smw + O_W1D);
    uint32_t* A  = smw + O_A;
    uint32_t* BH = smw + O_BH;
    uint32_t* BL = smw + O_BL;

    const int tid  = threadIdx.x;
    const int wid  = tid >> 5;
    const int lane = tid & 31;
    const int gid  = lane >> 2;
    const int tig  = lane & 3;
    const int wr   = wid >> 2;      // 0..1 row-group (64 rows)
    const int wc   = wid & 3;       // 0..3 col-group (32 cols)

    // one-time: constants + B = W2^T fp16 hi/lo planes
    for (int i = tid; i < 384; i += 256) w1ds[i] = e_w1[262 * 128 + i];
    if (tid < 128) b2s[tid] = e_b2[tid];
    for (int idx = tid; idx < 8192; idx += 256) {
        int n = idx >> 6, p = idx & 63, k0 = p << 1;
        uint32_t hw, lw;
        split_pack_h(e_w2[k0 * 128 + n], e_w2[(k0 + 1) * 128 + n], hw, lw);
        BH[n * PWS + p] = hw;
        BL[n * PWS + p] = lw;
    }

    for (int tile = blockIdx.x; tile < EDGE_NTILES; tile += gridDim.x) {
        __syncthreads();
        const int e0 = tile * TILE_M;
        if (tid < 128) {
            int e = e0 + tid;
            int s = ei[e];
            srcs[tid] = s;
            dsts[tid] = ei[Ee + e];
            gs[tid]   = e2g[e];
            atomicAdd(&g_cnt[s], 1);
        }
        for (int i = tid; i < 384; i += 256) fds[i] = frac_diff[e0 * 3 + i];
        __syncthreads();

        // Phase A: e1 tile -> silu -> single fp16 plane
#pragma unroll 4
        for (int idx = tid; idx < 8192; idx += 256) {
            int m = idx >> 6, p = idx & 63, c0 = p << 1;
            const float2 pa = *(const float2*)(g_Pa + srcs[m] * 128 + c0);
            const float2 pb = *(const float2*)(g_Pb + dsts[m] * 128 + c0);
            const float2 qb = *(const float2*)(g_Qb + gs[m] * 128 + c0);
            float f0 = fds[m * 3], f1 = fds[m * 3 + 1], f2 = fds[m * 3 + 2];
            float v0 = pa.x + pb.x + qb.x
                     + f0 * w1ds[c0] + f1 * w1ds[128 + c0] + f2 * w1ds[256 + c0];
            float v1 = pa.y + pb.y + qb.y
                     + f0 * w1ds[c0 + 1] + f1 * w1ds[129 + c0] + f2 * w1ds[257 + c0];
            A[m * PWS + p] = pack_h2(silu_f(v0), silu_f(v1));
        }
        __syncthreads();

        // MMA: 4 m-frags x 4 n-frags per warp, fp16 2-chain
        float acc[4][4][4];
#pragma unroll
        for (int mf = 0; mf < 4; mf++)
#pragma unroll
            for (int nfr = 0; nfr < 4; nfr++)
#pragma unroll
                for (int q = 0; q < 4; q++) acc[mf][nfr][q] = 0.0f;

#pragma unroll
        for (int ks = 0; ks < 8; ks++) {
            const int kw = ks * 8 + tig;
            uint32_t bh[4][2], bl[4][2];
#pragma unroll
            for (int nfr = 0; nfr < 4; nfr++) {
                const int nr = (wc * 32 + nfr * 8 + gid) * PWS + kw;
                bh[nfr][0] = BH[nr]; bh[nfr][1] = BH[nr + 4];
                bl[nfr][0] = BL[nr]; bl[nfr][1] = BL[nr + 4];
            }
#pragma unroll
            for (int mf = 0; mf < 4; mf++) {
                const int ar0 = (wr * 64 + mf * 16 + gid) * PWS;
                const int ar1 = ar0 + 8 * PWS;
                uint32_t a[4];
                load_afrag1(a, A, ar0, ar1, kw);
#pragma unroll
                for (int nfr = 0; nfr < 4; nfr++)
                    mma2(acc[mf][nfr], a, bh[nfr], bl[nfr]);
            }
        }

        // Epilogue: bias+silu, shfl-pair into 4-col runs, red.v4 into g_agg
        const bool evn = ((tig & 1) == 0);
#pragma unroll
        for (int mf = 0; mf < 4; mf++) {
            const int m1 = wr * 64 + mf * 16 + gid;
            const int myrow = evn ? m1 : (m1 + 8);
            float* agg = g_agg + srcs[myrow] * 128;
#pragma unroll
            for (int nfr = 0; nfr < 4; nfr++) {
                const int c0 = wc * 32 + nfr * 8 + tig * 2;
                float s0 = silu_f(acc[mf][nfr][0] + b2s[c0]);
                float s1 = silu_f(acc[mf][nfr][1] + b2s[c0 + 1]);
                float s2 = silu_f(acc[mf][nfr][2] + b2s[c0]);
                float s3 = silu_f(acc[mf][nfr][3] + b2s[c0 + 1]);
                float t0 = __shfl_xor_sync(0xFFFFFFFFu, s0, 1);
                float t1 = __shfl_xor_sync(0xFFFFFFFFu, s1, 1);
                float t2 = __shfl_xor_sync(0xFFFFFFFFu, s2, 1);
                float t3 = __shfl_xor_sync(0xFFFFFFFFu, s3, 1);
                if (evn) red_add_v4(agg + c0, s0, s1, t0, t1);       // row m1
                else     red_add_v4(agg + c0 - 2, t2, t3, s2, s3);   // row m1+8
            }
        }
    }
}

// ---------------------------------------------------------------------------
// Kernel 4: node model + residual, persistent. 128 rows/tile, fp16 2-chain.
// ---------------------------------------------------------------------------
#define N_B1H  0
#define N_B1L  8704
#define N_B2H  17408
#define N_B2L  26112
#define N_A    34816
#define N_NB2  43520
#define N_CINV 43648
#define NODE_SMEM_BYTES ((N_CINV + 128) * 4)   // 175,104 B
#define NODE_NTILES ((Nn + 127) / 128)          // 391

__launch_bounds__(512, 1)
__global__ void node_out_kernel(const float* __restrict__ nf,
                                const float* __restrict__ n_w1,
                                const float* __restrict__ n_w2,
                                const float* __restrict__ n_b2,
                                float* __restrict__ out)
{
    uint32_t* smw = (uint32_t*)dyn_smem;
    uint32_t* B1H = smw + N_B1H;
    uint32_t* B1L = smw + N_B1L;
    uint32_t* B2H = smw + N_B2H;
    uint32_t* B2L = smw + N_B2L;
    uint32_t* A   = smw + N_A;
    float*    NB2 = (float*)(smw + N_NB2);
    float*   cinv = (float*)(smw + N_CINV);

    const int tid  = threadIdx.x;
    const int wid  = tid >> 5;
    const int lane = tid & 31;
    const int gid  = lane >> 2;
    const int tig  = lane & 3;

    if (tid < 128) NB2[tid] = n_b2[tid];
    for (int idx = tid; idx < 8192; idx += 512) {
        int n = idx >> 6, p = idx & 63, k0 = p << 1;
        uint32_t hw, lw;
        split_pack_h(n_w1[(128 + k0) * 128 + n], n_w1[(129 + k0) * 128 + n], hw, lw);
        B1H[n * PWS + p] = hw;
        B1L[n * PWS + p] = lw;
        split_pack_h(n_w2[k0 * 128 + n], n_w2[(k0 + 1) * 128 + n], hw, lw);
        B2H[n * PWS + p] = hw;
        B2L[n * PWS + p] = lw;
    }

    const int rg  = wid >> 1;
    const int nfh = wid & 1;
    const int ar0 = (rg * 16 + gid) * PWS;
    const int ar1 = ar0 + 8 * PWS;
    const int m1  = rg * 16 + gid;
    const int m2  = m1 + 8;

    for (int tile = blockIdx.x; tile < NODE_NTILES; tile += gridDim.x) {
        const int row0 = tile * 128;
        __syncthreads();
        if (tid < 128) {
            int row = row0 + tid;
            cinv[tid] = (row < Nn) ? 1.0f / fmaxf((float)g_cnt[row], 1.0f) : 0.0f;
        }
        __syncthreads();

        for (int idx = tid; idx < 8192; idx += 512) {
            int m = idx >> 6, p = idx & 63, c0 = p << 1;
            int row = row0 + m;
            float v0 = 0.0f, v1 = 0.0f;
            if (row < Nn) {
                const float2 v = *(const float2*)(g_agg + row * 128 + c0);
                v0 = v.x * cinv[m]; v1 = v.y * cinv[m];
            }
            A[m * PWS + p] = pack_h2(v0, v1);
        }
        __syncthreads();

        float acc[8][4];
#pragma unroll
        for (int j = 0; j < 8; j++)
#pragma unroll
            for (int q = 0; q < 4; q++) acc[j][q] = 0.0f;
#pragma unroll
        for (int ks = 0; ks < 8; ks++) {
            const int kw = ks * 8 + tig;
            uint32_t a[4];
            load_afrag1(a, A, ar0, ar1, kw);
#pragma unroll
            for (int j = 0; j < 8; j++) {
                const int nr = ((nfh * 8 + j) * 8 + gid) * PWS;
                uint32_t bh[2] = {B1H[nr + kw], B1H[nr + kw + 4]};
                uint32_t bl[2] = {B1L[nr + kw], B1L[nr + kw + 4]};
                mma2(acc[j], a, bh, bl);
            }
        }
        __syncthreads();

        const int row1 = row0 + m1, row2 = row0 + m2;
#pragma unroll
        for (int j = 0; j < 8; j++) {
            const int col = (nfh * 8 + j) * 8 + tig * 2;
            const int p = col >> 1;
            float2 pc1 = make_float2(0.0f, 0.0f), pc2 = make_float2(0.0f, 0.0f);
            if (row1 < Nn) pc1 = *(const float2*)(g_Pc + row1 * 128 + col);
            if (row2 < Nn) pc2 = *(const float2*)(g_Pc + row2 * 128 + col);
            A[m1 * PWS + p] = pack_h2(silu_f(acc[j][0] + pc1.x),
                                      silu_f(acc[j][1] + pc1.y));
            A[m2 * PWS + p] = pack_h2(silu_f(acc[j][2] + pc2.x),
                                      silu_f(acc[j][3] + pc2.y));
        }
        __syncthreads();

        float acc2[8][4];
#pragma unroll
        for (int j = 0; j < 8; j++)
#pragma unroll
            for (int q = 0; q < 4; q++) acc2[j][q] = 0.0f;
#pragma unroll
        for (int ks = 0; ks < 8; ks++) {
            const int kw = ks * 8 + tig;
            uint32_t a[4];
            load_afrag1(a, A, ar0, ar1, kw);
#pragma unroll
            for (int j = 0; j < 8; j++) {
                const int nr = ((nfh * 8 + j) * 8 + gid) * PWS;
                uint32_t bh[2] = {B2H[nr + kw], B2H[nr + kw + 4]};
                uint32_t bl[2] = {B2L[nr + kw], B2L[nr + kw + 4]};
                mma2(acc2[j], a, bh, bl);
            }
        }

#pragma unroll
        for (int j = 0; j < 8; j++) {
            const int col = (nfh * 8 + j) * 8 + tig * 2;
            float b0 = NB2[col], b1 = NB2[col + 1];
            if (row1 < Nn) {
                const float2 x = *(const float2*)(nf + row1 * 128 + col);
                *(float2*)(out + row1 * 128 + col) =
                    make_float2(x.x + silu_f(acc2[j][0] + b0),
                                x.y + silu_f(acc2[j][1] + b1));
            }
            if (row2 < Nn) {
                const float2 x = *(const float2*)(nf + row2 * 128 + col);
                *(float2*)(out + row2 * 128 + col) =
                    make_float2(x.x + silu_f(acc2[j][2] + b0),
                                x.y + silu_f(acc2[j][3] + b1));
            }
        }
    }
}

// ---------------------------------------------------------------------------
extern "C" void kernel_launch(void* const* d_in, const int* in_sizes, int n_in,
                              void* d_out, int out_size)
{
    (void)in_sizes; (void)n_in; (void)out_size;
    const float* nf   = (const float*)d_in[0];
    const float* lat  = (const float*)d_in[2];
    const float* fd   = (const float*)d_in[3];
    const int*   ei   = (const int*)d_in[4];
    const int*   e2g  = (const int*)d_in[5];
    const float* e_w1 = (const float*)d_in[6];
    const float* e_b1 = (const float*)d_in[7];
    const float* e_w2 = (const float*)d_in[8];
    const float* e_b2 = (const float*)d_in[9];
    const float* n_w1 = (const float*)d_in[10];
    const float* n_b1 = (const float*)d_in[11];
    const float* n_w2 = (const float*)d_in[12];
    const float* n_b2 = (const float*)d_in[13];
    float* out = (float*)d_out;

    cudaFuncSetAttribute(prep_node_kernel,
                         cudaFuncAttributeMaxDynamicSharedMemorySize,
                         PREP_SMEM_BYTES);
    cudaFuncSetAttribute(edge_kernel,
                         cudaFuncAttributeMaxDynamicSharedMemorySize,
                         EDGE_SMEM_BYTES);
    cudaFuncSetAttribute(node_out_kernel,
                         cudaFuncAttributeMaxDynamicSharedMemorySize,
                         NODE_SMEM_BYTES);

    prep_node_kernel<<<NODE_NTILES, 512, PREP_SMEM_BYTES>>>(nf, e_w1, n_w1, n_b1);
    prep_graph_kernel<<<Gg, 128>>>(lat, e_w1, e_b1);
    edge_kernel<<<296, 256, EDGE_SMEM_BYTES>>>(fd, ei, e2g, e_w1, e_w2, e_b2);
    node_out_kernel<<<148, 512, NODE_SMEM_BYTES>>>(nf, n_w1, n_w2, n_b2, out);
}

// round 9
// speedup vs baseline: 1.4826x; 1.3272x over previous
#include <cuda_runtime.h>
#include <cuda_fp16.h>
#include <cstdint>
#include <cstring>

#define Nn 50000
#define Ee 800000
#define Gg 2048
#define Hh 128

extern __shared__ char dyn_smem[];

// ---------------- device scratch ----------
__device__ float g_Pa[Nn * Hh];    // nf @ e_w1[0:128]
__device__ float g_Pb[Nn * Hh];    // nf @ e_w1[128:256]
__device__ float g_Pc[Nn * Hh];    // nf @ n_w1[0:128] + n_b1
__device__ float g_Qb[Gg * Hh];    // lat @ e_w1[256:262] + e_b1
__device__ float g_agg[Nn * Hh];   // scatter-sum accumulator
__device__ int   g_cnt[Nn];        // per-node edge count

// silu via hw tanh: x*sigmoid(x) = 0.5*x*(1+tanh(x/2)). 1 MUFU vs 2.
__device__ __forceinline__ float silu_f(float x) {
    float t;
    asm("tanh.approx.f32 %0, %1;" : "=f"(t) : "f"(0.5f * x));
    return 0.5f * x * (1.0f + t);
}

// pack two floats -> fp16x2 word (v0 -> lo, v1 -> hi)
__device__ __forceinline__ uint32_t pack_h2(float v0, float v1) {
    __half2 h = __floats2half2_rn(v0, v1);
    uint32_t u;
    memcpy(&u, &h, 4);
    return u;
}

// warp-level fp16 MMA, fp32 accum (sm_80+, compiles at base sm_103 target)
__device__ __forceinline__ void mma16816h(float* d, const uint32_t* a, const uint32_t* b) {
    asm volatile(
        "mma.sync.aligned.m16n8k16.row.col.f32.f16.f16.f32 "
        "{%0,%1,%2,%3}, {%4,%5,%6,%7}, {%8,%9}, {%0,%1,%2,%3};"
        : "+f"(d[0]), "+f"(d[1]), "+f"(d[2]), "+f"(d[3])
        : "r"(a[0]), "r"(a[1]), "r"(a[2]), "r"(a[3]), "r"(b[0]), "r"(b[1]));
}

__device__ __forceinline__ void red_add_v4(float* p, float a, float b, float c, float d) {
    asm volatile("red.global.add.v4.f32 [%0], {%1, %2, %3, %4};"
                 :: "l"(p), "f"(a), "f"(b), "f"(c), "f"(d) : "memory");
}

#define PWS 68   // plane word-stride per row (64 pair-words + 4 pad)

// single-plane A fragment load
__device__ __forceinline__ void load_afrag1(uint32_t* a, const uint32_t* A,
                                            int ar0, int ar1, int kw) {
    a[0] = A[ar0 + kw];     a[1] = A[ar1 + kw];
    a[2] = A[ar0 + kw + 4]; a[3] = A[ar1 + kw + 4];
}

// ---------------------------------------------------------------------------
// Kernel 1: Pa/Pb/Pc precompute + zero agg/cnt. 128 rows per block.
// Full fp16 single-chain MMA.
// ---------------------------------------------------------------------------
#define P_B   0
#define P_A   8704
#define P_NB1 17408
#define PREP_SMEM_BYTES ((P_NB1 + 128) * 4)   // 70,144 B

__launch_bounds__(512, 1)
__global__ void prep_node_kernel(const float* __restrict__ nf,
                                 const float* __restrict__ e_w1,
                                 const float* __restrict__ n_w1,
                                 const float* __restrict__ n_b1)
{
    uint32_t* smw = (uint32_t*)dyn_smem;
    uint32_t* B   = smw + P_B;
    uint32_t* A   = smw + P_A;
    float*    NB1 = (float*)(smw + P_NB1);

    const int tid  = threadIdx.x;
    const int wid  = tid >> 5;
    const int lane = tid & 31;
    const int gid  = lane >> 2;
    const int tig  = lane & 3;
    const int row0 = blockIdx.x * 128;

    if (tid < 128) NB1[tid] = n_b1[tid];
    if (tid < 128 && row0 + tid < Nn) g_cnt[row0 + tid] = 0;

    // A plane: nf rows -> fp16; zero g_agg alongside
    for (int idx = tid; idx < 8192; idx += 512) {
        int m = idx >> 6, p = idx & 63, c0 = p << 1;
        int row = row0 + m;
        float v0 = 0.0f, v1 = 0.0f;
        if (row < Nn) {
            const float2 v = *(const float2*)(nf + row * 128 + c0);
            v0 = v.x; v1 = v.y;
            *(float2*)(g_agg + row * 128 + c0) = make_float2(0.0f, 0.0f);
        }
        A[m * PWS + p] = pack_h2(v0, v1);
    }

    const int rg  = wid >> 1;      // 0..7 row-group
    const int nfh = wid & 1;       // output-col half
    const int ar0 = (rg * 16 + gid) * PWS;
    const int ar1 = ar0 + 8 * PWS;
    const int m1  = rg * 16 + gid;
    const int row1 = row0 + m1, row2 = row1 + 8;

    for (int blk = 0; blk < 3; blk++) {
        __syncthreads();
        const float* bsrc = (blk == 0) ? e_w1
                          : (blk == 1) ? (e_w1 + 128 * 128)
                                       : n_w1;
        for (int idx = tid; idx < 8192; idx += 512) {
            int n = idx >> 6, p = idx & 63, k0 = p << 1;
            B[n * PWS + p] = pack_h2(bsrc[k0 * 128 + n], bsrc[(k0 + 1) * 128 + n]);
        }
        __syncthreads();

        float acc[8][4];
#pragma unroll
        for (int j = 0; j < 8; j++)
#pragma unroll
            for (int q = 0; q < 4; q++) acc[j][q] = 0.0f;

#pragma unroll
        for (int ks = 0; ks < 8; ks++) {
            const int kw = ks * 8 + tig;
            uint32_t a[4];
            load_afrag1(a, A, ar0, ar1, kw);
#pragma unroll
            for (int j = 0; j < 8; j++) {
                const int nr = ((nfh * 8 + j) * 8 + gid) * PWS;
                uint32_t b[2] = {B[nr + kw], B[nr + kw + 4]};
                mma16816h(acc[j], a, b);
            }
        }

        float* dst = (blk == 0) ? g_Pa : (blk == 1) ? g_Pb : g_Pc;
#pragma unroll
        for (int j = 0; j < 8; j++) {
            const int col = (nfh * 8 + j) * 8 + tig * 2;
            float b0 = 0.0f, b1 = 0.0f;
            if (blk == 2) { b0 = NB1[col]; b1 = NB1[col + 1]; }
            if (row1 < Nn)
                *(float2*)(dst + row1 * 128 + col) =
                    make_float2(acc[j][0] + b0, acc[j][1] + b1);
            if (row2 < Nn)
                *(float2*)(dst + row2 * 128 + col) =
                    make_float2(acc[j][2] + b0, acc[j][3] + b1);
        }
    }
}

// ---------------------------------------------------------------------------
// Kernel 2: per-graph lattice term + edge bias 1.
// ---------------------------------------------------------------------------
__global__ void prep_graph_kernel(const float* __restrict__ lat,
                                  const float* __restrict__ e_w1,
                                  const float* __restrict__ e_b1)
{
    const int g = blockIdx.x;
    const int c = threadIdx.x;
    float acc = e_b1[c];
#pragma unroll
    for (int k = 0; k < 6; k++)
        acc += lat[g * 6 + k] * e_w1[(256 + k) * 128 + c];
    g_Qb[g * 128 + c] = acc;
}

// ---------------------------------------------------------------------------
// Kernel 3: fused edge pipeline. fp16 single-chain. 128 edges/tile,
// 256 threads, 2 CTAs/SM. Warp grid 2x4: 64 rows x 32 cols per warp.
// ---------------------------------------------------------------------------
#define TILE_M 128
#define EDGE_NTILES (Ee / TILE_M)      // 6250

#define O_SRC   0
#define O_DST   128
#define O_GS    256
#define O_FDS   384
#define O_B2    768
#define O_W1D   896
#define O_A     1280
#define O_B     (O_A + 128 * PWS)
#define EDGE_SMEM_BYTES ((O_B + 128 * PWS) * 4)   // 74,752 B

__launch_bounds__(256, 2)
__global__ void edge_kernel(const float* __restrict__ frac_diff,
                            const int*   __restrict__ ei,
                            const int*   __restrict__ e2g,
                            const float* __restrict__ e_w1,
                            const float* __restrict__ e_w2,
                            const float* __restrict__ e_b2)
{
    uint32_t* smw = (uint32_t*)dyn_smem;
    int*   srcs = (int*)(smw + O_SRC);
    int*   dsts = (int*)(smw + O_DST);
    int*   gs   = (int*)(smw + O_GS);
    float* fds  = (float*)(smw + O_FDS);
    float* b2s  = (float*)(smw + O_B2);
    float* w1ds = (float*)(smw + O_W1D);
    uint32_t* A = smw + O_A;
    uint32_t* B = smw + O_B;

    const int tid  = threadIdx.x;
    const int wid  = tid >> 5;
    const int lane = tid & 31;
    const int gid  = lane >> 2;
    const int tig  = lane & 3;
    const int wr   = wid >> 2;      // 0..1 row-group (64 rows)
    const int wc   = wid & 3;       // 0..3 col-group (32 cols)

    // one-time: constants + B = W2^T fp16 plane
    for (int i = tid; i < 384; i += 256) w1ds[i] = e_w1[262 * 128 + i];
    if (tid < 128) b2s[tid] = e_b2[tid];
    for (int idx = tid; idx < 8192; idx += 256) {
        int n = idx >> 6, p = idx & 63, k0 = p << 1;
        B[n * PWS + p] = pack_h2(e_w2[k0 * 128 + n], e_w2[(k0 + 1) * 128 + n]);
    }

    for (int tile = blockIdx.x; tile < EDGE_NTILES; tile += gridDim.x) {
        __syncthreads();
        const int e0 = tile * TILE_M;
        if (tid < 128) {
            int e = e0 + tid;
            int s = ei[e];
            srcs[tid] = s;
            dsts[tid] = ei[Ee + e];
            gs[tid]   = e2g[e];
            atomicAdd(&g_cnt[s], 1);
        }
        for (int i = tid; i < 384; i += 256) fds[i] = frac_diff[e0 * 3 + i];
        __syncthreads();

        // Phase A: e1 tile -> silu -> single fp16 plane
#pragma unroll 4
        for (int idx = tid; idx < 8192; idx += 256) {
            int m = idx >> 6, p = idx & 63, c0 = p << 1;
            const float2 pa = *(const float2*)(g_Pa + srcs[m] * 128 + c0);
            const float2 pb = *(const float2*)(g_Pb + dsts[m] * 128 + c0);
            const float2 qb = *(const float2*)(g_Qb + gs[m] * 128 + c0);
            float f0 = fds[m * 3], f1 = fds[m * 3 + 1], f2 = fds[m * 3 + 2];
            float v0 = pa.x + pb.x + qb.x
                     + f0 * w1ds[c0] + f1 * w1ds[128 + c0] + f2 * w1ds[256 + c0];
            float v1 = pa.y + pb.y + qb.y
                     + f0 * w1ds[c0 + 1] + f1 * w1ds[129 + c0] + f2 * w1ds[257 + c0];
            A[m * PWS + p] = pack_h2(silu_f(v0), silu_f(v1));
        }
        __syncthreads();

        // MMA: 4 m-frags x 4 n-frags per warp, single-chain fp16
        float acc[4][4][4];
#pragma unroll
        for (int mf = 0; mf < 4; mf++)
#pragma unroll
            for (int nfr = 0; nfr < 4; nfr++)
#pragma unroll
                for (int q = 0; q < 4; q++) acc[mf][nfr][q] = 0.0f;

#pragma unroll
        for (int ks = 0; ks < 8; ks++) {
            const int kw = ks * 8 + tig;
            uint32_t b[4][2];
#pragma unroll
            for (int nfr = 0; nfr < 4; nfr++) {
                const int nr = (wc * 32 + nfr * 8 + gid) * PWS + kw;
                b[nfr][0] = B[nr]; b[nfr][1] = B[nr + 4];
            }
#pragma unroll
            for (int mf = 0; mf < 4; mf++) {
                const int ar0 = (wr * 64 + mf * 16 + gid) * PWS;
                const int ar1 = ar0 + 8 * PWS;
                uint32_t a[4];
                load_afrag1(a, A, ar0, ar1, kw);
#pragma unroll
                for (int nfr = 0; nfr < 4; nfr++)
                    mma16816h(acc[mf][nfr], a, b[nfr]);
            }
        }

        // Epilogue: bias+silu, shfl-pair into 4-col runs, red.v4 into g_agg
        const bool evn = ((tig & 1) == 0);
#pragma unroll
        for (int mf = 0; mf < 4; mf++) {
            const int m1 = wr * 64 + mf * 16 + gid;
            const int myrow = evn ? m1 : (m1 + 8);
            float* agg = g_agg + srcs[myrow] * 128;
#pragma unroll
            for (int nfr = 0; nfr < 4; nfr++) {
                const int c0 = wc * 32 + nfr * 8 + tig * 2;
                float s0 = silu_f(acc[mf][nfr][0] + b2s[c0]);
                float s1 = silu_f(acc[mf][nfr][1] + b2s[c0 + 1]);
                float s2 = silu_f(acc[mf][nfr][2] + b2s[c0]);
                float s3 = silu_f(acc[mf][nfr][3] + b2s[c0 + 1]);
                float t0 = __shfl_xor_sync(0xFFFFFFFFu, s0, 1);
                float t1 = __shfl_xor_sync(0xFFFFFFFFu, s1, 1);
                float t2 = __shfl_xor_sync(0xFFFFFFFFu, s2, 1);
                float t3 = __shfl_xor_sync(0xFFFFFFFFu, s3, 1);
                if (evn) red_add_v4(agg + c0, s0, s1, t0, t1);       // row m1
                else     red_add_v4(agg + c0 - 2, t2, t3, s2, s3);   // row m1+8
            }
        }
    }
}

// ---------------------------------------------------------------------------
// Kernel 4: node model + residual, persistent. 128 rows/tile, fp16 1-chain.
// ---------------------------------------------------------------------------
#define N_B1   0
#define N_B2   8704
#define N_A    17408
#define N_NB2  26112
#define N_CINV 26240
#define NODE_SMEM_BYTES ((N_CINV + 128) * 4)   // 105,472 B
#define NODE_NTILES ((Nn + 127) / 128)          // 391

__launch_bounds__(512, 1)
__global__ void node_out_kernel(const float* __restrict__ nf,
                                const float* __restrict__ n_w1,
                                const float* __restrict__ n_w2,
                                const float* __restrict__ n_b2,
                                float* __restrict__ out)
{
    uint32_t* smw = (uint32_t*)dyn_smem;
    uint32_t* B1  = smw + N_B1;
    uint32_t* B2  = smw + N_B2;
    uint32_t* A   = smw + N_A;
    float*    NB2 = (float*)(smw + N_NB2);
    float*   cinv = (float*)(smw + N_CINV);

    const int tid  = threadIdx.x;
    const int wid  = tid >> 5;
    const int lane = tid & 31;
    const int gid  = lane >> 2;
    const int tig  = lane & 3;

    if (tid < 128) NB2[tid] = n_b2[tid];
    for (int idx = tid; idx < 8192; idx += 512) {
        int n = idx >> 6, p = idx & 63, k0 = p << 1;
        B1[n * PWS + p] = pack_h2(n_w1[(128 + k0) * 128 + n],
                                  n_w1[(129 + k0) * 128 + n]);
        B2[n * PWS + p] = pack_h2(n_w2[k0 * 128 + n],
                                  n_w2[(k0 + 1) * 128 + n]);
    }

    const int rg  = wid >> 1;
    const int nfh = wid & 1;
    const int ar0 = (rg * 16 + gid) * PWS;
    const int ar1 = ar0 + 8 * PWS;
    const int m1  = rg * 16 + gid;
    const int m2  = m1 + 8;

    for (int tile = blockIdx.x; tile < NODE_NTILES; tile += gridDim.x) {
        const int row0 = tile * 128;
        __syncthreads();
        if (tid < 128) {
            int row = row0 + tid;
            cinv[tid] = (row < Nn) ? 1.0f / fmaxf((float)g_cnt[row], 1.0f) : 0.0f;
        }
        __syncthreads();

        for (int idx = tid; idx < 8192; idx += 512) {
            int m = idx >> 6, p = idx & 63, c0 = p << 1;
            int row = row0 + m;
            float v0 = 0.0f, v1 = 0.0f;
            if (row < Nn) {
                const float2 v = *(const float2*)(g_agg + row * 128 + c0);
                v0 = v.x * cinv[m]; v1 = v.y * cinv[m];
            }
            A[m * PWS + p] = pack_h2(v0, v1);
        }
        __syncthreads();

        float acc[8][4];
#pragma unroll
        for (int j = 0; j < 8; j++)
#pragma unroll
            for (int q = 0; q < 4; q++) acc[j][q] = 0.0f;
#pragma unroll
        for (int ks = 0; ks < 8; ks++) {
            const int kw = ks * 8 + tig;
            uint32_t a[4];
            load_afrag1(a, A, ar0, ar1, kw);
#pragma unroll
            for (int j = 0; j < 8; j++) {
                const int nr = ((nfh * 8 + j) * 8 + gid) * PWS;
                uint32_t b[2] = {B1[nr + kw], B1[nr + kw + 4]};
                mma16816h(acc[j], a, b);
            }
        }
        __syncthreads();

        const int row1 = row0 + m1, row2 = row0 + m2;
#pragma unroll
        for (int j = 0; j < 8; j++) {
            const int col = (nfh * 8 + j) * 8 + tig * 2;
            const int p = col >> 1;
            float2 pc1 = make_float2(0.0f, 0.0f), pc2 = make_float2(0.0f, 0.0f);
            if (row1 < Nn) pc1 = *(const float2*)(g_Pc + row1 * 128 + col);
            if (row2 < Nn) pc2 = *(const float2*)(g_Pc + row2 * 128 + col);
            A[m1 * PWS + p] = pack_h2(silu_f(acc[j][0] + pc1.x),
                                      silu_f(acc[j][1] + pc1.y));
            A[m2 * PWS + p] = pack_h2(silu_f(acc[j][2] + pc2.x),
                                      silu_f(acc[j][3] + pc2.y));
        }
        __syncthreads();

        float acc2[8][4];
#pragma unroll
        for (int j = 0; j < 8; j++)
#pragma unroll
            for (int q = 0; q < 4; q++) acc2[j][q] = 0.0f;
#pragma unroll
        for (int ks = 0; ks < 8; ks++) {
            const int kw = ks * 8 + tig;
            uint32_t a[4];
            load_afrag1(a, A, ar0, ar1, kw);
#pragma unroll
            for (int j = 0; j < 8; j++) {
                const int nr = ((nfh * 8 + j) * 8 + gid) * PWS;
                uint32_t b[2] = {B2[nr + kw], B2[nr + kw + 4]};
                mma16816h(acc2[j], a, b);
            }
        }

#pragma unroll
        for (int j = 0; j < 8; j++) {
            const int col = (nfh * 8 + j) * 8 + tig * 2;
            float b0 = NB2[col], b1 = NB2[col + 1];
            if (row1 < Nn) {
                const float2 x = *(const float2*)(nf + row1 * 128 + col);
                *(float2*)(out + row1 * 128 + col) =
                    make_float2(x.x + silu_f(acc2[j][0] + b0),
                                x.y + silu_f(acc2[j][1] + b1));
            }
            if (row2 < Nn) {
                const float2 x = *(const float2*)(nf + row2 * 128 + col);
                *(float2*)(out + row2 * 128 + col) =
                    make_float2(x.x + silu_f(acc2[j][2] + b0),
                                x.y + silu_f(acc2[j][3] + b1));
            }
        }
    }
}

// ---------------------------------------------------------------------------
extern "C" void kernel_launch(void* const* d_in, const int* in_sizes, int n_in,
                              void* d_out, int out_size)
{
    (void)in_sizes; (void)n_in; (void)out_size;
    const float* nf   = (const float*)d_in[0];
    const float* lat  = (const float*)d_in[2];
    const float* fd   = (const float*)d_in[3];
    const int*   ei   = (const int*)d_in[4];
    const int*   e2g  = (const int*)d_in[5];
    const float* e_w1 = (const float*)d_in[6];
    const float* e_b1 = (const float*)d_in[7];
    const float* e_w2 = (const float*)d_in[8];
    const float* e_b2 = (const float*)d_in[9];
    const float* n_w1 = (const float*)d_in[10];
    const float* n_b1 = (const float*)d_in[11];
    const float* n_w2 = (const float*)d_in[12];
    const float* n_b2 = (const float*)d_in[13];
    float* out = (float*)d_out;

    cudaFuncSetAttribute(prep_node_kernel,
                         cudaFuncAttributeMaxDynamicSharedMemorySize,
                         PREP_SMEM_BYTES);
    cudaFuncSetAttribute(edge_kernel,
                         cudaFuncAttributeMaxDynamicSharedMemorySize,
                         EDGE_SMEM_BYTES);
    cudaFuncSetAttribute(node_out_kernel,
                         cudaFuncAttributeMaxDynamicSharedMemorySize,
                         NODE_SMEM_BYTES);

    prep_node_kernel<<<NODE_NTILES, 512, PREP_SMEM_BYTES>>>(nf, e_w1, n_w1, n_b1);
    prep_graph_kernel<<<Gg, 128>>>(lat, e_w1, e_b1);
    edge_kernel<<<296, 256, EDGE_SMEM_BYTES>>>(fd, ei, e2g, e_w1, e_w2, e_b2);
    node_out_kernel<<<148, 512, NODE_SMEM_BYTES>>>(nf, n_w1, n_w2, n_b2, out);
}

// round 10
// speedup vs baseline: 1.5519x; 1.0468x over previous
#include <cuda_runtime.h>
#include <cuda_fp16.h>
#include <cstdint>
#include <cstring>

#define Nn 50000
#define Ee 800000
#define Gg 2048
#define Hh 128

extern __shared__ char dyn_smem[];

// ---------------- device scratch ----------
__device__ uint32_t g_Pa16[Nn * 64];   // fp16x2: nf @ e_w1[0:128]
__device__ uint32_t g_Pb16[Nn * 64];   // fp16x2: nf @ e_w1[128:256]
__device__ uint32_t g_Qb16[Gg * 64];   // fp16x2: lat @ e_w1[256:262] + e_b1
__device__ float    g_Pc[Nn * Hh];     // fp32:   nf @ n_w1[0:128] + n_b1
__device__ float    g_agg[Nn * Hh];    // scatter-sum accumulator
__device__ int      g_cnt[Nn];         // per-node edge count

// silu via hw tanh: x*sigmoid(x) = 0.5*x*(1+tanh(x/2)). 1 MUFU vs 2.
__device__ __forceinline__ float silu_f(float x) {
    float t;
    asm("tanh.approx.f32 %0, %1;" : "=f"(t) : "f"(0.5f * x));
    return 0.5f * x * (1.0f + t);
}

// pack two floats -> fp16x2 word (v0 -> lo, v1 -> hi)
__device__ __forceinline__ uint32_t pack_h2(float v0, float v1) {
    __half2 h = __floats2half2_rn(v0, v1);
    uint32_t u;
    memcpy(&u, &h, 4);
    return u;
}

__device__ __forceinline__ float2 unpack_h2(uint32_t u) {
    __half2 h;
    memcpy(&h, &u, 4);
    return __half22float2(h);
}

// warp-level fp16 MMA, fp32 accum (sm_80+, compiles at base sm_103 target)
__device__ __forceinline__ void mma16816h(float* d, const uint32_t* a, const uint32_t* b) {
    asm volatile(
        "mma.sync.aligned.m16n8k16.row.col.f32.f16.f16.f32 "
        "{%0,%1,%2,%3}, {%4,%5,%6,%7}, {%8,%9}, {%0,%1,%2,%3};"
        : "+f"(d[0]), "+f"(d[1]), "+f"(d[2]), "+f"(d[3])
        : "r"(a[0]), "r"(a[1]), "r"(a[2]), "r"(a[3]), "r"(b[0]), "r"(b[1]));
}

__device__ __forceinline__ void red_add_v4(float* p, float a, float b, float c, float d) {
    asm volatile("red.global.add.v4.f32 [%0], {%1, %2, %3, %4};"
                 :: "l"(p), "f"(a), "f"(b), "f"(c), "f"(d) : "memory");
}

#define PWS 68   // plane word-stride per row (64 pair-words + 4 pad)

// single-plane A fragment load
__device__ __forceinline__ void load_afrag1(uint32_t* a, const uint32_t* A,
                                            int ar0, int ar1, int kw) {
    a[0] = A[ar0 + kw];     a[1] = A[ar1 + kw];
    a[2] = A[ar0 + kw + 4]; a[3] = A[ar1 + kw + 4];
}

// ---------------------------------------------------------------------------
// Kernel 1: Pa/Pb (fp16 packed) + Pc (fp32) precompute + zero agg/cnt.
// 128 rows per block, fp16 single-chain MMA.
// ---------------------------------------------------------------------------
#define P_B   0
#define P_A   8704
#define P_NB1 17408
#define PREP_SMEM_BYTES ((P_NB1 + 128) * 4)   // 70,144 B

__launch_bounds__(512, 1)
__global__ void prep_node_kernel(const float* __restrict__ nf,
                                 const float* __restrict__ e_w1,
                                 const float* __restrict__ n_w1,
                                 const float* __restrict__ n_b1)
{
    uint32_t* smw = (uint32_t*)dyn_smem;
    uint32_t* B   = smw + P_B;
    uint32_t* A   = smw + P_A;
    float*    NB1 = (float*)(smw + P_NB1);

    const int tid  = threadIdx.x;
    const int wid  = tid >> 5;
    const int lane = tid & 31;
    const int gid  = lane >> 2;
    const int tig  = lane & 3;
    const int row0 = blockIdx.x * 128;

    if (tid < 128) NB1[tid] = n_b1[tid];
    if (tid < 128 && row0 + tid < Nn) g_cnt[row0 + tid] = 0;

    // A plane: nf rows -> fp16; zero g_agg alongside
    for (int idx = tid; idx < 8192; idx += 512) {
        int m = idx >> 6, p = idx & 63, c0 = p << 1;
        int row = row0 + m;
        float v0 = 0.0f, v1 = 0.0f;
        if (row < Nn) {
            const float2 v = *(const float2*)(nf + row * 128 + c0);
            v0 = v.x; v1 = v.y;
            *(float2*)(g_agg + row * 128 + c0) = make_float2(0.0f, 0.0f);
        }
        A[m * PWS + p] = pack_h2(v0, v1);
    }

    const int rg  = wid >> 1;      // 0..7 row-group
    const int nfh = wid & 1;       // output-col half
    const int ar0 = (rg * 16 + gid) * PWS;
    const int ar1 = ar0 + 8 * PWS;
    const int m1  = rg * 16 + gid;
    const int row1 = row0 + m1, row2 = row1 + 8;

    for (int blk = 0; blk < 3; blk++) {
        __syncthreads();
        const float* bsrc = (blk == 0) ? e_w1
                          : (blk == 1) ? (e_w1 + 128 * 128)
                                       : n_w1;
        for (int idx = tid; idx < 8192; idx += 512) {
            int n = idx >> 6, p = idx & 63, k0 = p << 1;
            B[n * PWS + p] = pack_h2(bsrc[k0 * 128 + n], bsrc[(k0 + 1) * 128 + n]);
        }
        __syncthreads();

        float acc[8][4];
#pragma unroll
        for (int j = 0; j < 8; j++)
#pragma unroll
            for (int q = 0; q < 4; q++) acc[j][q] = 0.0f;

#pragma unroll
        for (int ks = 0; ks < 8; ks++) {
            const int kw = ks * 8 + tig;
            uint32_t a[4];
            load_afrag1(a, A, ar0, ar1, kw);
#pragma unroll
            for (int j = 0; j < 8; j++) {
                const int nr = ((nfh * 8 + j) * 8 + gid) * PWS;
                uint32_t b[2] = {B[nr + kw], B[nr + kw + 4]};
                mma16816h(acc[j], a, b);
            }
        }

        if (blk < 2) {
            // Pa/Pb: pack result pairs to fp16x2 words
            uint32_t* dst16 = (blk == 0) ? g_Pa16 : g_Pb16;
#pragma unroll
            for (int j = 0; j < 8; j++) {
                const int col = (nfh * 8 + j) * 8 + tig * 2;
                const int pw = col >> 1;
                if (row1 < Nn) dst16[row1 * 64 + pw] = pack_h2(acc[j][0], acc[j][1]);
                if (row2 < Nn) dst16[row2 * 64 + pw] = pack_h2(acc[j][2], acc[j][3]);
            }
        } else {
            // Pc fp32 + bias
#pragma unroll
            for (int j = 0; j < 8; j++) {
                const int col = (nfh * 8 + j) * 8 + tig * 2;
                float b0 = NB1[col], b1 = NB1[col + 1];
                if (row1 < Nn)
                    *(float2*)(g_Pc + row1 * 128 + col) =
                        make_float2(acc[j][0] + b0, acc[j][1] + b1);
                if (row2 < Nn)
                    *(float2*)(g_Pc + row2 * 128 + col) =
                        make_float2(acc[j][2] + b0, acc[j][3] + b1);
            }
        }
    }
}

// ---------------------------------------------------------------------------
// Kernel 2: per-graph lattice term + edge bias 1 -> fp16x2 packed.
// 64 threads, 2 cols each.
// ---------------------------------------------------------------------------
__global__ void prep_graph_kernel(const float* __restrict__ lat,
                                  const float* __restrict__ e_w1,
                                  const float* __restrict__ e_b1)
{
    const int g = blockIdx.x;
    const int c0 = threadIdx.x * 2;
    float a0 = e_b1[c0], a1 = e_b1[c0 + 1];
#pragma unroll
    for (int k = 0; k < 6; k++) {
        float lv = lat[g * 6 + k];
        a0 += lv * e_w1[(256 + k) * 128 + c0];
        a1 += lv * e_w1[(256 + k) * 128 + c0 + 1];
    }
    g_Qb16[g * 64 + threadIdx.x] = pack_h2(a0, a1);
}

// ---------------------------------------------------------------------------
// Kernel 3: fused edge pipeline. fp16 single-chain. 128 edges/tile,
// 256 threads, 2 CTAs/SM. Gather planes are fp16 (half the L2 bytes).
// ---------------------------------------------------------------------------
#define TILE_M 128
#define EDGE_NTILES (Ee / TILE_M)      // 6250

#define O_SRC   0
#define O_DST   128
#define O_GS    256
#define O_FDS   384
#define O_B2    768
#define O_W1D   896
#define O_A     1280
#define O_B     (O_A + 128 * PWS)
#define EDGE_SMEM_BYTES ((O_B + 128 * PWS) * 4)   // 74,752 B

__launch_bounds__(256, 2)
__global__ void edge_kernel(const float* __restrict__ frac_diff,
                            const int*   __restrict__ ei,
                            const int*   __restrict__ e2g,
                            const float* __restrict__ e_w1,
                            const float* __restrict__ e_w2,
                            const float* __restrict__ e_b2)
{
    uint32_t* smw = (uint32_t*)dyn_smem;
    int*   srcs = (int*)(smw + O_SRC);
    int*   dsts = (int*)(smw + O_DST);
    int*   gs   = (int*)(smw + O_GS);
    float* fds  = (float*)(smw + O_FDS);
    float* b2s  = (float*)(smw + O_B2);
    float* w1ds = (float*)(smw + O_W1D);
    uint32_t* A = smw + O_A;
    uint32_t* B = smw + O_B;

    const int tid  = threadIdx.x;
    const int wid  = tid >> 5;
    const int lane = tid & 31;
    const int gid  = lane >> 2;
    const int tig  = lane & 3;
    const int wr   = wid >> 2;      // 0..1 row-group (64 rows)
    const int wc   = wid & 3;       // 0..3 col-group (32 cols)

    // one-time: constants + B = W2^T fp16 plane
    for (int i = tid; i < 384; i += 256) w1ds[i] = e_w1[262 * 128 + i];
    if (tid < 128) b2s[tid] = e_b2[tid];
    for (int idx = tid; idx < 8192; idx += 256) {
        int n = idx >> 6, p = idx & 63, k0 = p << 1;
        B[n * PWS + p] = pack_h2(e_w2[k0 * 128 + n], e_w2[(k0 + 1) * 128 + n]);
    }

    for (int tile = blockIdx.x; tile < EDGE_NTILES; tile += gridDim.x) {
        __syncthreads();
        const int e0 = tile * TILE_M;
        if (tid < 128) {
            int e = e0 + tid;
            int s = ei[e];
            srcs[tid] = s;
            dsts[tid] = ei[Ee + e];
            gs[tid]   = e2g[e];
            atomicAdd(&g_cnt[s], 1);
        }
        for (int i = tid; i < 384; i += 256) fds[i] = frac_diff[e0 * 3 + i];
        __syncthreads();

        // Phase A: e1 tile -> silu -> single fp16 plane (fp16 gathers)
#pragma unroll 4
        for (int idx = tid; idx < 8192; idx += 256) {
            int m = idx >> 6, p = idx & 63, c0 = p << 1;
            const float2 pa = unpack_h2(g_Pa16[srcs[m] * 64 + p]);
            const float2 pb = unpack_h2(g_Pb16[dsts[m] * 64 + p]);
            const float2 qb = unpack_h2(g_Qb16[gs[m] * 64 + p]);
            float f0 = fds[m * 3], f1 = fds[m * 3 + 1], f2 = fds[m * 3 + 2];
            float v0 = pa.x + pb.x + qb.x
                     + f0 * w1ds[c0] + f1 * w1ds[128 + c0] + f2 * w1ds[256 + c0];
            float v1 = pa.y + pb.y + qb.y
                     + f0 * w1ds[c0 + 1] + f1 * w1ds[129 + c0] + f2 * w1ds[257 + c0];
            A[m * PWS + p] = pack_h2(silu_f(v0), silu_f(v1));
        }
        __syncthreads();

        // MMA: 4 m-frags x 4 n-frags per warp, single-chain fp16
        float acc[4][4][4];
#pragma unroll
        for (int mf = 0; mf < 4; mf++)
#pragma unroll
            for (int nfr = 0; nfr < 4; nfr++)
#pragma unroll
                for (int q = 0; q < 4; q++) acc[mf][nfr][q] = 0.0f;

#pragma unroll
        for (int ks = 0; ks < 8; ks++) {
            const int kw = ks * 8 + tig;
            uint32_t b[4][2];
#pragma unroll
            for (int nfr = 0; nfr < 4; nfr++) {
                const int nr = (wc * 32 + nfr * 8 + gid) * PWS + kw;
                b[nfr][0] = B[nr]; b[nfr][1] = B[nr + 4];
            }
#pragma unroll
            for (int mf = 0; mf < 4; mf++) {
                const int ar0 = (wr * 64 + mf * 16 + gid) * PWS;
                const int ar1 = ar0 + 8 * PWS;
                uint32_t a[4];
                load_afrag1(a, A, ar0, ar1, kw);
#pragma unroll
                for (int nfr = 0; nfr < 4; nfr++)
                    mma16816h(acc[mf][nfr], a, b[nfr]);
            }
        }

        // Epilogue: bias+silu, shfl-pair into 4-col runs, red.v4 into g_agg
        const bool evn = ((tig & 1) == 0);
#pragma unroll
        for (int mf = 0; mf < 4; mf++) {
            const int m1 = wr * 64 + mf * 16 + gid;
            const int myrow = evn ? m1 : (m1 + 8);
            float* agg = g_agg + srcs[myrow] * 128;
#pragma unroll
            for (int nfr = 0; nfr < 4; nfr++) {
                const int c0 = wc * 32 + nfr * 8 + tig * 2;
                float s0 = silu_f(acc[mf][nfr][0] + b2s[c0]);
                float s1 = silu_f(acc[mf][nfr][1] + b2s[c0 + 1]);
                float s2 = silu_f(acc[mf][nfr][2] + b2s[c0]);
                float s3 = silu_f(acc[mf][nfr][3] + b2s[c0 + 1]);
                float t0 = __shfl_xor_sync(0xFFFFFFFFu, s0, 1);
                float t1 = __shfl_xor_sync(0xFFFFFFFFu, s1, 1);
                float t2 = __shfl_xor_sync(0xFFFFFFFFu, s2, 1);
                float t3 = __shfl_xor_sync(0xFFFFFFFFu, s3, 1);
                if (evn) red_add_v4(agg + c0, s0, s1, t0, t1);       // row m1
                else     red_add_v4(agg + c0 - 2, t2, t3, s2, s3);   // row m1+8
            }
        }
    }
}

// ---------------------------------------------------------------------------
// Kernel 4: node model + residual, persistent. 128 rows/tile, fp16 1-chain.
// ---------------------------------------------------------------------------
#define N_B1   0
#define N_B2   8704
#define N_A    17408
#define N_NB2  26112
#define N_CINV 26240
#define NODE_SMEM_BYTES ((N_CINV + 128) * 4)   // 105,472 B
#define NODE_NTILES ((Nn + 127) / 128)          // 391

__launch_bounds__(512, 1)
__global__ void node_out_kernel(const float* __restrict__ nf,
                                const float* __restrict__ n_w1,
                                const float* __restrict__ n_w2,
                                const float* __restrict__ n_b2,
                                float* __restrict__ out)
{
    uint32_t* smw = (uint32_t*)dyn_smem;
    uint32_t* B1  = smw + N_B1;
    uint32_t* B2  = smw + N_B2;
    uint32_t* A   = smw + N_A;
    float*    NB2 = (float*)(smw + N_NB2);
    float*   cinv = (float*)(smw + N_CINV);

    const int tid  = threadIdx.x;
    const int wid  = tid >> 5;
    const int lane = tid & 31;
    const int gid  = lane >> 2;
    const int tig  = lane & 3;

    if (tid < 128) NB2[tid] = n_b2[tid];
    for (int idx = tid; idx < 8192; idx += 512) {
        int n = idx >> 6, p = idx & 63, k0 = p << 1;
        B1[n * PWS + p] = pack_h2(n_w1[(128 + k0) * 128 + n],
                                  n_w1[(129 + k0) * 128 + n]);
        B2[n * PWS + p] = pack_h2(n_w2[k0 * 128 + n],
                                  n_w2[(k0 + 1) * 128 + n]);
    }

    const int rg  = wid >> 1;
    const int nfh = wid & 1;
    const int ar0 = (rg * 16 + gid) * PWS;
    const int ar1 = ar0 + 8 * PWS;
    const int m1  = rg * 16 + gid;
    const int m2  = m1 + 8;

    for (int tile = blockIdx.x; tile < NODE_NTILES; tile += gridDim.x) {
        const int row0 = tile * 128;
        __syncthreads();
        if (tid < 128) {
            int row = row0 + tid;
            cinv[tid] = (row < Nn) ? 1.0f / fmaxf((float)g_cnt[row], 1.0f) : 0.0f;
        }
        __syncthreads();

        for (int idx = tid; idx < 8192; idx += 512) {
            int m = idx >> 6, p = idx & 63, c0 = p << 1;
            int row = row0 + m;
            float v0 = 0.0f, v1 = 0.0f;
            if (row < Nn) {
                const float2 v = *(const float2*)(g_agg + row * 128 + c0);
                v0 = v.x * cinv[m]; v1 = v.y * cinv[m];
            }
            A[m * PWS + p] = pack_h2(v0, v1);
        }
        __syncthreads();

        float acc[8][4];
#pragma unroll
        for (int j = 0; j < 8; j++)
#pragma unroll
            for (int q = 0; q < 4; q++) acc[j][q] = 0.0f;
#pragma unroll
        for (int ks = 0; ks < 8; ks++) {
            const int kw = ks * 8 + tig;
            uint32_t a[4];
            load_afrag1(a, A, ar0, ar1, kw);
#pragma unroll
            for (int j = 0; j < 8; j++) {
                const int nr = ((nfh * 8 + j) * 8 + gid) * PWS;
                uint32_t b[2] = {B1[nr + kw], B1[nr + kw + 4]};
                mma16816h(acc[j], a, b);
            }
        }
        __syncthreads();

        const int row1 = row0 + m1, row2 = row0 + m2;
#pragma unroll
        for (int j = 0; j < 8; j++) {
            const int col = (nfh * 8 + j) * 8 + tig * 2;
            const int p = col >> 1;
            float2 pc1 = make_float2(0.0f, 0.0f), pc2 = make_float2(0.0f, 0.0f);
            if (row1 < Nn) pc1 = *(const float2*)(g_Pc + row1 * 128 + col);
            if (row2 < Nn) pc2 = *(const float2*)(g_Pc + row2 * 128 + col);
            A[m1 * PWS + p] = pack_h2(silu_f(acc[j][0] + pc1.x),
                                      silu_f(acc[j][1] + pc1.y));
            A[m2 * PWS + p] = pack_h2(silu_f(acc[j][2] + pc2.x),
                                      silu_f(acc[j][3] + pc2.y));
        }
        __syncthreads();

        float acc2[8][4];
#pragma unroll
        for (int j = 0; j < 8; j++)
#pragma unroll
            for (int q = 0; q < 4; q++) acc2[j][q] = 0.0f;
#pragma unroll
        for (int ks = 0; ks < 8; ks++) {
            const int kw = ks * 8 + tig;
            uint32_t a[4];
            load_afrag1(a, A, ar0, ar1, kw);
#pragma unroll
            for (int j = 0; j < 8; j++) {
                const int nr = ((nfh * 8 + j) * 8 + gid) * PWS;
                uint32_t b[2] = {B2[nr + kw], B2[nr + kw + 4]};
                mma16816h(acc2[j], a, b);
            }
        }

#pragma unroll
        for (int j = 0; j < 8; j++) {
            const int col = (nfh * 8 + j) * 8 + tig * 2;
            float b0 = NB2[col], b1 = NB2[col + 1];
            if (row1 < Nn) {
                const float2 x = *(const float2*)(nf + row1 * 128 + col);
                *(float2*)(out + row1 * 128 + col) =
                    make_float2(x.x + silu_f(acc2[j][0] + b0),
                                x.y + silu_f(acc2[j][1] + b1));
            }
            if (row2 < Nn) {
                const float2 x = *(const float2*)(nf + row2 * 128 + col);
                *(float2*)(out + row2 * 128 + col) =
                    make_float2(x.x + silu_f(acc2[j][2] + b0),
                                x.y + silu_f(acc2[j][3] + b1));
            }
        }
    }
}

// ---------------------------------------------------------------------------
extern "C" void kernel_launch(void* const* d_in, const int* in_sizes, int n_in,
                              void* d_out, int out_size)
{
    (void)in_sizes; (void)n_in; (void)out_size;
    const float* nf   = (const float*)d_in[0];
    const float* lat  = (const float*)d_in[2];
    const float* fd   = (const float*)d_in[3];
    const int*   ei   = (const int*)d_in[4];
    const int*   e2g  = (const int*)d_in[5];
    const float* e_w1 = (const float*)d_in[6];
    const float* e_b1 = (const float*)d_in[7];
    const float* e_w2 = (const float*)d_in[8];
    const float* e_b2 = (const float*)d_in[9];
    const float* n_w1 = (const float*)d_in[10];
    const float* n_b1 = (const float*)d_in[11];
    const float* n_w2 = (const float*)d_in[12];
    const float* n_b2 = (const float*)d_in[13];
    float* out = (float*)d_out;

    cudaFuncSetAttribute(prep_node_kernel,
                         cudaFuncAttributeMaxDynamicSharedMemorySize,
                         PREP_SMEM_BYTES);
    cudaFuncSetAttribute(edge_kernel,
                         cudaFuncAttributeMaxDynamicSharedMemorySize,
                         EDGE_SMEM_BYTES);
    cudaFuncSetAttribute(node_out_kernel,
                         cudaFuncAttributeMaxDynamicSharedMemorySize,
                         NODE_SMEM_BYTES);

    prep_node_kernel<<<NODE_NTILES, 512, PREP_SMEM_BYTES>>>(nf, e_w1, n_w1, n_b1);
    prep_graph_kernel<<<Gg, 64>>>(lat, e_w1, e_b1);
    edge_kernel<<<296, 256, EDGE_SMEM_BYTES>>>(fd, ei, e2g, e_w1, e_w2, e_b2);
    node_out_kernel<<<148, 512, NODE_SMEM_BYTES>>>(nf, n_w1, n_w2, n_b2, out);
}

// round 11
// speedup vs baseline: 1.7468x; 1.1256x over previous
#include <cuda_runtime.h>
#include <cuda_fp16.h>
#include <cstdint>
#include <cstring>

#define Nn 50000
#define Ee 800000
#define Gg 2048
#define Hh 128

extern __shared__ char dyn_smem[];

// ---------------- device scratch ----------
__device__ uint32_t g_Pa16[Nn * 64];   // fp16x2: nf @ e_w1[0:128]
__device__ uint32_t g_Pb16[Nn * 64];   // fp16x2: nf @ e_w1[128:256]
__device__ uint32_t g_Qb16[Gg * 64];   // fp16x2: lat @ e_w1[256:262] + e_b1
__device__ float    g_Pc[Nn * Hh];     // fp32:   nf @ n_w1[0:128] + n_b1
__device__ float    g_agg[Nn * Hh];    // scatter-sum accumulator
__device__ int      g_cnt[Nn];         // per-node edge count

// silu via hw tanh: x*sigmoid(x) = 0.5*x*(1+tanh(x/2)). 1 MUFU vs 2.
__device__ __forceinline__ float silu_f(float x) {
    float t;
    asm("tanh.approx.f32 %0, %1;" : "=f"(t) : "f"(0.5f * x));
    return 0.5f * x * (1.0f + t);
}

__device__ __forceinline__ uint32_t pack_h2(float v0, float v1) {
    __half2 h = __floats2half2_rn(v0, v1);
    uint32_t u;
    memcpy(&u, &h, 4);
    return u;
}

__device__ __forceinline__ float2 unpack_h2(uint32_t u) {
    __half2 h;
    memcpy(&h, &u, 4);
    return __half22float2(h);
}

__device__ __forceinline__ void mma16816h(float* d, const uint32_t* a, const uint32_t* b) {
    asm volatile(
        "mma.sync.aligned.m16n8k16.row.col.f32.f16.f16.f32 "
        "{%0,%1,%2,%3}, {%4,%5,%6,%7}, {%8,%9}, {%0,%1,%2,%3};"
        : "+f"(d[0]), "+f"(d[1]), "+f"(d[2]), "+f"(d[3])
        : "r"(a[0]), "r"(a[1]), "r"(a[2]), "r"(a[3]), "r"(b[0]), "r"(b[1]));
}

__device__ __forceinline__ void red_add_v4(float* p, float a, float b, float c, float d) {
    asm volatile("red.global.add.v4.f32 [%0], {%1, %2, %3, %4};"
                 :: "l"(p), "f"(a), "f"(b), "f"(c), "f"(d) : "memory");
}

#define PWS 68   // plane word-stride per row (64 pair-words + 4 pad)

__device__ __forceinline__ void load_afrag1(uint32_t* a, const uint32_t* A,
                                            int ar0, int ar1, int kw) {
    a[0] = A[ar0 + kw];     a[1] = A[ar1 + kw];
    a[2] = A[ar0 + kw + 4]; a[3] = A[ar1 + kw + 4];
}

// ---------------------------------------------------------------------------
// Kernel 1: persistent Pa/Pb (fp16) + Pc (fp32) precompute + zero agg/cnt.
// All three B planes resident in smem, built ONCE per CTA.
// ---------------------------------------------------------------------------
#define P_B0  0
#define P_B1  8704
#define P_B2  17408
#define P_A   26112
#define P_NB1 34816
#define PREP_SMEM_BYTES ((P_NB1 + 128) * 4)   // 139,776 B
#define PREP_NTILES ((Nn + 127) / 128)         // 391

__launch_bounds__(512, 1)
__global__ void prep_node_kernel(const float* __restrict__ nf,
                                 const float* __restrict__ e_w1,
                                 const float* __restrict__ n_w1,
                                 const float* __restrict__ n_b1)
{
    uint32_t* smw = (uint32_t*)dyn_smem;
    uint32_t* Bp[3] = {smw + P_B0, smw + P_B1, smw + P_B2};
    uint32_t* A   = smw + P_A;
    float*    NB1 = (float*)(smw + P_NB1);

    const int tid  = threadIdx.x;
    const int wid  = tid >> 5;
    const int lane = tid & 31;
    const int gid  = lane >> 2;
    const int tig  = lane & 3;

    if (tid < 128) NB1[tid] = n_b1[tid];
    // build all 3 B planes once
    for (int blk = 0; blk < 3; blk++) {
        const float* bsrc = (blk == 0) ? e_w1
                          : (blk == 1) ? (e_w1 + 128 * 128)
                                       : n_w1;
        uint32_t* B = Bp[blk];
        for (int idx = tid; idx < 8192; idx += 512) {
            int n = idx >> 6, p = idx & 63, k0 = p << 1;
            B[n * PWS + p] = pack_h2(bsrc[k0 * 128 + n], bsrc[(k0 + 1) * 128 + n]);
        }
    }

    const int rg  = wid >> 1;
    const int nfh = wid & 1;
    const int ar0 = (rg * 16 + gid) * PWS;
    const int ar1 = ar0 + 8 * PWS;
    const int m1  = rg * 16 + gid;

    for (int tile = blockIdx.x; tile < PREP_NTILES; tile += gridDim.x) {
        const int row0 = tile * 128;
        __syncthreads();   // prev tile's GEMM reads done before A overwrite
        if (tid < 128 && row0 + tid < Nn) g_cnt[row0 + tid] = 0;
        for (int idx = tid; idx < 8192; idx += 512) {
            int m = idx >> 6, p = idx & 63, c0 = p << 1;
            int row = row0 + m;
            float v0 = 0.0f, v1 = 0.0f;
            if (row < Nn) {
                const float2 v = *(const float2*)(nf + row * 128 + c0);
                v0 = v.x; v1 = v.y;
                *(float2*)(g_agg + row * 128 + c0) = make_float2(0.0f, 0.0f);
            }
            A[m * PWS + p] = pack_h2(v0, v1);
        }
        __syncthreads();

        const int row1 = row0 + m1, row2 = row1 + 8;
        for (int blk = 0; blk < 3; blk++) {
            uint32_t* B = Bp[blk];
            float acc[8][4];
#pragma unroll
            for (int j = 0; j < 8; j++)
#pragma unroll
                for (int q = 0; q < 4; q++) acc[j][q] = 0.0f;

#pragma unroll
            for (int ks = 0; ks < 8; ks++) {
                const int kw = ks * 8 + tig;
                uint32_t a[4];
                load_afrag1(a, A, ar0, ar1, kw);
#pragma unroll
                for (int j = 0; j < 8; j++) {
                    const int nr = ((nfh * 8 + j) * 8 + gid) * PWS;
                    uint32_t b[2] = {B[nr + kw], B[nr + kw + 4]};
                    mma16816h(acc[j], a, b);
                }
            }

            if (blk < 2) {
                uint32_t* dst16 = (blk == 0) ? g_Pa16 : g_Pb16;
#pragma unroll
                for (int j = 0; j < 8; j++) {
                    const int col = (nfh * 8 + j) * 8 + tig * 2;
                    const int pw = col >> 1;
                    if (row1 < Nn) dst16[row1 * 64 + pw] = pack_h2(acc[j][0], acc[j][1]);
                    if (row2 < Nn) dst16[row2 * 64 + pw] = pack_h2(acc[j][2], acc[j][3]);
                }
            } else {
#pragma unroll
                for (int j = 0; j < 8; j++) {
                    const int col = (nfh * 8 + j) * 8 + tig * 2;
                    float b0 = NB1[col], b1 = NB1[col + 1];
                    if (row1 < Nn)
                        *(float2*)(g_Pc + row1 * 128 + col) =
                            make_float2(acc[j][0] + b0, acc[j][1] + b1);
                    if (row2 < Nn)
                        *(float2*)(g_Pc + row2 * 128 + col) =
                            make_float2(acc[j][2] + b0, acc[j][3] + b1);
                }
            }
        }
    }
}

// ---------------------------------------------------------------------------
// Kernel 2: per-graph lattice term + edge bias 1 -> fp16x2 packed.
// ---------------------------------------------------------------------------
__global__ void prep_graph_kernel(const float* __restrict__ lat,
                                  const float* __restrict__ e_w1,
                                  const float* __restrict__ e_b1)
{
    const int g = blockIdx.x;
    const int c0 = threadIdx.x * 2;
    float a0 = e_b1[c0], a1 = e_b1[c0 + 1];
#pragma unroll
    for (int k = 0; k < 6; k++) {
        float lv = lat[g * 6 + k];
        a0 += lv * e_w1[(256 + k) * 128 + c0];
        a1 += lv * e_w1[(256 + k) * 128 + c0 + 1];
    }
    g_Qb16[g * 64 + threadIdx.x] = pack_h2(a0, a1);
}

// ---------------------------------------------------------------------------
// Kernel 3: fused edge pipeline. fp16 single-chain. 128 edges/tile,
// 256 threads, 2 CTAs/SM. w1d + b2 hoisted to registers (tile-invariant).
// ---------------------------------------------------------------------------
#define TILE_M 128
#define EDGE_NTILES (Ee / TILE_M)      // 6250

#define O_SRC   0
#define O_DST   128
#define O_GS    256
#define O_FDS   384
#define O_A     1280
#define O_B     (O_A + 128 * PWS)
#define EDGE_SMEM_BYTES ((O_B + 128 * PWS) * 4)   // 74,752 B

__launch_bounds__(256, 2)
__global__ void edge_kernel(const float* __restrict__ frac_diff,
                            const int*   __restrict__ ei,
                            const int*   __restrict__ e2g,
                            const float* __restrict__ e_w1,
                            const float* __restrict__ e_w2,
                            const float* __restrict__ e_b2)
{
    uint32_t* smw = (uint32_t*)dyn_smem;
    int*   srcs = (int*)(smw + O_SRC);
    int*   dsts = (int*)(smw + O_DST);
    int*   gs   = (int*)(smw + O_GS);
    float* fds  = (float*)(smw + O_FDS);
    uint32_t* A = smw + O_A;
    uint32_t* B = smw + O_B;

    const int tid  = threadIdx.x;
    const int wid  = tid >> 5;
    const int lane = tid & 31;
    const int gid  = lane >> 2;
    const int tig  = lane & 3;
    const int wr   = wid >> 2;      // 0..1 row-group (64 rows)
    const int wc   = wid & 3;       // 0..3 col-group (32 cols)

    // hoisted tile-invariant constants -> registers
    const int cA = (tid & 63) * 2;          // Phase-A column pair
    const float w0a = e_w1[262 * 128 + cA],     w0b = e_w1[262 * 128 + cA + 1];
    const float w1a = e_w1[263 * 128 + cA],     w1b = e_w1[263 * 128 + cA + 1];
    const float w2a = e_w1[264 * 128 + cA],     w2b = e_w1[264 * 128 + cA + 1];
    float b2r[8];
#pragma unroll
    for (int nfr = 0; nfr < 4; nfr++) {
        const int c0 = wc * 32 + nfr * 8 + tig * 2;
        b2r[nfr * 2]     = e_b2[c0];
        b2r[nfr * 2 + 1] = e_b2[c0 + 1];
    }

    // one-time: B = W2^T fp16 plane
    for (int idx = tid; idx < 8192; idx += 256) {
        int n = idx >> 6, p = idx & 63, k0 = p << 1;
        B[n * PWS + p] = pack_h2(e_w2[k0 * 128 + n], e_w2[(k0 + 1) * 128 + n]);
    }

    for (int tile = blockIdx.x; tile < EDGE_NTILES; tile += gridDim.x) {
        __syncthreads();
        const int e0 = tile * TILE_M;
        if (tid < 128) {
            int e = e0 + tid;
            int s = ei[e];
            srcs[tid] = s;
            dsts[tid] = ei[Ee + e];
            gs[tid]   = e2g[e];
            atomicAdd(&g_cnt[s], 1);
        }
        for (int i = tid; i < 384; i += 256) fds[i] = frac_diff[e0 * 3 + i];
        __syncthreads();

        // Phase A: e1 tile -> silu -> single fp16 plane
        const int pA = tid & 63;
        const int m0 = tid >> 6;
#pragma unroll 4
        for (int mi = 0; mi < 32; mi++) {
            const int m = m0 + mi * 4;
            const float2 pa = unpack_h2(g_Pa16[srcs[m] * 64 + pA]);
            const float2 pb = unpack_h2(g_Pb16[dsts[m] * 64 + pA]);
            const float2 qb = unpack_h2(g_Qb16[gs[m] * 64 + pA]);
            float f0 = fds[m * 3], f1 = fds[m * 3 + 1], f2 = fds[m * 3 + 2];
            float v0 = pa.x + pb.x + qb.x + f0 * w0a + f1 * w1a + f2 * w2a;
            float v1 = pa.y + pb.y + qb.y + f0 * w0b + f1 * w1b + f2 * w2b;
            A[m * PWS + pA] = pack_h2(silu_f(v0), silu_f(v1));
        }
        __syncthreads();

        // MMA: 4 m-frags x 4 n-frags per warp, single-chain fp16
        float acc[4][4][4];
#pragma unroll
        for (int mf = 0; mf < 4; mf++)
#pragma unroll
            for (int nfr = 0; nfr < 4; nfr++)
#pragma unroll
                for (int q = 0; q < 4; q++) acc[mf][nfr][q] = 0.0f;

#pragma unroll
        for (int ks = 0; ks < 8; ks++) {
            const int kw = ks * 8 + tig;
            uint32_t b[4][2];
#pragma unroll
            for (int nfr = 0; nfr < 4; nfr++) {
                const int nr = (wc * 32 + nfr * 8 + gid) * PWS + kw;
                b[nfr][0] = B[nr]; b[nfr][1] = B[nr + 4];
            }
#pragma unroll
            for (int mf = 0; mf < 4; mf++) {
                const int ar0 = (wr * 64 + mf * 16 + gid) * PWS;
                const int ar1 = ar0 + 8 * PWS;
                uint32_t a[4];
                load_afrag1(a, A, ar0, ar1, kw);
#pragma unroll
                for (int nfr = 0; nfr < 4; nfr++)
                    mma16816h(acc[mf][nfr], a, b[nfr]);
            }
        }

        // Epilogue: bias+silu, shfl-pair into 4-col runs, red.v4 into g_agg
        const bool evn = ((tig & 1) == 0);
#pragma unroll
        for (int mf = 0; mf < 4; mf++) {
            const int m1 = wr * 64 + mf * 16 + gid;
            const int myrow = evn ? m1 : (m1 + 8);
            float* agg = g_agg + srcs[myrow] * 128;
#pragma unroll
            for (int nfr = 0; nfr < 4; nfr++) {
                const int c0 = wc * 32 + nfr * 8 + tig * 2;
                float s0 = silu_f(acc[mf][nfr][0] + b2r[nfr * 2]);
                float s1 = silu_f(acc[mf][nfr][1] + b2r[nfr * 2 + 1]);
                float s2 = silu_f(acc[mf][nfr][2] + b2r[nfr * 2]);
                float s3 = silu_f(acc[mf][nfr][3] + b2r[nfr * 2 + 1]);
                float t0 = __shfl_xor_sync(0xFFFFFFFFu, s0, 1);
                float t1 = __shfl_xor_sync(0xFFFFFFFFu, s1, 1);
                float t2 = __shfl_xor_sync(0xFFFFFFFFu, s2, 1);
                float t3 = __shfl_xor_sync(0xFFFFFFFFu, s3, 1);
                if (evn) red_add_v4(agg + c0, s0, s1, t0, t1);       // row m1
                else     red_add_v4(agg + c0 - 2, t2, t3, s2, s3);   // row m1+8
            }
        }
    }
}

// ---------------------------------------------------------------------------
// Kernel 4: node model + residual, persistent. 128 rows/tile, fp16 1-chain.
// ---------------------------------------------------------------------------
#define N_B1   0
#define N_B2   8704
#define N_A    17408
#define N_NB2  26112
#define N_CINV 26240
#define NODE_SMEM_BYTES ((N_CINV + 128) * 4)   // 105,472 B
#define NODE_NTILES ((Nn + 127) / 128)          // 391

__launch_bounds__(512, 1)
__global__ void node_out_kernel(const float* __restrict__ nf,
                                const float* __restrict__ n_w1,
                                const float* __restrict__ n_w2,
                                const float* __restrict__ n_b2,
                                float* __restrict__ out)
{
    uint32_t* smw = (uint32_t*)dyn_smem;
    uint32_t* B1  = smw + N_B1;
    uint32_t* B2  = smw + N_B2;
    uint32_t* A   = smw + N_A;
    float*    NB2 = (float*)(smw + N_NB2);
    float*   cinv = (float*)(smw + N_CINV);

    const int tid  = threadIdx.x;
    const int wid  = tid >> 5;
    const int lane = tid & 31;
    const int gid  = lane >> 2;
    const int tig  = lane & 3;

    if (tid < 128) NB2[tid] = n_b2[tid];
    for (int idx = tid; idx < 8192; idx += 512) {
        int n = idx >> 6, p = idx & 63, k0 = p << 1;
        B1[n * PWS + p] = pack_h2(n_w1[(128 + k0) * 128 + n],
                                  n_w1[(129 + k0) * 128 + n]);
        B2[n * PWS + p] = pack_h2(n_w2[k0 * 128 + n],
                                  n_w2[(k0 + 1) * 128 + n]);
    }

    const int rg  = wid >> 1;
    const int nfh = wid & 1;
    const int ar0 = (rg * 16 + gid) * PWS;
    const int ar1 = ar0 + 8 * PWS;
    const int m1  = rg * 16 + gid;
    const int m2  = m1 + 8;

    for (int tile = blockIdx.x; tile < NODE_NTILES; tile += gridDim.x) {
        const int row0 = tile * 128;
        __syncthreads();
        if (tid < 128) {
            int row = row0 + tid;
            cinv[tid] = (row < Nn) ? 1.0f / fmaxf((float)g_cnt[row], 1.0f) : 0.0f;
        }
        __syncthreads();

        for (int idx = tid; idx < 8192; idx += 512) {
            int m = idx >> 6, p = idx & 63, c0 = p << 1;
            int row = row0 + m;
            float v0 = 0.0f, v1 = 0.0f;
            if (row < Nn) {
                const float2 v = *(const float2*)(g_agg + row * 128 + c0);
                v0 = v.x * cinv[m]; v1 = v.y * cinv[m];
            }
            A[m * PWS + p] = pack_h2(v0, v1);
        }
        __syncthreads();

        float acc[8][4];
#pragma unroll
        for (int j = 0; j < 8; j++)
#pragma unroll
            for (int q = 0; q < 4; q++) acc[j][q] = 0.0f;
#pragma unroll
        for (int ks = 0; ks < 8; ks++) {
            const int kw = ks * 8 + tig;
            uint32_t a[4];
            load_afrag1(a, A, ar0, ar1, kw);
#pragma unroll
            for (int j = 0; j < 8; j++) {
                const int nr = ((nfh * 8 + j) * 8 + gid) * PWS;
                uint32_t b[2] = {B1[nr + kw], B1[nr + kw + 4]};
                mma16816h(acc[j], a, b);
            }
        }
        __syncthreads();

        const int row1 = row0 + m1, row2 = row0 + m2;
#pragma unroll
        for (int j = 0; j < 8; j++) {
            const int col = (nfh * 8 + j) * 8 + tig * 2;
            const int p = col >> 1;
            float2 pc1 = make_float2(0.0f, 0.0f), pc2 = make_float2(0.0f, 0.0f);
            if (row1 < Nn) pc1 = *(const float2*)(g_Pc + row1 * 128 + col);
            if (row2 < Nn) pc2 = *(const float2*)(g_Pc + row2 * 128 + col);
            A[m1 * PWS + p] = pack_h2(silu_f(acc[j][0] + pc1.x),
                                      silu_f(acc[j][1] + pc1.y));
            A[m2 * PWS + p] = pack_h2(silu_f(acc[j][2] + pc2.x),
                                      silu_f(acc[j][3] + pc2.y));
        }
        __syncthreads();

        float acc2[8][4];
#pragma unroll
        for (int j = 0; j < 8; j++)
#pragma unroll
            for (int q = 0; q < 4; q++) acc2[j][q] = 0.0f;
#pragma unroll
        for (int ks = 0; ks < 8; ks++) {
            const int kw = ks * 8 + tig;
            uint32_t a[4];
            load_afrag1(a, A, ar0, ar1, kw);
#pragma unroll
            for (int j = 0; j < 8; j++) {
                const int nr = ((nfh * 8 + j) * 8 + gid) * PWS;
                uint32_t b[2] = {B2[nr + kw], B2[nr + kw + 4]};
                mma16816h(acc2[j], a, b);
            }
        }

#pragma unroll
        for (int j = 0; j < 8; j++) {
            const int col = (nfh * 8 + j) * 8 + tig * 2;
            float b0 = NB2[col], b1 = NB2[col + 1];
            if (row1 < Nn) {
                const float2 x = *(const float2*)(nf + row1 * 128 + col);
                *(float2*)(out + row1 * 128 + col) =
                    make_float2(x.x + silu_f(acc2[j][0] + b0),
                                x.y + silu_f(acc2[j][1] + b1));
            }
            if (row2 < Nn) {
                const float2 x = *(const float2*)(nf + row2 * 128 + col);
                *(float2*)(out + row2 * 128 + col) =
                    make_float2(x.x + silu_f(acc2[j][2] + b0),
                                x.y + silu_f(acc2[j][3] + b1));
            }
        }
    }
}

// ---------------------------------------------------------------------------
extern "C" void kernel_launch(void* const* d_in, const int* in_sizes, int n_in,
                              void* d_out, int out_size)
{
    (void)in_sizes; (void)n_in; (void)out_size;
    const float* nf   = (const float*)d_in[0];
    const float* lat  = (const float*)d_in[2];
    const float* fd   = (const float*)d_in[3];
    const int*   ei   = (const int*)d_in[4];
    const int*   e2g  = (const int*)d_in[5];
    const float* e_w1 = (const float*)d_in[6];
    const float* e_b1 = (const float*)d_in[7];
    const float* e_w2 = (const float*)d_in[8];
    const float* e_b2 = (const float*)d_in[9];
    const float* n_w1 = (const float*)d_in[10];
    const float* n_b1 = (const float*)d_in[11];
    const float* n_w2 = (const float*)d_in[12];
    const float* n_b2 = (const float*)d_in[13];
    float* out = (float*)d_out;

    cudaFuncSetAttribute(prep_node_kernel,
                         cudaFuncAttributeMaxDynamicSharedMemorySize,
                         PREP_SMEM_BYTES);
    cudaFuncSetAttribute(edge_kernel,
                         cudaFuncAttributeMaxDynamicSharedMemorySize,
                         EDGE_SMEM_BYTES);
    cudaFuncSetAttribute(node_out_kernel,
                         cudaFuncAttributeMaxDynamicSharedMemorySize,
                         NODE_SMEM_BYTES);

    prep_node_kernel<<<148, 512, PREP_SMEM_BYTES>>>(nf, e_w1, n_w1, n_b1);
    prep_graph_kernel<<<Gg, 64>>>(lat, e_w1, e_b1);
    edge_kernel<<<296, 256, EDGE_SMEM_BYTES>>>(fd, ei, e2g, e_w1, e_w2, e_b2);
    node_out_kernel<<<148, 512, NODE_SMEM_BYTES>>>(nf, n_w1, n_w2, n_b2, out);
}

// round 12
// speedup vs baseline: 1.9410x; 1.1111x over previous
#include <cuda_runtime.h>
#include <cuda_fp16.h>
#include <cstdint>
#include <cstring>

#define Nn 50000
#define Ee 800000
#define Gg 2048
#define Hh 128

extern __shared__ char dyn_smem[];

// ---------------- device scratch ----------
__device__ uint32_t g_Pa16[Nn * 64];   // fp16x2: nf @ e_w1[0:128]
__device__ uint32_t g_Pb16[Nn * 64];   // fp16x2: nf @ e_w1[128:256]
__device__ uint32_t g_Qb16[Gg * 64];   // fp16x2: lat @ e_w1[256:262] + e_b1
__device__ float    g_Pc[Nn * Hh];     // fp32:   nf @ n_w1[0:128] + n_b1
__device__ float    g_agg[Nn * Hh];    // scatter-sum accumulator
__device__ int      g_cnt[Nn];         // per-node edge count

// silu via hw tanh: x*sigmoid(x) = 0.5*x*(1+tanh(x/2)). 1 MUFU vs 2.
__device__ __forceinline__ float silu_f(float x) {
    float t;
    asm("tanh.approx.f32 %0, %1;" : "=f"(t) : "f"(0.5f * x));
    return 0.5f * x * (1.0f + t);
}

__device__ __forceinline__ uint32_t pack_h2(float v0, float v1) {
    __half2 h = __floats2half2_rn(v0, v1);
    uint32_t u;
    memcpy(&u, &h, 4);
    return u;
}

__device__ __forceinline__ float2 unpack_h2(uint32_t u) {
    __half2 h;
    memcpy(&h, &u, 4);
    return __half22float2(h);
}

__device__ __forceinline__ __half2 h2bits(uint32_t u) {
    __half2 h; memcpy(&h, &u, 4); return h;
}
__device__ __forceinline__ uint32_t bitsh2(__half2 h) {
    uint32_t u; memcpy(&u, &h, 4); return u;
}

// fp16x2 silu: h = 0.5x; r = h + h*tanh(h)
__device__ __forceinline__ __half2 silu_h2(__half2 x) {
    __half2 h = __hmul2(x, __float2half2_rn(0.5f));
    uint32_t hb = bitsh2(h), tb;
    asm("tanh.approx.f16x2 %0, %1;" : "=r"(tb) : "r"(hb));
    __half2 t = h2bits(tb);
    return __hfma2(h, t, h);
}

__device__ __forceinline__ void mma16816h(float* d, const uint32_t* a, const uint32_t* b) {
    asm volatile(
        "mma.sync.aligned.m16n8k16.row.col.f32.f16.f16.f32 "
        "{%0,%1,%2,%3}, {%4,%5,%6,%7}, {%8,%9}, {%0,%1,%2,%3};"
        : "+f"(d[0]), "+f"(d[1]), "+f"(d[2]), "+f"(d[3])
        : "r"(a[0]), "r"(a[1]), "r"(a[2]), "r"(a[3]), "r"(b[0]), "r"(b[1]));
}

__device__ __forceinline__ void ldsm_x4(uint32_t* r, uint32_t saddr) {
    asm volatile("ldmatrix.sync.aligned.m8n8.x4.shared.b16 {%0,%1,%2,%3}, [%4];"
        : "=r"(r[0]), "=r"(r[1]), "=r"(r[2]), "=r"(r[3]) : "r"(saddr));
}
__device__ __forceinline__ void ldsm_x2(uint32_t* r, uint32_t saddr) {
    asm volatile("ldmatrix.sync.aligned.m8n8.x2.shared.b16 {%0,%1}, [%2];"
        : "=r"(r[0]), "=r"(r[1]) : "r"(saddr));
}

__device__ __forceinline__ void red_add_v4(float* p, float a, float b, float c, float d) {
    asm volatile("red.global.add.v4.f32 [%0], {%1, %2, %3, %4};"
                 :: "l"(p), "f"(a), "f"(b), "f"(c), "f"(d) : "memory");
}

#define PWS 68   // plane word-stride per row (64 pair-words + 4 pad)

__device__ __forceinline__ void load_afrag1(uint32_t* a, const uint32_t* A,
                                            int ar0, int ar1, int kw) {
    a[0] = A[ar0 + kw];     a[1] = A[ar1 + kw];
    a[2] = A[ar0 + kw + 4]; a[3] = A[ar1 + kw + 4];
}

// ---------------------------------------------------------------------------
// Kernel 1: persistent Pa/Pb (fp16) + Pc (fp32) precompute + zero agg/cnt.
// ---------------------------------------------------------------------------
#define P_B0  0
#define P_B1  8704
#define P_B2  17408
#define P_A   26112
#define P_NB1 34816
#define PREP_SMEM_BYTES ((P_NB1 + 128) * 4)   // 139,776 B
#define PREP_NTILES ((Nn + 127) / 128)         // 391

__launch_bounds__(512, 1)
__global__ void prep_node_kernel(const float* __restrict__ nf,
                                 const float* __restrict__ e_w1,
                                 const float* __restrict__ n_w1,
                                 const float* __restrict__ n_b1)
{
    uint32_t* smw = (uint32_t*)dyn_smem;
    uint32_t* Bp[3] = {smw + P_B0, smw + P_B1, smw + P_B2};
    uint32_t* A   = smw + P_A;
    float*    NB1 = (float*)(smw + P_NB1);

    const int tid  = threadIdx.x;
    const int wid  = tid >> 5;
    const int lane = tid & 31;
    const int gid  = lane >> 2;
    const int tig  = lane & 3;

    if (tid < 128) NB1[tid] = n_b1[tid];
    for (int blk = 0; blk < 3; blk++) {
        const float* bsrc = (blk == 0) ? e_w1
                          : (blk == 1) ? (e_w1 + 128 * 128)
                                       : n_w1;
        uint32_t* B = Bp[blk];
        for (int idx = tid; idx < 8192; idx += 512) {
            int n = idx >> 6, p = idx & 63, k0 = p << 1;
            B[n * PWS + p] = pack_h2(bsrc[k0 * 128 + n], bsrc[(k0 + 1) * 128 + n]);
        }
    }

    const int rg  = wid >> 1;
    const int nfh = wid & 1;
    const int ar0 = (rg * 16 + gid) * PWS;
    const int ar1 = ar0 + 8 * PWS;
    const int m1  = rg * 16 + gid;

    for (int tile = blockIdx.x; tile < PREP_NTILES; tile += gridDim.x) {
        const int row0 = tile * 128;
        __syncthreads();
        if (tid < 128 && row0 + tid < Nn) g_cnt[row0 + tid] = 0;
        for (int idx = tid; idx < 8192; idx += 512) {
            int m = idx >> 6, p = idx & 63, c0 = p << 1;
            int row = row0 + m;
            float v0 = 0.0f, v1 = 0.0f;
            if (row < Nn) {
                const float2 v = *(const float2*)(nf + row * 128 + c0);
                v0 = v.x; v1 = v.y;
                *(float2*)(g_agg + row * 128 + c0) = make_float2(0.0f, 0.0f);
            }
            A[m * PWS + p] = pack_h2(v0, v1);
        }
        __syncthreads();

        const int row1 = row0 + m1, row2 = row1 + 8;
        for (int blk = 0; blk < 3; blk++) {
            uint32_t* B = Bp[blk];
            float acc[8][4];
#pragma unroll
            for (int j = 0; j < 8; j++)
#pragma unroll
                for (int q = 0; q < 4; q++) acc[j][q] = 0.0f;

#pragma unroll
            for (int ks = 0; ks < 8; ks++) {
                const int kw = ks * 8 + tig;
                uint32_t a[4];
                load_afrag1(a, A, ar0, ar1, kw);
#pragma unroll
                for (int j = 0; j < 8; j++) {
                    const int nr = ((nfh * 8 + j) * 8 + gid) * PWS;
                    uint32_t b[2] = {B[nr + kw], B[nr + kw + 4]};
                    mma16816h(acc[j], a, b);
                }
            }

            if (blk < 2) {
                uint32_t* dst16 = (blk == 0) ? g_Pa16 : g_Pb16;
#pragma unroll
                for (int j = 0; j < 8; j++) {
                    const int col = (nfh * 8 + j) * 8 + tig * 2;
                    const int pw = col >> 1;
                    if (row1 < Nn) dst16[row1 * 64 + pw] = pack_h2(acc[j][0], acc[j][1]);
                    if (row2 < Nn) dst16[row2 * 64 + pw] = pack_h2(acc[j][2], acc[j][3]);
                }
            } else {
#pragma unroll
                for (int j = 0; j < 8; j++) {
                    const int col = (nfh * 8 + j) * 8 + tig * 2;
                    float b0 = NB1[col], b1 = NB1[col + 1];
                    if (row1 < Nn)
                        *(float2*)(g_Pc + row1 * 128 + col) =
                            make_float2(acc[j][0] + b0, acc[j][1] + b1);
                    if (row2 < Nn)
                        *(float2*)(g_Pc + row2 * 128 + col) =
                            make_float2(acc[j][2] + b0, acc[j][3] + b1);
                }
            }
        }
    }
}

// ---------------------------------------------------------------------------
// Kernel 2: per-graph lattice term + edge bias 1 -> fp16x2 packed.
// ---------------------------------------------------------------------------
__global__ void prep_graph_kernel(const float* __restrict__ lat,
                                  const float* __restrict__ e_w1,
                                  const float* __restrict__ e_b1)
{
    const int g = blockIdx.x;
    const int c0 = threadIdx.x * 2;
    float a0 = e_b1[c0], a1 = e_b1[c0 + 1];
#pragma unroll
    for (int k = 0; k < 6; k++) {
        float lv = lat[g * 6 + k];
        a0 += lv * e_w1[(256 + k) * 128 + c0];
        a1 += lv * e_w1[(256 + k) * 128 + c0 + 1];
    }
    g_Qb16[g * 64 + threadIdx.x] = pack_h2(a0, a1);
}

// ---------------------------------------------------------------------------
// Kernel 3: fused edge pipeline. 128 edges/tile, 256 threads, 2 CTAs/SM.
// Phase A: one row per 2 threads, all-fp16x2 arithmetic, LDG.128 gathers.
// MMA: ldmatrix fragment loads (tile-invariant addresses).
// ---------------------------------------------------------------------------
#define TILE_M 128
#define EDGE_NTILES (Ee / TILE_M)      // 6250

#define O_SRC   0
#define O_DST   128
#define O_GS    256
#define O_FDS   384
#define O_W1DH  768
#define O_A     960
#define O_B     (O_A + 128 * PWS)
#define EDGE_SMEM_BYTES ((O_B + 128 * PWS) * 4)   // 73,472 B

__launch_bounds__(256, 2)
__global__ void edge_kernel(const float* __restrict__ frac_diff,
                            const int*   __restrict__ ei,
                            const int*   __restrict__ e2g,
                            const float* __restrict__ e_w1,
                            const float* __restrict__ e_w2,
                            const float* __restrict__ e_b2)
{
    uint32_t* smw = (uint32_t*)dyn_smem;
    int*   srcs = (int*)(smw + O_SRC);
    int*   dsts = (int*)(smw + O_DST);
    int*   gs   = (int*)(smw + O_GS);
    float* fds  = (float*)(smw + O_FDS);
    uint32_t* W1DH = smw + O_W1DH;
    uint32_t* A = smw + O_A;
    uint32_t* B = smw + O_B;

    const int tid  = threadIdx.x;
    const int wid  = tid >> 5;
    const int lane = tid & 31;
    const int gid  = lane >> 2;
    const int tig  = lane & 3;
    const int wr   = wid >> 2;      // 0..1 row-group (64 rows)
    const int wc   = wid & 3;       // 0..3 col-group (32 cols)

    // epilogue bias in registers
    float b2r[8];
#pragma unroll
    for (int nfr = 0; nfr < 4; nfr++) {
        const int c0 = wc * 32 + nfr * 8 + tig * 2;
        b2r[nfr * 2]     = e_b2[c0];
        b2r[nfr * 2 + 1] = e_b2[c0 + 1];
    }

    // one-time: W1D as fp16x2 [k][word], B = W2^T fp16 plane
    for (int i = tid; i < 192; i += 256) {
        int k = i >> 6, w = i & 63;
        W1DH[i] = pack_h2(e_w1[(262 + k) * 128 + w * 2],
                          e_w1[(262 + k) * 128 + w * 2 + 1]);
    }
    for (int idx = tid; idx < 8192; idx += 256) {
        int n = idx >> 6, p = idx & 63, k0 = p << 1;
        B[n * PWS + p] = pack_h2(e_w2[k0 * 128 + n], e_w2[(k0 + 1) * 128 + n]);
    }

    // tile-invariant ldmatrix addresses
    uint32_t aaddr[4], baddr[4];
    {
        uint32_t A_s = (uint32_t)__cvta_generic_to_shared(A);
        uint32_t B_s = (uint32_t)__cvta_generic_to_shared(B);
        int lsub = lane >> 3;
#pragma unroll
        for (int mf = 0; mf < 4; mf++) {
            int arow = wr * 64 + mf * 16 + (lsub & 1) * 8 + (lane & 7);
            aaddr[mf] = A_s + arow * (PWS * 4) + (lsub >> 1) * 16;
        }
        int bsub = lsub & 1;
#pragma unroll
        for (int nfr = 0; nfr < 4; nfr++) {
            int brow = wc * 32 + nfr * 8 + (lane & 7);
            baddr[nfr] = B_s + brow * (PWS * 4) + bsub * 16;
        }
    }

    const int myrow = tid >> 1;
    const int halfw = (tid & 1) * 32;

    for (int tile = blockIdx.x; tile < EDGE_NTILES; tile += gridDim.x) {
        __syncthreads();
        const int e0 = tile * TILE_M;
        if (tid < 128) {
            int e = e0 + tid;
            int s = ei[e];
            srcs[tid] = s;
            dsts[tid] = ei[Ee + e];
            gs[tid]   = e2g[e];
            atomicAdd(&g_cnt[s], 1);
        }
        for (int i = tid; i < 384; i += 256) fds[i] = frac_diff[e0 * 3 + i];
        __syncthreads();

        // Phase A: per-thread half row, all fp16x2 math
        {
            const int sA = srcs[myrow], dAi = dsts[myrow], gA = gs[myrow];
            const __half2 f0h = __float2half2_rn(fds[myrow * 3 + 0]);
            const __half2 f1h = __float2half2_rn(fds[myrow * 3 + 1]);
            const __half2 f2h = __float2half2_rn(fds[myrow * 3 + 2]);
            const uint32_t* paP = g_Pa16 + sA * 64 + halfw;
            const uint32_t* pbP = g_Pb16 + dAi * 64 + halfw;
            const uint32_t* qbP = g_Qb16 + gA * 64 + halfw;
            const uint32_t* wP  = W1DH + halfw;
            uint32_t* aRow = A + myrow * PWS + halfw;
#pragma unroll
            for (int it = 0; it < 8; it++) {
                uint4 pa = *(const uint4*)(paP + it * 4);
                uint4 pb = *(const uint4*)(pbP + it * 4);
                uint4 qb = *(const uint4*)(qbP + it * 4);
                uint4 w0 = *(const uint4*)(wP + it * 4);
                uint4 w1 = *(const uint4*)(wP + 64 + it * 4);
                uint4 w2 = *(const uint4*)(wP + 128 + it * 4);
                uint4 outw;
                uint32_t paw[4] = {pa.x, pa.y, pa.z, pa.w};
                uint32_t pbw[4] = {pb.x, pb.y, pb.z, pb.w};
                uint32_t qbw[4] = {qb.x, qb.y, qb.z, qb.w};
                uint32_t w0w[4] = {w0.x, w0.y, w0.z, w0.w};
                uint32_t w1w[4] = {w1.x, w1.y, w1.z, w1.w};
                uint32_t w2w[4] = {w2.x, w2.y, w2.z, w2.w};
                uint32_t ow[4];
#pragma unroll
                for (int j = 0; j < 4; j++) {
                    __half2 x = __hadd2(h2bits(paw[j]), h2bits(pbw[j]));
                    x = __hadd2(x, h2bits(qbw[j]));
                    x = __hfma2(f0h, h2bits(w0w[j]), x);
                    x = __hfma2(f1h, h2bits(w1w[j]), x);
                    x = __hfma2(f2h, h2bits(w2w[j]), x);
                    ow[j] = bitsh2(silu_h2(x));
                }
                outw.x = ow[0]; outw.y = ow[1]; outw.z = ow[2]; outw.w = ow[3];
                *(uint4*)(aRow + it * 4) = outw;
            }
        }
        __syncthreads();

        // MMA: ldmatrix fragments, 4 m-frags x 4 n-frags per warp
        float acc[4][4][4];
#pragma unroll
        for (int mf = 0; mf < 4; mf++)
#pragma unroll
            for (int nfr = 0; nfr < 4; nfr++)
#pragma unroll
                for (int q = 0; q < 4; q++) acc[mf][nfr][q] = 0.0f;

#pragma unroll
        for (int ks = 0; ks < 8; ks++) {
            uint32_t b[4][2];
#pragma unroll
            for (int nfr = 0; nfr < 4; nfr++)
                ldsm_x2(b[nfr], baddr[nfr] + ks * 32);
#pragma unroll
            for (int mf = 0; mf < 4; mf++) {
                uint32_t a[4];
                ldsm_x4(a, aaddr[mf] + ks * 32);
#pragma unroll
                for (int nfr = 0; nfr < 4; nfr++)
                    mma16816h(acc[mf][nfr], a, b[nfr]);
            }
        }

        // Epilogue: bias+silu, shfl-pair into 4-col runs, red.v4 into g_agg
        const bool evn = ((tig & 1) == 0);
#pragma unroll
        for (int mf = 0; mf < 4; mf++) {
            const int m1 = wr * 64 + mf * 16 + gid;
            const int myr = evn ? m1 : (m1 + 8);
            float* agg = g_agg + srcs[myr] * 128;
#pragma unroll
            for (int nfr = 0; nfr < 4; nfr++) {
                const int c0 = wc * 32 + nfr * 8 + tig * 2;
                float s0 = silu_f(acc[mf][nfr][0] + b2r[nfr * 2]);
                float s1 = silu_f(acc[mf][nfr][1] + b2r[nfr * 2 + 1]);
                float s2 = silu_f(acc[mf][nfr][2] + b2r[nfr * 2]);
                float s3 = silu_f(acc[mf][nfr][3] + b2r[nfr * 2 + 1]);
                float t0 = __shfl_xor_sync(0xFFFFFFFFu, s0, 1);
                float t1 = __shfl_xor_sync(0xFFFFFFFFu, s1, 1);
                float t2 = __shfl_xor_sync(0xFFFFFFFFu, s2, 1);
                float t3 = __shfl_xor_sync(0xFFFFFFFFu, s3, 1);
                if (evn) red_add_v4(agg + c0, s0, s1, t0, t1);
                else     red_add_v4(agg + c0 - 2, t2, t3, s2, s3);
            }
        }
    }
}

// ---------------------------------------------------------------------------
// Kernel 4: node model + residual, persistent. 128 rows/tile, fp16 1-chain.
// ---------------------------------------------------------------------------
#define N_B1   0
#define N_B2   8704
#define N_A    17408
#define N_NB2  26112
#define N_CINV 26240
#define NODE_SMEM_BYTES ((N_CINV + 128) * 4)   // 105,472 B
#define NODE_NTILES ((Nn + 127) / 128)          // 391

__launch_bounds__(512, 1)
__global__ void node_out_kernel(const float* __restrict__ nf,
                                const float* __restrict__ n_w1,
                                const float* __restrict__ n_w2,
                                const float* __restrict__ n_b2,
                                float* __restrict__ out)
{
    uint32_t* smw = (uint32_t*)dyn_smem;
    uint32_t* B1  = smw + N_B1;
    uint32_t* B2  = smw + N_B2;
    uint32_t* A   = smw + N_A;
    float*    NB2 = (float*)(smw + N_NB2);
    float*   cinv = (float*)(smw + N_CINV);

    const int tid  = threadIdx.x;
    const int wid  = tid >> 5;
    const int lane = tid & 31;
    const int gid  = lane >> 2;
    const int tig  = lane & 3;

    if (tid < 128) NB2[tid] = n_b2[tid];
    for (int idx = tid; idx < 8192; idx += 512) {
        int n = idx >> 6, p = idx & 63, k0 = p << 1;
        B1[n * PWS + p] = pack_h2(n_w1[(128 + k0) * 128 + n],
                                  n_w1[(129 + k0) * 128 + n]);
        B2[n * PWS + p] = pack_h2(n_w2[k0 * 128 + n],
                                  n_w2[(k0 + 1) * 128 + n]);
    }

    const int rg  = wid >> 1;
    const int nfh = wid & 1;
    const int ar0 = (rg * 16 + gid) * PWS;
    const int ar1 = ar0 + 8 * PWS;
    const int m1  = rg * 16 + gid;
    const int m2  = m1 + 8;

    for (int tile = blockIdx.x; tile < NODE_NTILES; tile += gridDim.x) {
        const int row0 = tile * 128;
        __syncthreads();
        if (tid < 128) {
            int row = row0 + tid;
            cinv[tid] = (row < Nn) ? 1.0f / fmaxf((float)g_cnt[row], 1.0f) : 0.0f;
        }
        __syncthreads();

        for (int idx = tid; idx < 8192; idx += 512) {
            int m = idx >> 6, p = idx & 63, c0 = p << 1;
            int row = row0 + m;
            float v0 = 0.0f, v1 = 0.0f;
            if (row < Nn) {
                const float2 v = *(const float2*)(g_agg + row * 128 + c0);
                v0 = v.x * cinv[m]; v1 = v.y * cinv[m];
            }
            A[m * PWS + p] = pack_h2(v0, v1);
        }
        __syncthreads();

        float acc[8][4];
#pragma unroll
        for (int j = 0; j < 8; j++)
#pragma unroll
            for (int q = 0; q < 4; q++) acc[j][q] = 0.0f;
#pragma unroll
        for (int ks = 0; ks < 8; ks++) {
            const int kw = ks * 8 + tig;
            uint32_t a[4];
            load_afrag1(a, A, ar0, ar1, kw);
#pragma unroll
            for (int j = 0; j < 8; j++) {
                const int nr = ((nfh * 8 + j) * 8 + gid) * PWS;
                uint32_t b[2] = {B1[nr + kw], B1[nr + kw + 4]};
                mma16816h(acc[j], a, b);
            }
        }
        __syncthreads();

        const int row1 = row0 + m1, row2 = row0 + m2;
#pragma unroll
        for (int j = 0; j < 8; j++) {
            const int col = (nfh * 8 + j) * 8 + tig * 2;
            const int p = col >> 1;
            float2 pc1 = make_float2(0.0f, 0.0f), pc2 = make_float2(0.0f, 0.0f);
            if (row1 < Nn) pc1 = *(const float2*)(g_Pc + row1 * 128 + col);
            if (row2 < Nn) pc2 = *(const float2*)(g_Pc + row2 * 128 + col);
            A[m1 * PWS + p] = pack_h2(silu_f(acc[j][0] + pc1.x),
                                      silu_f(acc[j][1] + pc1.y));
            A[m2 * PWS + p] = pack_h2(silu_f(acc[j][2] + pc2.x),
                                      silu_f(acc[j][3] + pc2.y));
        }
        __syncthreads();

        float acc2[8][4];
#pragma unroll
        for (int j = 0; j < 8; j++)
#pragma unroll
            for (int q = 0; q < 4; q++) acc2[j][q] = 0.0f;
#pragma unroll
        for (int ks = 0; ks < 8; ks++) {
            const int kw = ks * 8 + tig;
            uint32_t a[4];
            load_afrag1(a, A, ar0, ar1, kw);
#pragma unroll
            for (int j = 0; j < 8; j++) {
                const int nr = ((nfh * 8 + j) * 8 + gid) * PWS;
                uint32_t b[2] = {B2[nr + kw], B2[nr + kw + 4]};
                mma16816h(acc2[j], a, b);
            }
        }

#pragma unroll
        for (int j = 0; j < 8; j++) {
            const int col = (nfh * 8 + j) * 8 + tig * 2;
            float b0 = NB2[col], b1 = NB2[col + 1];
            if (row1 < Nn) {
                const float2 x = *(const float2*)(nf + row1 * 128 + col);
                *(float2*)(out + row1 * 128 + col) =
                    make_float2(x.x + silu_f(acc2[j][0] + b0),
                                x.y + silu_f(acc2[j][1] + b1));
            }
            if (row2 < Nn) {
                const float2 x = *(const float2*)(nf + row2 * 128 + col);
                *(float2*)(out + row2 * 128 + col) =
                    make_float2(x.x + silu_f(acc2[j][2] + b0),
                                x.y + silu_f(acc2[j][3] + b1));
            }
        }
    }
}

// ---------------------------------------------------------------------------
extern "C" void kernel_launch(void* const* d_in, const int* in_sizes, int n_in,
                              void* d_out, int out_size)
{
    (void)in_sizes; (void)n_in; (void)out_size;
    const float* nf   = (const float*)d_in[0];
    const float* lat  = (const float*)d_in[2];
    const float* fd   = (const float*)d_in[3];
    const int*   ei   = (const int*)d_in[4];
    const int*   e2g  = (const int*)d_in[5];
    const float* e_w1 = (const float*)d_in[6];
    const float* e_b1 = (const float*)d_in[7];
    const float* e_w2 = (const float*)d_in[8];
    const float* e_b2 = (const float*)d_in[9];
    const float* n_w1 = (const float*)d_in[10];
    const float* n_b1 = (const float*)d_in[11];
    const float* n_w2 = (const float*)d_in[12];
    const float* n_b2 = (const float*)d_in[13];
    float* out = (float*)d_out;

    cudaFuncSetAttribute(prep_node_kernel,
                         cudaFuncAttributeMaxDynamicSharedMemorySize,
                         PREP_SMEM_BYTES);
    cudaFuncSetAttribute(edge_kernel,
                         cudaFuncAttributeMaxDynamicSharedMemorySize,
                         EDGE_SMEM_BYTES);
    cudaFuncSetAttribute(node_out_kernel,
                         cudaFuncAttributeMaxDynamicSharedMemorySize,
                         NODE_SMEM_BYTES);

    prep_node_kernel<<<148, 512, PREP_SMEM_BYTES>>>(nf, e_w1, n_w1, n_b1);
    prep_graph_kernel<<<Gg, 64>>>(lat, e_w1, e_b1);
    edge_kernel<<<296, 256, EDGE_SMEM_BYTES>>>(fd, ei, e2g, e_w1, e_w2, e_b2);
    node_out_kernel<<<148, 512, NODE_SMEM_BYTES>>>(nf, n_w1, n_w2, n_b2, out);
}

// round 13
// speedup vs baseline: 2.0487x; 1.0555x over previous
#include <cuda_runtime.h>
#include <cuda_fp16.h>
#include <cstdint>
#include <cstring>

#define Nn 50000
#define Ee 800000
#define Gg 2048
#define Hh 128

extern __shared__ char dyn_smem[];

// ---------------- device scratch ----------
__device__ uint32_t g_Pa16[Nn * 64];   // fp16x2: nf @ e_w1[0:128]
__device__ uint32_t g_Pb16[Nn * 64];   // fp16x2: nf @ e_w1[128:256]
__device__ uint32_t g_Qb16[Gg * 64];   // fp16x2: lat @ e_w1[256:262] + e_b1
__device__ float    g_Pc[Nn * Hh];     // fp32:   nf @ n_w1[0:128] + n_b1
__device__ uint32_t g_agg16[Nn * 64];  // fp16x2 scatter-sum accumulator
__device__ int      g_cnt[Nn];         // per-node edge count

// silu via hw tanh: x*sigmoid(x) = 0.5*x*(1+tanh(x/2)). 1 MUFU vs 2.
__device__ __forceinline__ float silu_f(float x) {
    float t;
    asm("tanh.approx.f32 %0, %1;" : "=f"(t) : "f"(0.5f * x));
    return 0.5f * x * (1.0f + t);
}

__device__ __forceinline__ uint32_t pack_h2(float v0, float v1) {
    __half2 h = __floats2half2_rn(v0, v1);
    uint32_t u;
    memcpy(&u, &h, 4);
    return u;
}

__device__ __forceinline__ __half2 h2bits(uint32_t u) {
    __half2 h; memcpy(&h, &u, 4); return h;
}
__device__ __forceinline__ uint32_t bitsh2(__half2 h) {
    uint32_t u; memcpy(&u, &h, 4); return u;
}

// fp16x2 silu: h = 0.5x; r = h + h*tanh(h)
__device__ __forceinline__ __half2 silu_h2(__half2 x) {
    __half2 h = __hmul2(x, __float2half2_rn(0.5f));
    uint32_t hb = bitsh2(h), tb;
    asm("tanh.approx.f16x2 %0, %1;" : "=r"(tb) : "r"(hb));
    __half2 t = h2bits(tb);
    return __hfma2(h, t, h);
}

__device__ __forceinline__ void mma16816h(float* d, const uint32_t* a, const uint32_t* b) {
    asm volatile(
        "mma.sync.aligned.m16n8k16.row.col.f32.f16.f16.f32 "
        "{%0,%1,%2,%3}, {%4,%5,%6,%7}, {%8,%9}, {%0,%1,%2,%3};"
        : "+f"(d[0]), "+f"(d[1]), "+f"(d[2]), "+f"(d[3])
        : "r"(a[0]), "r"(a[1]), "r"(a[2]), "r"(a[3]), "r"(b[0]), "r"(b[1]));
}

__device__ __forceinline__ void ldsm_x4(uint32_t* r, uint32_t saddr) {
    asm volatile("ldmatrix.sync.aligned.m8n8.x4.shared.b16 {%0,%1,%2,%3}, [%4];"
        : "=r"(r[0]), "=r"(r[1]), "=r"(r[2]), "=r"(r[3]) : "r"(saddr));
}
__device__ __forceinline__ void ldsm_x2(uint32_t* r, uint32_t saddr) {
    asm volatile("ldmatrix.sync.aligned.m8n8.x2.shared.b16 {%0,%1}, [%2];"
        : "=r"(r[0]), "=r"(r[1]) : "r"(saddr));
}

// vectorized fp16x2 global reduction (4 halves per op)
__device__ __forceinline__ void red2_h2(uint32_t* p, uint32_t a, uint32_t b) {
    asm volatile("red.global.add.noftz.v2.f16x2 [%0], {%1, %2};"
                 :: "l"(p), "r"(a), "r"(b) : "memory");
}

#define PWS 68   // plane word-stride per row (64 pair-words + 4 pad)

__device__ __forceinline__ void load_afrag1(uint32_t* a, const uint32_t* A,
                                            int ar0, int ar1, int kw) {
    a[0] = A[ar0 + kw];     a[1] = A[ar1 + kw];
    a[2] = A[ar0 + kw + 4]; a[3] = A[ar1 + kw + 4];
}

// ---------------------------------------------------------------------------
// Kernel 1: persistent Pa/Pb (fp16) + Pc (fp32) precompute + zero agg/cnt.
// ---------------------------------------------------------------------------
#define P_B0  0
#define P_B1  8704
#define P_B2  17408
#define P_A   26112
#define P_NB1 34816
#define PREP_SMEM_BYTES ((P_NB1 + 128) * 4)   // 139,776 B
#define PREP_NTILES ((Nn + 127) / 128)         // 391

__launch_bounds__(512, 1)
__global__ void prep_node_kernel(const float* __restrict__ nf,
                                 const float* __restrict__ e_w1,
                                 const float* __restrict__ n_w1,
                                 const float* __restrict__ n_b1)
{
    uint32_t* smw = (uint32_t*)dyn_smem;
    uint32_t* Bp[3] = {smw + P_B0, smw + P_B1, smw + P_B2};
    uint32_t* A   = smw + P_A;
    float*    NB1 = (float*)(smw + P_NB1);

    const int tid  = threadIdx.x;
    const int wid  = tid >> 5;
    const int lane = tid & 31;
    const int gid  = lane >> 2;
    const int tig  = lane & 3;

    if (tid < 128) NB1[tid] = n_b1[tid];
    for (int blk = 0; blk < 3; blk++) {
        const float* bsrc = (blk == 0) ? e_w1
                          : (blk == 1) ? (e_w1 + 128 * 128)
                                       : n_w1;
        uint32_t* B = Bp[blk];
        for (int idx = tid; idx < 8192; idx += 512) {
            int n = idx >> 6, p = idx & 63, k0 = p << 1;
            B[n * PWS + p] = pack_h2(bsrc[k0 * 128 + n], bsrc[(k0 + 1) * 128 + n]);
        }
    }

    const int rg  = wid >> 1;
    const int nfh = wid & 1;
    const int ar0 = (rg * 16 + gid) * PWS;
    const int ar1 = ar0 + 8 * PWS;
    const int m1  = rg * 16 + gid;

    for (int tile = blockIdx.x; tile < PREP_NTILES; tile += gridDim.x) {
        const int row0 = tile * 128;
        __syncthreads();
        if (tid < 128 && row0 + tid < Nn) g_cnt[row0 + tid] = 0;
        for (int idx = tid; idx < 8192; idx += 512) {
            int m = idx >> 6, p = idx & 63, c0 = p << 1;
            int row = row0 + m;
            float v0 = 0.0f, v1 = 0.0f;
            if (row < Nn) {
                const float2 v = *(const float2*)(nf + row * 128 + c0);
                v0 = v.x; v1 = v.y;
                g_agg16[row * 64 + p] = 0u;
            }
            A[m * PWS + p] = pack_h2(v0, v1);
        }
        __syncthreads();

        const int row1 = row0 + m1, row2 = row1 + 8;
        for (int blk = 0; blk < 3; blk++) {
            uint32_t* B = Bp[blk];
            float acc[8][4];
#pragma unroll
            for (int j = 0; j < 8; j++)
#pragma unroll
                for (int q = 0; q < 4; q++) acc[j][q] = 0.0f;

#pragma unroll
            for (int ks = 0; ks < 8; ks++) {
                const int kw = ks * 8 + tig;
                uint32_t a[4];
                load_afrag1(a, A, ar0, ar1, kw);
#pragma unroll
                for (int j = 0; j < 8; j++) {
                    const int nr = ((nfh * 8 + j) * 8 + gid) * PWS;
                    uint32_t b[2] = {B[nr + kw], B[nr + kw + 4]};
                    mma16816h(acc[j], a, b);
                }
            }

            if (blk < 2) {
                uint32_t* dst16 = (blk == 0) ? g_Pa16 : g_Pb16;
#pragma unroll
                for (int j = 0; j < 8; j++) {
                    const int col = (nfh * 8 + j) * 8 + tig * 2;
                    const int pw = col >> 1;
                    if (row1 < Nn) dst16[row1 * 64 + pw] = pack_h2(acc[j][0], acc[j][1]);
                    if (row2 < Nn) dst16[row2 * 64 + pw] = pack_h2(acc[j][2], acc[j][3]);
                }
            } else {
#pragma unroll
                for (int j = 0; j < 8; j++) {
                    const int col = (nfh * 8 + j) * 8 + tig * 2;
                    float b0 = NB1[col], b1 = NB1[col + 1];
                    if (row1 < Nn)
                        *(float2*)(g_Pc + row1 * 128 + col) =
                            make_float2(acc[j][0] + b0, acc[j][1] + b1);
                    if (row2 < Nn)
                        *(float2*)(g_Pc + row2 * 128 + col) =
                            make_float2(acc[j][2] + b0, acc[j][3] + b1);
                }
            }
        }
    }
}

// ---------------------------------------------------------------------------
// Kernel 2: per-graph lattice term + edge bias 1 -> fp16x2 packed.
// ---------------------------------------------------------------------------
__global__ void prep_graph_kernel(const float* __restrict__ lat,
                                  const float* __restrict__ e_w1,
                                  const float* __restrict__ e_b1)
{
    const int g = blockIdx.x;
    const int c0 = threadIdx.x * 2;
    float a0 = e_b1[c0], a1 = e_b1[c0 + 1];
#pragma unroll
    for (int k = 0; k < 6; k++) {
        float lv = lat[g * 6 + k];
        a0 += lv * e_w1[(256 + k) * 128 + c0];
        a1 += lv * e_w1[(256 + k) * 128 + c0 + 1];
    }
    g_Qb16[g * 64 + threadIdx.x] = pack_h2(a0, a1);
}

// ---------------------------------------------------------------------------
// Kernel 3: fused edge pipeline. 128 edges/tile, 256 threads, 2 CTAs/SM.
// Phase A: h2 math; MMA: ldmatrix; epilogue: h2 silu + red.v2.f16x2.
// ---------------------------------------------------------------------------
#define TILE_M 128
#define EDGE_NTILES (Ee / TILE_M)      // 6250

#define O_SRC   0
#define O_DST   128
#define O_GS    256
#define O_FDS   384
#define O_W1DH  768
#define O_A     960
#define O_B     (O_A + 128 * PWS)
#define EDGE_SMEM_BYTES ((O_B + 128 * PWS) * 4)   // 73,472 B

__launch_bounds__(256, 2)
__global__ void edge_kernel(const float* __restrict__ frac_diff,
                            const int*   __restrict__ ei,
                            const int*   __restrict__ e2g,
                            const float* __restrict__ e_w1,
                            const float* __restrict__ e_w2,
                            const float* __restrict__ e_b2)
{
    uint32_t* smw = (uint32_t*)dyn_smem;
    int*   srcs = (int*)(smw + O_SRC);
    int*   dsts = (int*)(smw + O_DST);
    int*   gs   = (int*)(smw + O_GS);
    float* fds  = (float*)(smw + O_FDS);
    uint32_t* W1DH = smw + O_W1DH;
    uint32_t* A = smw + O_A;
    uint32_t* B = smw + O_B;

    const int tid  = threadIdx.x;
    const int wid  = tid >> 5;
    const int lane = tid & 31;
    const int gid  = lane >> 2;
    const int tig  = lane & 3;
    const int wr   = wid >> 2;      // 0..1 row-group (64 rows)
    const int wc   = wid & 3;       // 0..3 col-group (32 cols)

    // epilogue bias as fp16x2 registers
    uint32_t b2h[4];
#pragma unroll
    for (int nfr = 0; nfr < 4; nfr++) {
        const int c0 = wc * 32 + nfr * 8 + tig * 2;
        b2h[nfr] = pack_h2(e_b2[c0], e_b2[c0 + 1]);
    }

    // one-time: W1D as fp16x2 [k][word], B = W2^T fp16 plane
    for (int i = tid; i < 192; i += 256) {
        int k = i >> 6, w = i & 63;
        W1DH[i] = pack_h2(e_w1[(262 + k) * 128 + w * 2],
                          e_w1[(262 + k) * 128 + w * 2 + 1]);
    }
    for (int idx = tid; idx < 8192; idx += 256) {
        int n = idx >> 6, p = idx & 63, k0 = p << 1;
        B[n * PWS + p] = pack_h2(e_w2[k0 * 128 + n], e_w2[(k0 + 1) * 128 + n]);
    }

    // tile-invariant ldmatrix addresses
    uint32_t aaddr[4], baddr[4];
    {
        uint32_t A_s = (uint32_t)__cvta_generic_to_shared(A);
        uint32_t B_s = (uint32_t)__cvta_generic_to_shared(B);
        int lsub = lane >> 3;
#pragma unroll
        for (int mf = 0; mf < 4; mf++) {
            int arow = wr * 64 + mf * 16 + (lsub & 1) * 8 + (lane & 7);
            aaddr[mf] = A_s + arow * (PWS * 4) + (lsub >> 1) * 16;
        }
        int bsub = lsub & 1;
#pragma unroll
        for (int nfr = 0; nfr < 4; nfr++) {
            int brow = wc * 32 + nfr * 8 + (lane & 7);
            baddr[nfr] = B_s + brow * (PWS * 4) + bsub * 16;
        }
    }

    const int myrow = tid >> 1;
    const int halfw = (tid & 1) * 32;

    for (int tile = blockIdx.x; tile < EDGE_NTILES; tile += gridDim.x) {
        __syncthreads();
        const int e0 = tile * TILE_M;
        if (tid < 128) {
            int e = e0 + tid;
            int s = ei[e];
            srcs[tid] = s;
            dsts[tid] = ei[Ee + e];
            gs[tid]   = e2g[e];
            atomicAdd(&g_cnt[s], 1);
        }
        for (int i = tid; i < 384; i += 256) fds[i] = frac_diff[e0 * 3 + i];
        __syncthreads();

        // Phase A: per-thread half row, all fp16x2 math
        {
            const int sA = srcs[myrow], dAi = dsts[myrow], gA = gs[myrow];
            const __half2 f0h = __float2half2_rn(fds[myrow * 3 + 0]);
            const __half2 f1h = __float2half2_rn(fds[myrow * 3 + 1]);
            const __half2 f2h = __float2half2_rn(fds[myrow * 3 + 2]);
            const uint32_t* paP = g_Pa16 + sA * 64 + halfw;
            const uint32_t* pbP = g_Pb16 + dAi * 64 + halfw;
            const uint32_t* qbP = g_Qb16 + gA * 64 + halfw;
            const uint32_t* wP  = W1DH + halfw;
            uint32_t* aRow = A + myrow * PWS + halfw;
#pragma unroll
            for (int it = 0; it < 8; it++) {
                uint4 pa = *(const uint4*)(paP + it * 4);
                uint4 pb = *(const uint4*)(pbP + it * 4);
                uint4 qb = *(const uint4*)(qbP + it * 4);
                uint4 w0 = *(const uint4*)(wP + it * 4);
                uint4 w1 = *(const uint4*)(wP + 64 + it * 4);
                uint4 w2 = *(const uint4*)(wP + 128 + it * 4);
                uint4 outw;
                uint32_t paw[4] = {pa.x, pa.y, pa.z, pa.w};
                uint32_t pbw[4] = {pb.x, pb.y, pb.z, pb.w};
                uint32_t qbw[4] = {qb.x, qb.y, qb.z, qb.w};
                uint32_t w0w[4] = {w0.x, w0.y, w0.z, w0.w};
                uint32_t w1w[4] = {w1.x, w1.y, w1.z, w1.w};
                uint32_t w2w[4] = {w2.x, w2.y, w2.z, w2.w};
                uint32_t ow[4];
#pragma unroll
                for (int j = 0; j < 4; j++) {
                    __half2 x = __hadd2(h2bits(paw[j]), h2bits(pbw[j]));
                    x = __hadd2(x, h2bits(qbw[j]));
                    x = __hfma2(f0h, h2bits(w0w[j]), x);
                    x = __hfma2(f1h, h2bits(w1w[j]), x);
                    x = __hfma2(f2h, h2bits(w2w[j]), x);
                    ow[j] = bitsh2(silu_h2(x));
                }
                outw.x = ow[0]; outw.y = ow[1]; outw.z = ow[2]; outw.w = ow[3];
                *(uint4*)(aRow + it * 4) = outw;
            }
        }
        __syncthreads();

        // MMA: ldmatrix fragments, 4 m-frags x 4 n-frags per warp
        float acc[4][4][4];
#pragma unroll
        for (int mf = 0; mf < 4; mf++)
#pragma unroll
            for (int nfr = 0; nfr < 4; nfr++)
#pragma unroll
                for (int q = 0; q < 4; q++) acc[mf][nfr][q] = 0.0f;

#pragma unroll
        for (int ks = 0; ks < 8; ks++) {
            uint32_t b[4][2];
#pragma unroll
            for (int nfr = 0; nfr < 4; nfr++)
                ldsm_x2(b[nfr], baddr[nfr] + ks * 32);
#pragma unroll
            for (int mf = 0; mf < 4; mf++) {
                uint32_t a[4];
                ldsm_x4(a, aaddr[mf] + ks * 32);
#pragma unroll
                for (int nfr = 0; nfr < 4; nfr++)
                    mma16816h(acc[mf][nfr], a, b[nfr]);
            }
        }

        // Epilogue: h2 bias+silu, shfl-pair, red.v2.f16x2 into g_agg16
        const bool evn = ((tig & 1) == 0);
#pragma unroll
        for (int mf = 0; mf < 4; mf++) {
            const int m1 = wr * 64 + mf * 16 + gid;
            uint32_t* agg1 = g_agg16 + srcs[m1] * 64;
            uint32_t* agg2 = g_agg16 + srcs[m1 + 8] * 64;
#pragma unroll
            for (int nfr = 0; nfr < 4; nfr++) {
                const int c0 = wc * 32 + nfr * 8 + tig * 2;
                __half2 hA = __floats2half2_rn(acc[mf][nfr][0], acc[mf][nfr][1]);
                __half2 hB = __floats2half2_rn(acc[mf][nfr][2], acc[mf][nfr][3]);
                hA = silu_h2(__hadd2(hA, h2bits(b2h[nfr])));
                hB = silu_h2(__hadd2(hB, h2bits(b2h[nfr])));
                uint32_t wA = bitsh2(hA), wB = bitsh2(hB);
                uint32_t tA = __shfl_xor_sync(0xFFFFFFFFu, wA, 1);
                uint32_t tB = __shfl_xor_sync(0xFFFFFFFFu, wB, 1);
                if (evn) red2_h2(agg1 + (c0 >> 1), wA, tA);           // row m1
                else     red2_h2(agg2 + ((c0 - 2) >> 1), tB, wB);     // row m1+8
            }
        }
    }
}

// ---------------------------------------------------------------------------
// Kernel 4: node model + residual, persistent. 128 rows/tile, fp16 1-chain.
// Phase A reads fp16x2 agg and scales with HMUL2.
// ---------------------------------------------------------------------------
#define N_B1   0
#define N_B2   8704
#define N_A    17408
#define N_NB2  26112
#define N_CINV 26240
#define NODE_SMEM_BYTES ((N_CINV + 128) * 4)   // 105,472 B
#define NODE_NTILES ((Nn + 127) / 128)          // 391

__launch_bounds__(512, 1)
__global__ void node_out_kernel(const float* __restrict__ nf,
                                const float* __restrict__ n_w1,
                                const float* __restrict__ n_w2,
                                const float* __restrict__ n_b2,
                                float* __restrict__ out)
{
    uint32_t* smw = (uint32_t*)dyn_smem;
    uint32_t* B1  = smw + N_B1;
    uint32_t* B2  = smw + N_B2;
    uint32_t* A   = smw + N_A;
    float*    NB2 = (float*)(smw + N_NB2);
    uint32_t* cinvh = smw + N_CINV;

    const int tid  = threadIdx.x;
    const int wid  = tid >> 5;
    const int lane = tid & 31;
    const int gid  = lane >> 2;
    const int tig  = lane & 3;

    if (tid < 128) NB2[tid] = n_b2[tid];
    for (int idx = tid; idx < 8192; idx += 512) {
        int n = idx >> 6, p = idx & 63, k0 = p << 1;
        B1[n * PWS + p] = pack_h2(n_w1[(128 + k0) * 128 + n],
                                  n_w1[(129 + k0) * 128 + n]);
        B2[n * PWS + p] = pack_h2(n_w2[k0 * 128 + n],
                                  n_w2[(k0 + 1) * 128 + n]);
    }

    const int rg  = wid >> 1;
    const int nfh = wid & 1;
    const int ar0 = (rg * 16 + gid) * PWS;
    const int ar1 = ar0 + 8 * PWS;
    const int m1  = rg * 16 + gid;
    const int m2  = m1 + 8;

    for (int tile = blockIdx.x; tile < NODE_NTILES; tile += gridDim.x) {
        const int row0 = tile * 128;
        __syncthreads();
        if (tid < 128) {
            int row = row0 + tid;
            float ci = (row < Nn) ? 1.0f / fmaxf((float)g_cnt[row], 1.0f) : 0.0f;
            cinvh[tid] = pack_h2(ci, ci);
        }
        __syncthreads();

        for (int idx = tid; idx < 8192; idx += 512) {
            int m = idx >> 6, p = idx & 63;
            int row = row0 + m;
            uint32_t w = 0u;
            if (row < Nn) {
                uint32_t av = g_agg16[row * 64 + p];
                w = bitsh2(__hmul2(h2bits(av), h2bits(cinvh[m])));
            }
            A[m * PWS + p] = w;
        }
        __syncthreads();

        float acc[8][4];
#pragma unroll
        for (int j = 0; j < 8; j++)
#pragma unroll
            for (int q = 0; q < 4; q++) acc[j][q] = 0.0f;
#pragma unroll
        for (int ks = 0; ks < 8; ks++) {
            const int kw = ks * 8 + tig;
            uint32_t a[4];
            load_afrag1(a, A, ar0, ar1, kw);
#pragma unroll
            for (int j = 0; j < 8; j++) {
                const int nr = ((nfh * 8 + j) * 8 + gid) * PWS;
                uint32_t b[2] = {B1[nr + kw], B1[nr + kw + 4]};
                mma16816h(acc[j], a, b);
            }
        }
        __syncthreads();

        const int row1 = row0 + m1, row2 = row0 + m2;
#pragma unroll
        for (int j = 0; j < 8; j++) {
            const int col = (nfh * 8 + j) * 8 + tig * 2;
            const int p = col >> 1;
            float2 pc1 = make_float2(0.0f, 0.0f), pc2 = make_float2(0.0f, 0.0f);
            if (row1 < Nn) pc1 = *(const float2*)(g_Pc + row1 * 128 + col);
            if (row2 < Nn) pc2 = *(const float2*)(g_Pc + row2 * 128 + col);
            A[m1 * PWS + p] = pack_h2(silu_f(acc[j][0] + pc1.x),
                                      silu_f(acc[j][1] + pc1.y));
            A[m2 * PWS + p] = pack_h2(silu_f(acc[j][2] + pc2.x),
                                      silu_f(acc[j][3] + pc2.y));
        }
        __syncthreads();

        float acc2[8][4];
#pragma unroll
        for (int j = 0; j < 8; j++)
#pragma unroll
            for (int q = 0; q < 4; q++) acc2[j][q] = 0.0f;
#pragma unroll
        for (int ks = 0; ks < 8; ks++) {
            const int kw = ks * 8 + tig;
            uint32_t a[4];
            load_afrag1(a, A, ar0, ar1, kw);
#pragma unroll
            for (int j = 0; j < 8; j++) {
                const int nr = ((nfh * 8 + j) * 8 + gid) * PWS;
                uint32_t b[2] = {B2[nr + kw], B2[nr + kw + 4]};
                mma16816h(acc2[j], a, b);
            }
        }

#pragma unroll
        for (int j = 0; j < 8; j++) {
            const int col = (nfh * 8 + j) * 8 + tig * 2;
            float b0 = NB2[col], b1 = NB2[col + 1];
            if (row1 < Nn) {
                const float2 x = *(const float2*)(nf + row1 * 128 + col);
                *(float2*)(out + row1 * 128 + col) =
                    make_float2(x.x + silu_f(acc2[j][0] + b0),
                                x.y + silu_f(acc2[j][1] + b1));
            }
            if (row2 < Nn) {
                const float2 x = *(const float2*)(nf + row2 * 128 + col);
                *(float2*)(out + row2 * 128 + col) =
                    make_float2(x.x + silu_f(acc2[j][2] + b0),
                                x.y + silu_f(acc2[j][3] + b1));
            }
        }
    }
}

// ---------------------------------------------------------------------------
extern "C" void kernel_launch(void* const* d_in, const int* in_sizes, int n_in,
                              void* d_out, int out_size)
{
    (void)in_sizes; (void)n_in; (void)out_size;
    const float* nf   = (const float*)d_in[0];
    const float* lat  = (const float*)d_in[2];
    const float* fd   = (const float*)d_in[3];
    const int*   ei   = (const int*)d_in[4];
    const int*   e2g  = (const int*)d_in[5];
    const float* e_w1 = (const float*)d_in[6];
    const float* e_b1 = (const float*)d_in[7];
    const float* e_w2 = (const float*)d_in[8];
    const float* e_b2 = (const float*)d_in[9];
    const float* n_w1 = (const float*)d_in[10];
    const float* n_b1 = (const float*)d_in[11];
    const float* n_w2 = (const float*)d_in[12];
    const float* n_b2 = (const float*)d_in[13];
    float* out = (float*)d_out;

    cudaFuncSetAttribute(prep_node_kernel,
                         cudaFuncAttributeMaxDynamicSharedMemorySize,
                         PREP_SMEM_BYTES);
    cudaFuncSetAttribute(edge_kernel,
                         cudaFuncAttributeMaxDynamicSharedMemorySize,
                         EDGE_SMEM_BYTES);
    cudaFuncSetAttribute(node_out_kernel,
                         cudaFuncAttributeMaxDynamicSharedMemorySize,
                         NODE_SMEM_BYTES);

    prep_node_kernel<<<148, 512, PREP_SMEM_BYTES>>>(nf, e_w1, n_w1, n_b1);
    prep_graph_kernel<<<Gg, 64>>>(lat, e_w1, e_b1);
    edge_kernel<<<296, 256, EDGE_SMEM_BYTES>>>(fd, ei, e2g, e_w1, e_w2, e_b2);
    node_out_kernel<<<148, 512, NODE_SMEM_BYTES>>>(nf, n_w1, n_w2, n_b2, out);
}

// round 14
// speedup vs baseline: 2.0685x; 1.0097x over previous
#include <cuda_runtime.h>
#include <cuda_fp16.h>
#include <cstdint>
#include <cstring>

#define Nn 50000
#define Ee 800000
#define Gg 2048
#define Hh 128

extern __shared__ char dyn_smem[];

// ---------------- device scratch ----------
__device__ uint32_t g_Pa16[Nn * 64];   // fp16x2: nf @ e_w1[0:128]
__device__ uint32_t g_Pb16[Nn * 64];   // fp16x2: nf @ e_w1[128:256]
__device__ uint32_t g_Qb16[Gg * 64];   // fp16x2: lat @ e_w1[256:262] + e_b1
__device__ float    g_Pc[Nn * Hh];     // fp32:   nf @ n_w1[0:128] + n_b1
__device__ uint32_t g_agg16[Nn * 64];  // fp16x2 scatter-sum accumulator
__device__ int      g_cnt[Nn];         // per-node edge count

// silu via hw tanh: x*sigmoid(x) = 0.5*x*(1+tanh(x/2)). 1 MUFU vs 2.
__device__ __forceinline__ float silu_f(float x) {
    float t;
    asm("tanh.approx.f32 %0, %1;" : "=f"(t) : "f"(0.5f * x));
    return 0.5f * x * (1.0f + t);
}

__device__ __forceinline__ uint32_t pack_h2(float v0, float v1) {
    __half2 h = __floats2half2_rn(v0, v1);
    uint32_t u;
    memcpy(&u, &h, 4);
    return u;
}

__device__ __forceinline__ __half2 h2bits(uint32_t u) {
    __half2 h; memcpy(&h, &u, 4); return h;
}
__device__ __forceinline__ uint32_t bitsh2(__half2 h) {
    uint32_t u; memcpy(&u, &h, 4); return u;
}

// fp16x2 silu: h = 0.5x; r = h + h*tanh(h)
__device__ __forceinline__ __half2 silu_h2(__half2 x) {
    __half2 h = __hmul2(x, __float2half2_rn(0.5f));
    uint32_t hb = bitsh2(h), tb;
    asm("tanh.approx.f16x2 %0, %1;" : "=r"(tb) : "r"(hb));
    __half2 t = h2bits(tb);
    return __hfma2(h, t, h);
}

__device__ __forceinline__ void mma16816h(float* d, const uint32_t* a, const uint32_t* b) {
    asm volatile(
        "mma.sync.aligned.m16n8k16.row.col.f32.f16.f16.f32 "
        "{%0,%1,%2,%3}, {%4,%5,%6,%7}, {%8,%9}, {%0,%1,%2,%3};"
        : "+f"(d[0]), "+f"(d[1]), "+f"(d[2]), "+f"(d[3])
        : "r"(a[0]), "r"(a[1]), "r"(a[2]), "r"(a[3]), "r"(b[0]), "r"(b[1]));
}

__device__ __forceinline__ void ldsm_x4(uint32_t* r, uint32_t saddr) {
    asm volatile("ldmatrix.sync.aligned.m8n8.x4.shared.b16 {%0,%1,%2,%3}, [%4];"
        : "=r"(r[0]), "=r"(r[1]), "=r"(r[2]), "=r"(r[3]) : "r"(saddr));
}
__device__ __forceinline__ void ldsm_x2(uint32_t* r, uint32_t saddr) {
    asm volatile("ldmatrix.sync.aligned.m8n8.x2.shared.b16 {%0,%1}, [%2];"
        : "=r"(r[0]), "=r"(r[1]) : "r"(saddr));
}

// vectorized fp16x2 global reduction (4 halves per op)
__device__ __forceinline__ void red2_h2(uint32_t* p, uint32_t a, uint32_t b) {
    asm volatile("red.global.add.noftz.v2.f16x2 [%0], {%1, %2};"
                 :: "l"(p), "r"(a), "r"(b) : "memory");
}

#define PWS 68   // plane word-stride per row (64 pair-words + 4 pad)

// ---------------------------------------------------------------------------
// Kernel 1: persistent Pa/Pb (fp16) + Pc (fp32) precompute + zero agg/cnt.
// ldmatrix fragment loads.
// ---------------------------------------------------------------------------
#define P_B0  0
#define P_B1  8704
#define P_B2  17408
#define P_A   26112
#define P_NB1 34816
#define PREP_SMEM_BYTES ((P_NB1 + 128) * 4)   // 139,776 B
#define PREP_NTILES ((Nn + 127) / 128)         // 391

__launch_bounds__(512, 1)
__global__ void prep_node_kernel(const float* __restrict__ nf,
                                 const float* __restrict__ e_w1,
                                 const float* __restrict__ n_w1,
                                 const float* __restrict__ n_b1)
{
    uint32_t* smw = (uint32_t*)dyn_smem;
    uint32_t* Bp[3] = {smw + P_B0, smw + P_B1, smw + P_B2};
    uint32_t* A   = smw + P_A;
    float*    NB1 = (float*)(smw + P_NB1);

    const int tid  = threadIdx.x;
    const int wid  = tid >> 5;
    const int lane = tid & 31;
    const int gid  = lane >> 2;
    const int tig  = lane & 3;

    if (tid < 128) NB1[tid] = n_b1[tid];
    for (int blk = 0; blk < 3; blk++) {
        const float* bsrc = (blk == 0) ? e_w1
                          : (blk == 1) ? (e_w1 + 128 * 128)
                                       : n_w1;
        uint32_t* B = Bp[blk];
        for (int idx = tid; idx < 8192; idx += 512) {
            int n = idx >> 6, p = idx & 63, k0 = p << 1;
            B[n * PWS + p] = pack_h2(bsrc[k0 * 128 + n], bsrc[(k0 + 1) * 128 + n]);
        }
    }

    const int rg  = wid >> 1;
    const int nfh = wid & 1;
    const int m1  = rg * 16 + gid;

    // tile-invariant ldmatrix addresses
    uint32_t aaddr, baddr0[3];
    const uint32_t jstride = 8u * (PWS * 4);
    {
        int lsub = lane >> 3;
        int arow = rg * 16 + (lsub & 1) * 8 + (lane & 7);
        aaddr = (uint32_t)__cvta_generic_to_shared(A)
              + arow * (PWS * 4) + (lsub >> 1) * 16;
        int brow = nfh * 64 + (lane & 7);
        uint32_t boff = brow * (PWS * 4) + (lsub & 1) * 16;
        for (int blk = 0; blk < 3; blk++)
            baddr0[blk] = (uint32_t)__cvta_generic_to_shared(Bp[blk]) + boff;
    }

    for (int tile = blockIdx.x; tile < PREP_NTILES; tile += gridDim.x) {
        const int row0 = tile * 128;
        __syncthreads();
        if (tid < 128 && row0 + tid < Nn) g_cnt[row0 + tid] = 0;
        for (int idx = tid; idx < 8192; idx += 512) {
            int m = idx >> 6, p = idx & 63, c0 = p << 1;
            int row = row0 + m;
            float v0 = 0.0f, v1 = 0.0f;
            if (row < Nn) {
                const float2 v = *(const float2*)(nf + row * 128 + c0);
                v0 = v.x; v1 = v.y;
                g_agg16[row * 64 + p] = 0u;
            }
            A[m * PWS + p] = pack_h2(v0, v1);
        }
        __syncthreads();

        const int row1 = row0 + m1, row2 = row1 + 8;
        for (int blk = 0; blk < 3; blk++) {
            float acc[8][4];
#pragma unroll
            for (int j = 0; j < 8; j++)
#pragma unroll
                for (int q = 0; q < 4; q++) acc[j][q] = 0.0f;

#pragma unroll
            for (int ks = 0; ks < 8; ks++) {
                uint32_t a[4];
                ldsm_x4(a, aaddr + ks * 32);
#pragma unroll
                for (int j = 0; j < 8; j++) {
                    uint32_t b[2];
                    ldsm_x2(b, baddr0[blk] + j * jstride + ks * 32);
                    mma16816h(acc[j], a, b);
                }
            }

            if (blk < 2) {
                uint32_t* dst16 = (blk == 0) ? g_Pa16 : g_Pb16;
#pragma unroll
                for (int j = 0; j < 8; j++) {
                    const int col = (nfh * 8 + j) * 8 + tig * 2;
                    const int pw = col >> 1;
                    if (row1 < Nn) dst16[row1 * 64 + pw] = pack_h2(acc[j][0], acc[j][1]);
                    if (row2 < Nn) dst16[row2 * 64 + pw] = pack_h2(acc[j][2], acc[j][3]);
                }
            } else {
#pragma unroll
                for (int j = 0; j < 8; j++) {
                    const int col = (nfh * 8 + j) * 8 + tig * 2;
                    float b0 = NB1[col], b1 = NB1[col + 1];
                    if (row1 < Nn)
                        *(float2*)(g_Pc + row1 * 128 + col) =
                            make_float2(acc[j][0] + b0, acc[j][1] + b1);
                    if (row2 < Nn)
                        *(float2*)(g_Pc + row2 * 128 + col) =
                            make_float2(acc[j][2] + b0, acc[j][3] + b1);
                }
            }
        }
    }
}

// ---------------------------------------------------------------------------
// Kernel 2: per-graph lattice term + edge bias 1 -> fp16x2 packed.
// ---------------------------------------------------------------------------
__global__ void prep_graph_kernel(const float* __restrict__ lat,
                                  const float* __restrict__ e_w1,
                                  const float* __restrict__ e_b1)
{
    const int g = blockIdx.x;
    const int c0 = threadIdx.x * 2;
    float a0 = e_b1[c0], a1 = e_b1[c0 + 1];
#pragma unroll
    for (int k = 0; k < 6; k++) {
        float lv = lat[g * 6 + k];
        a0 += lv * e_w1[(256 + k) * 128 + c0];
        a1 += lv * e_w1[(256 + k) * 128 + c0 + 1];
    }
    g_Qb16[g * 64 + threadIdx.x] = pack_h2(a0, a1);
}

// ---------------------------------------------------------------------------
// Kernel 3: fused edge pipeline. 128 edges/tile, 256 threads, 2 CTAs/SM.
// Phase A: h2 math; MMA: ldmatrix; epilogue: h2 silu + red.v2.f16x2.
// ---------------------------------------------------------------------------
#define TILE_M 128
#define EDGE_NTILES (Ee / TILE_M)      // 6250

#define O_SRC   0
#define O_DST   128
#define O_GS    256
#define O_FDS   384
#define O_W1DH  768
#define O_A     960
#define O_B     (O_A + 128 * PWS)
#define EDGE_SMEM_BYTES ((O_B + 128 * PWS) * 4)   // 73,472 B

__launch_bounds__(256, 2)
__global__ void edge_kernel(const float* __restrict__ frac_diff,
                            const int*   __restrict__ ei,
                            const int*   __restrict__ e2g,
                            const float* __restrict__ e_w1,
                            const float* __restrict__ e_w2,
                            const float* __restrict__ e_b2)
{
    uint32_t* smw = (uint32_t*)dyn_smem;
    int*   srcs = (int*)(smw + O_SRC);
    int*   dsts = (int*)(smw + O_DST);
    int*   gs   = (int*)(smw + O_GS);
    float* fds  = (float*)(smw + O_FDS);
    uint32_t* W1DH = smw + O_W1DH;
    uint32_t* A = smw + O_A;
    uint32_t* B = smw + O_B;

    const int tid  = threadIdx.x;
    const int wid  = tid >> 5;
    const int lane = tid & 31;
    const int gid  = lane >> 2;
    const int tig  = lane & 3;
    const int wr   = wid >> 2;      // 0..1 row-group (64 rows)
    const int wc   = wid & 3;       // 0..3 col-group (32 cols)

    // epilogue bias as fp16x2 registers
    uint32_t b2h[4];
#pragma unroll
    for (int nfr = 0; nfr < 4; nfr++) {
        const int c0 = wc * 32 + nfr * 8 + tig * 2;
        b2h[nfr] = pack_h2(e_b2[c0], e_b2[c0 + 1]);
    }

    // one-time: W1D as fp16x2 [k][word], B = W2^T fp16 plane
    for (int i = tid; i < 192; i += 256) {
        int k = i >> 6, w = i & 63;
        W1DH[i] = pack_h2(e_w1[(262 + k) * 128 + w * 2],
                          e_w1[(262 + k) * 128 + w * 2 + 1]);
    }
    for (int idx = tid; idx < 8192; idx += 256) {
        int n = idx >> 6, p = idx & 63, k0 = p << 1;
        B[n * PWS + p] = pack_h2(e_w2[k0 * 128 + n], e_w2[(k0 + 1) * 128 + n]);
    }

    // tile-invariant ldmatrix addresses
    uint32_t aaddr[4], baddr[4];
    {
        uint32_t A_s = (uint32_t)__cvta_generic_to_shared(A);
        uint32_t B_s = (uint32_t)__cvta_generic_to_shared(B);
        int lsub = lane >> 3;
#pragma unroll
        for (int mf = 0; mf < 4; mf++) {
            int arow = wr * 64 + mf * 16 + (lsub & 1) * 8 + (lane & 7);
            aaddr[mf] = A_s + arow * (PWS * 4) + (lsub >> 1) * 16;
        }
        int bsub = lsub & 1;
#pragma unroll
        for (int nfr = 0; nfr < 4; nfr++) {
            int brow = wc * 32 + nfr * 8 + (lane & 7);
            baddr[nfr] = B_s + brow * (PWS * 4) + bsub * 16;
        }
    }

    const int myrow = tid >> 1;
    const int halfw = (tid & 1) * 32;

    for (int tile = blockIdx.x; tile < EDGE_NTILES; tile += gridDim.x) {
        __syncthreads();
        const int e0 = tile * TILE_M;
        if (tid < 128) {
            int e = e0 + tid;
            int s = ei[e];
            srcs[tid] = s;
            dsts[tid] = ei[Ee + e];
            gs[tid]   = e2g[e];
            atomicAdd(&g_cnt[s], 1);
        }
        for (int i = tid; i < 384; i += 256) fds[i] = frac_diff[e0 * 3 + i];
        __syncthreads();

        // Phase A: per-thread half row, all fp16x2 math
        {
            const int sA = srcs[myrow], dAi = dsts[myrow], gA = gs[myrow];
            const __half2 f0h = __float2half2_rn(fds[myrow * 3 + 0]);
            const __half2 f1h = __float2half2_rn(fds[myrow * 3 + 1]);
            const __half2 f2h = __float2half2_rn(fds[myrow * 3 + 2]);
            const uint32_t* paP = g_Pa16 + sA * 64 + halfw;
            const uint32_t* pbP = g_Pb16 + dAi * 64 + halfw;
            const uint32_t* qbP = g_Qb16 + gA * 64 + halfw;
            const uint32_t* wP  = W1DH + halfw;
            uint32_t* aRow = A + myrow * PWS + halfw;
#pragma unroll
            for (int it = 0; it < 8; it++) {
                uint4 pa = *(const uint4*)(paP + it * 4);
                uint4 pb = *(const uint4*)(pbP + it * 4);
                uint4 qb = *(const uint4*)(qbP + it * 4);
                uint4 w0 = *(const uint4*)(wP + it * 4);
                uint4 w1 = *(const uint4*)(wP + 64 + it * 4);
                uint4 w2 = *(const uint4*)(wP + 128 + it * 4);
                uint4 outw;
                uint32_t paw[4] = {pa.x, pa.y, pa.z, pa.w};
                uint32_t pbw[4] = {pb.x, pb.y, pb.z, pb.w};
                uint32_t qbw[4] = {qb.x, qb.y, qb.z, qb.w};
                uint32_t w0w[4] = {w0.x, w0.y, w0.z, w0.w};
                uint32_t w1w[4] = {w1.x, w1.y, w1.z, w1.w};
                uint32_t w2w[4] = {w2.x, w2.y, w2.z, w2.w};
                uint32_t ow[4];
#pragma unroll
                for (int j = 0; j < 4; j++) {
                    __half2 x = __hadd2(h2bits(paw[j]), h2bits(pbw[j]));
                    x = __hadd2(x, h2bits(qbw[j]));
                    x = __hfma2(f0h, h2bits(w0w[j]), x);
                    x = __hfma2(f1h, h2bits(w1w[j]), x);
                    x = __hfma2(f2h, h2bits(w2w[j]), x);
                    ow[j] = bitsh2(silu_h2(x));
                }
                outw.x = ow[0]; outw.y = ow[1]; outw.z = ow[2]; outw.w = ow[3];
                *(uint4*)(aRow + it * 4) = outw;
            }
        }
        __syncthreads();

        // MMA: ldmatrix fragments, 4 m-frags x 4 n-frags per warp
        float acc[4][4][4];
#pragma unroll
        for (int mf = 0; mf < 4; mf++)
#pragma unroll
            for (int nfr = 0; nfr < 4; nfr++)
#pragma unroll
                for (int q = 0; q < 4; q++) acc[mf][nfr][q] = 0.0f;

#pragma unroll
        for (int ks = 0; ks < 8; ks++) {
            uint32_t b[4][2];
#pragma unroll
            for (int nfr = 0; nfr < 4; nfr++)
                ldsm_x2(b[nfr], baddr[nfr] + ks * 32);
#pragma unroll
            for (int mf = 0; mf < 4; mf++) {
                uint32_t a[4];
                ldsm_x4(a, aaddr[mf] + ks * 32);
#pragma unroll
                for (int nfr = 0; nfr < 4; nfr++)
                    mma16816h(acc[mf][nfr], a, b[nfr]);
            }
        }

        // Epilogue: h2 bias+silu, shfl-pair, red.v2.f16x2 into g_agg16
        const bool evn = ((tig & 1) == 0);
#pragma unroll
        for (int mf = 0; mf < 4; mf++) {
            const int m1 = wr * 64 + mf * 16 + gid;
            uint32_t* agg1 = g_agg16 + srcs[m1] * 64;
            uint32_t* agg2 = g_agg16 + srcs[m1 + 8] * 64;
#pragma unroll
            for (int nfr = 0; nfr < 4; nfr++) {
                const int c0 = wc * 32 + nfr * 8 + tig * 2;
                __half2 hA = __floats2half2_rn(acc[mf][nfr][0], acc[mf][nfr][1]);
                __half2 hB = __floats2half2_rn(acc[mf][nfr][2], acc[mf][nfr][3]);
                hA = silu_h2(__hadd2(hA, h2bits(b2h[nfr])));
                hB = silu_h2(__hadd2(hB, h2bits(b2h[nfr])));
                uint32_t wA = bitsh2(hA), wB = bitsh2(hB);
                uint32_t tA = __shfl_xor_sync(0xFFFFFFFFu, wA, 1);
                uint32_t tB = __shfl_xor_sync(0xFFFFFFFFu, wB, 1);
                if (evn) red2_h2(agg1 + (c0 >> 1), wA, tA);           // row m1
                else     red2_h2(agg2 + ((c0 - 2) >> 1), tB, wB);     // row m1+8
            }
        }
    }
}

// ---------------------------------------------------------------------------
// Kernel 4: node model + residual, persistent. 128 rows/tile.
// ldmatrix fragment loads for both GEMMs.
// ---------------------------------------------------------------------------
#define N_B1   0
#define N_B2   8704
#define N_A    17408
#define N_NB2  26112
#define N_CINV 26240
#define NODE_SMEM_BYTES ((N_CINV + 128) * 4)   // 105,472 B
#define NODE_NTILES ((Nn + 127) / 128)          // 391

__launch_bounds__(512, 1)
__global__ void node_out_kernel(const float* __restrict__ nf,
                                const float* __restrict__ n_w1,
                                const float* __restrict__ n_w2,
                                const float* __restrict__ n_b2,
                                float* __restrict__ out)
{
    uint32_t* smw = (uint32_t*)dyn_smem;
    uint32_t* B1  = smw + N_B1;
    uint32_t* B2  = smw + N_B2;
    uint32_t* A   = smw + N_A;
    float*    NB2 = (float*)(smw + N_NB2);
    uint32_t* cinvh = smw + N_CINV;

    const int tid  = threadIdx.x;
    const int wid  = tid >> 5;
    const int lane = tid & 31;
    const int gid  = lane >> 2;
    const int tig  = lane & 3;

    if (tid < 128) NB2[tid] = n_b2[tid];
    for (int idx = tid; idx < 8192; idx += 512) {
        int n = idx >> 6, p = idx & 63, k0 = p << 1;
        B1[n * PWS + p] = pack_h2(n_w1[(128 + k0) * 128 + n],
                                  n_w1[(129 + k0) * 128 + n]);
        B2[n * PWS + p] = pack_h2(n_w2[k0 * 128 + n],
                                  n_w2[(k0 + 1) * 128 + n]);
    }

    const int rg  = wid >> 1;
    const int nfh = wid & 1;
    const int m1  = rg * 16 + gid;
    const int m2  = m1 + 8;

    // tile-invariant ldmatrix addresses
    uint32_t aaddr, b1addr, b2addr;
    const uint32_t jstride = 8u * (PWS * 4);
    {
        int lsub = lane >> 3;
        int arow = rg * 16 + (lsub & 1) * 8 + (lane & 7);
        aaddr = (uint32_t)__cvta_generic_to_shared(A)
              + arow * (PWS * 4) + (lsub >> 1) * 16;
        int brow = nfh * 64 + (lane & 7);
        uint32_t boff = brow * (PWS * 4) + (lsub & 1) * 16;
        b1addr = (uint32_t)__cvta_generic_to_shared(B1) + boff;
        b2addr = (uint32_t)__cvta_generic_to_shared(B2) + boff;
    }

    for (int tile = blockIdx.x; tile < NODE_NTILES; tile += gridDim.x) {
        const int row0 = tile * 128;
        __syncthreads();
        if (tid < 128) {
            int row = row0 + tid;
            float ci = (row < Nn) ? 1.0f / fmaxf((float)g_cnt[row], 1.0f) : 0.0f;
            cinvh[tid] = pack_h2(ci, ci);
        }
        __syncthreads();

        for (int idx = tid; idx < 8192; idx += 512) {
            int m = idx >> 6, p = idx & 63;
            int row = row0 + m;
            uint32_t w = 0u;
            if (row < Nn) {
                uint32_t av = g_agg16[row * 64 + p];
                w = bitsh2(__hmul2(h2bits(av), h2bits(cinvh[m])));
            }
            A[m * PWS + p] = w;
        }
        __syncthreads();

        float acc[8][4];
#pragma unroll
        for (int j = 0; j < 8; j++)
#pragma unroll
            for (int q = 0; q < 4; q++) acc[j][q] = 0.0f;
#pragma unroll
        for (int ks = 0; ks < 8; ks++) {
            uint32_t a[4];
            ldsm_x4(a, aaddr + ks * 32);
#pragma unroll
            for (int j = 0; j < 8; j++) {
                uint32_t b[2];
                ldsm_x2(b, b1addr + j * jstride + ks * 32);
                mma16816h(acc[j], a, b);
            }
        }
        __syncthreads();

        const int row1 = row0 + m1, row2 = row0 + m2;
#pragma unroll
        for (int j = 0; j < 8; j++) {
            const int col = (nfh * 8 + j) * 8 + tig * 2;
            const int p = col >> 1;
            float2 pc1 = make_float2(0.0f, 0.0f), pc2 = make_float2(0.0f, 0.0f);
            if (row1 < Nn) pc1 = *(const float2*)(g_Pc + row1 * 128 + col);
            if (row2 < Nn) pc2 = *(const float2*)(g_Pc + row2 * 128 + col);
            A[m1 * PWS + p] = pack_h2(silu_f(acc[j][0] + pc1.x),
                                      silu_f(acc[j][1] + pc1.y));
            A[m2 * PWS + p] = pack_h2(silu_f(acc[j][2] + pc2.x),
                                      silu_f(acc[j][3] + pc2.y));
        }
        __syncthreads();

        float acc2[8][4];
#pragma unroll
        for (int j = 0; j < 8; j++)
#pragma unroll
            for (int q = 0; q < 4; q++) acc2[j][q] = 0.0f;
#pragma unroll
        for (int ks = 0; ks < 8; ks++) {
            uint32_t a[4];
            ldsm_x4(a, aaddr + ks * 32);
#pragma unroll
            for (int j = 0; j < 8; j++) {
                uint32_t b[2];
                ldsm_x2(b, b2addr + j * jstride + ks * 32);
                mma16816h(acc2[j], a, b);
            }
        }

#pragma unroll
        for (int j = 0; j < 8; j++) {
            const int col = (nfh * 8 + j) * 8 + tig * 2;
            float b0 = NB2[col], b1 = NB2[col + 1];
            if (row1 < Nn) {
                const float2 x = *(const float2*)(nf + row1 * 128 + col);
                *(float2*)(out + row1 * 128 + col) =
                    make_float2(x.x + silu_f(acc2[j][0] + b0),
                                x.y + silu_f(acc2[j][1] + b1));
            }
            if (row2 < Nn) {
                const float2 x = *(const float2*)(nf + row2 * 128 + col);
                *(float2*)(out + row2 * 128 + col) =
                    make_float2(x.x + silu_f(acc2[j][2] + b0),
                                x.y + silu_f(acc2[j][3] + b1));
            }
        }
    }
}

// ---------------------------------------------------------------------------
extern "C" void kernel_launch(void* const* d_in, const int* in_sizes, int n_in,
                              void* d_out, int out_size)
{
    (void)in_sizes; (void)n_in; (void)out_size;
    const float* nf   = (const float*)d_in[0];
    const float* lat  = (const float*)d_in[2];
    const float* fd   = (const float*)d_in[3];
    const int*   ei   = (const int*)d_in[4];
    const int*   e2g  = (const int*)d_in[5];
    const float* e_w1 = (const float*)d_in[6];
    const float* e_b1 = (const float*)d_in[7];
    const float* e_w2 = (const float*)d_in[8];
    const float* e_b2 = (const float*)d_in[9];
    const float* n_w1 = (const float*)d_in[10];
    const float* n_b1 = (const float*)d_in[11];
    const float* n_w2 = (const float*)d_in[12];
    const float* n_b2 = (const float*)d_in[13];
    float* out = (float*)d_out;

    cudaFuncSetAttribute(prep_node_kernel,
                         cudaFuncAttributeMaxDynamicSharedMemorySize,
                         PREP_SMEM_BYTES);
    cudaFuncSetAttribute(edge_kernel,
                         cudaFuncAttributeMaxDynamicSharedMemorySize,
                         EDGE_SMEM_BYTES);
    cudaFuncSetAttribute(node_out_kernel,
                         cudaFuncAttributeMaxDynamicSharedMemorySize,
                         NODE_SMEM_BYTES);

    prep_node_kernel<<<148, 512, PREP_SMEM_BYTES>>>(nf, e_w1, n_w1, n_b1);
    prep_graph_kernel<<<Gg, 64>>>(lat, e_w1, e_b1);
    edge_kernel<<<296, 256, EDGE_SMEM_BYTES>>>(fd, ei, e2g, e_w1, e_w2, e_b2);
    node_out_kernel<<<148, 512, NODE_SMEM_BYTES>>>(nf, n_w1, n_w2, n_b2, out);
}

// round 15
// speedup vs baseline: 2.6942x; 1.3025x over previous
#include <cuda_runtime.h>
#include <cuda_fp16.h>
#include <cstdint>
#include <cstring>

#define Nn 50000
#define Ee 800000
#define Gg 2048
#define Hh 128

extern __shared__ char dyn_smem[];

// ---------------- device scratch ----------
__device__ uint32_t g_Pa16[Nn * 64];   // fp16x2: nf @ e_w1[0:128]
__device__ uint32_t g_Pb16[Nn * 64];   // fp16x2: nf @ e_w1[128:256]
__device__ uint32_t g_Qb16[Gg * 64];   // fp16x2: lat @ e_w1[256:262] + e_b1
__device__ float    g_Pc[Nn * Hh];     // fp32:   nf @ n_w1[0:128] + n_b1
__device__ uint32_t g_agg16[Nn * 64];  // fp16x2 scatter-sum accumulator
__device__ int      g_cnt[Nn];         // per-node edge count

// silu via hw tanh: x*sigmoid(x) = 0.5*x*(1+tanh(x/2)). 1 MUFU vs 2.
__device__ __forceinline__ float silu_f(float x) {
    float t;
    asm("tanh.approx.f32 %0, %1;" : "=f"(t) : "f"(0.5f * x));
    return 0.5f * x * (1.0f + t);
}

__device__ __forceinline__ uint32_t pack_h2(float v0, float v1) {
    __half2 h = __floats2half2_rn(v0, v1);
    uint32_t u;
    memcpy(&u, &h, 4);
    return u;
}

__device__ __forceinline__ __half2 h2bits(uint32_t u) {
    __half2 h; memcpy(&h, &u, 4); return h;
}
__device__ __forceinline__ uint32_t bitsh2(__half2 h) {
    uint32_t u; memcpy(&u, &h, 4); return u;
}

// fp16x2 silu: h = 0.5x; r = h + h*tanh(h)
__device__ __forceinline__ __half2 silu_h2(__half2 x) {
    __half2 h = __hmul2(x, __float2half2_rn(0.5f));
    uint32_t hb = bitsh2(h), tb;
    asm("tanh.approx.f16x2 %0, %1;" : "=r"(tb) : "r"(hb));
    __half2 t = h2bits(tb);
    return __hfma2(h, t, h);
}

__device__ __forceinline__ void mma16816h(float* d, const uint32_t* a, const uint32_t* b) {
    asm volatile(
        "mma.sync.aligned.m16n8k16.row.col.f32.f16.f16.f32 "
        "{%0,%1,%2,%3}, {%4,%5,%6,%7}, {%8,%9}, {%0,%1,%2,%3};"
        : "+f"(d[0]), "+f"(d[1]), "+f"(d[2]), "+f"(d[3])
        : "r"(a[0]), "r"(a[1]), "r"(a[2]), "r"(a[3]), "r"(b[0]), "r"(b[1]));
}

__device__ __forceinline__ void ldsm_x4(uint32_t* r, uint32_t saddr) {
    asm volatile("ldmatrix.sync.aligned.m8n8.x4.shared.b16 {%0,%1,%2,%3}, [%4];"
        : "=r"(r[0]), "=r"(r[1]), "=r"(r[2]), "=r"(r[3]) : "r"(saddr));
}
__device__ __forceinline__ void ldsm_x2(uint32_t* r, uint32_t saddr) {
    asm volatile("ldmatrix.sync.aligned.m8n8.x2.shared.b16 {%0,%1}, [%2];"
        : "=r"(r[0]), "=r"(r[1]) : "r"(saddr));
}

// vectorized fp16x2 global reduction (4 halves per op)
__device__ __forceinline__ void red2_h2(uint32_t* p, uint32_t a, uint32_t b) {
    asm volatile("red.global.add.noftz.v2.f16x2 [%0], {%1, %2};"
                 :: "l"(p), "r"(a), "r"(b) : "memory");
}

#define PWS 68   // plane word-stride per row (64 pair-words + 4 pad)

// ---------------------------------------------------------------------------
// Kernel 1: persistent Pa/Pb (fp16) + Pc (fp32) precompute + zero agg/cnt.
// ldmatrix fragment loads.
// ---------------------------------------------------------------------------
#define P_B0  0
#define P_B1  8704
#define P_B2  17408
#define P_A   26112
#define P_NB1 34816
#define PREP_SMEM_BYTES ((P_NB1 + 128) * 4)   // 139,776 B
#define PREP_NTILES ((Nn + 127) / 128)         // 391

__launch_bounds__(512, 1)
__global__ void prep_node_kernel(const float* __restrict__ nf,
                                 const float* __restrict__ e_w1,
                                 const float* __restrict__ n_w1,
                                 const float* __restrict__ n_b1)
{
    uint32_t* smw = (uint32_t*)dyn_smem;
    uint32_t* Bp[3] = {smw + P_B0, smw + P_B1, smw + P_B2};
    uint32_t* A   = smw + P_A;
    float*    NB1 = (float*)(smw + P_NB1);

    const int tid  = threadIdx.x;
    const int wid  = tid >> 5;
    const int lane = tid & 31;
    const int gid  = lane >> 2;
    const int tig  = lane & 3;

    if (tid < 128) NB1[tid] = n_b1[tid];
    for (int blk = 0; blk < 3; blk++) {
        const float* bsrc = (blk == 0) ? e_w1
                          : (blk == 1) ? (e_w1 + 128 * 128)
                                       : n_w1;
        uint32_t* B = Bp[blk];
        for (int idx = tid; idx < 8192; idx += 512) {
            int n = idx >> 6, p = idx & 63, k0 = p << 1;
            B[n * PWS + p] = pack_h2(bsrc[k0 * 128 + n], bsrc[(k0 + 1) * 128 + n]);
        }
    }

    const int rg  = wid >> 1;
    const int nfh = wid & 1;
    const int m1  = rg * 16 + gid;

    // tile-invariant ldmatrix addresses
    uint32_t aaddr, baddr0[3];
    const uint32_t jstride = 8u * (PWS * 4);
    {
        int lsub = lane >> 3;
        int arow = rg * 16 + (lsub & 1) * 8 + (lane & 7);
        aaddr = (uint32_t)__cvta_generic_to_shared(A)
              + arow * (PWS * 4) + (lsub >> 1) * 16;
        int brow = nfh * 64 + (lane & 7);
        uint32_t boff = brow * (PWS * 4) + (lsub & 1) * 16;
        for (int blk = 0; blk < 3; blk++)
            baddr0[blk] = (uint32_t)__cvta_generic_to_shared(Bp[blk]) + boff;
    }

    for (int tile = blockIdx.x; tile < PREP_NTILES; tile += gridDim.x) {
        const int row0 = tile * 128;
        __syncthreads();
        if (tid < 128 && row0 + tid < Nn) g_cnt[row0 + tid] = 0;
        for (int idx = tid; idx < 8192; idx += 512) {
            int m = idx >> 6, p = idx & 63, c0 = p << 1;
            int row = row0 + m;
            float v0 = 0.0f, v1 = 0.0f;
            if (row < Nn) {
                const float2 v = *(const float2*)(nf + row * 128 + c0);
                v0 = v.x; v1 = v.y;
                g_agg16[row * 64 + p] = 0u;
            }
            A[m * PWS + p] = pack_h2(v0, v1);
        }
        __syncthreads();

        const int row1 = row0 + m1, row2 = row1 + 8;
        for (int blk = 0; blk < 3; blk++) {
            float acc[8][4];
#pragma unroll
            for (int j = 0; j < 8; j++)
#pragma unroll
                for (int q = 0; q < 4; q++) acc[j][q] = 0.0f;

#pragma unroll
            for (int ks = 0; ks < 8; ks++) {
                uint32_t a[4];
                ldsm_x4(a, aaddr + ks * 32);
#pragma unroll
                for (int j = 0; j < 8; j++) {
                    uint32_t b[2];
                    ldsm_x2(b, baddr0[blk] + j * jstride + ks * 32);
                    mma16816h(acc[j], a, b);
                }
            }

            if (blk < 2) {
                uint32_t* dst16 = (blk == 0) ? g_Pa16 : g_Pb16;
#pragma unroll
                for (int j = 0; j < 8; j++) {
                    const int col = (nfh * 8 + j) * 8 + tig * 2;
                    const int pw = col >> 1;
                    if (row1 < Nn) dst16[row1 * 64 + pw] = pack_h2(acc[j][0], acc[j][1]);
                    if (row2 < Nn) dst16[row2 * 64 + pw] = pack_h2(acc[j][2], acc[j][3]);
                }
            } else {
#pragma unroll
                for (int j = 0; j < 8; j++) {
                    const int col = (nfh * 8 + j) * 8 + tig * 2;
                    float b0 = NB1[col], b1 = NB1[col + 1];
                    if (row1 < Nn)
                        *(float2*)(g_Pc + row1 * 128 + col) =
                            make_float2(acc[j][0] + b0, acc[j][1] + b1);
                    if (row2 < Nn)
                        *(float2*)(g_Pc + row2 * 128 + col) =
                            make_float2(acc[j][2] + b0, acc[j][3] + b1);
                }
            }
        }
    }
}

// ---------------------------------------------------------------------------
// Kernel 2: per-graph lattice term + edge bias 1 -> fp16x2 packed.
// ---------------------------------------------------------------------------
__global__ void prep_graph_kernel(const float* __restrict__ lat,
                                  const float* __restrict__ e_w1,
                                  const float* __restrict__ e_b1)
{
    const int g = blockIdx.x;
    const int c0 = threadIdx.x * 2;
    float a0 = e_b1[c0], a1 = e_b1[c0 + 1];
#pragma unroll
    for (int k = 0; k < 6; k++) {
        float lv = lat[g * 6 + k];
        a0 += lv * e_w1[(256 + k) * 128 + c0];
        a1 += lv * e_w1[(256 + k) * 128 + c0 + 1];
    }
    g_Qb16[g * 64 + threadIdx.x] = pack_h2(a0, a1);
}

// ---------------------------------------------------------------------------
// Kernel 3: fused edge pipeline. 128 edges/tile, 256 threads, 2 CTAs/SM.
// Phase A: line-coalesced warp-cooperative gather (16 lanes per row, each
// lane a fixed 16B column chunk -> 4 wavefronts per LDG.128 instead of 32).
// MMA: ldmatrix; epilogue: h2 silu + red.v2.f16x2.
// ---------------------------------------------------------------------------
#define TILE_M 128
#define EDGE_NTILES (Ee / TILE_M)      // 6250

#define O_SRC   0
#define O_DST   128
#define O_GS    256
#define O_FDS   384
#define O_A     768
#define O_B     (O_A + 128 * PWS)
#define EDGE_SMEM_BYTES ((O_B + 128 * PWS) * 4)   // 72,704 B

__launch_bounds__(256, 2)
__global__ void edge_kernel(const float* __restrict__ frac_diff,
                            const int*   __restrict__ ei,
                            const int*   __restrict__ e2g,
                            const float* __restrict__ e_w1,
                            const float* __restrict__ e_w2,
                            const float* __restrict__ e_b2)
{
    uint32_t* smw = (uint32_t*)dyn_smem;
    int*   srcs = (int*)(smw + O_SRC);
    int*   dsts = (int*)(smw + O_DST);
    int*   gs   = (int*)(smw + O_GS);
    float* fds  = (float*)(smw + O_FDS);
    uint32_t* A = smw + O_A;
    uint32_t* B = smw + O_B;

    const int tid  = threadIdx.x;
    const int wid  = tid >> 5;
    const int lane = tid & 31;
    const int gid  = lane >> 2;
    const int tig  = lane & 3;
    const int wr   = wid >> 2;      // 0..1 row-group (64 rows)
    const int wc   = wid & 3;       // 0..3 col-group (32 cols)

    // epilogue bias as fp16x2 registers
    uint32_t b2h[4];
#pragma unroll
    for (int nfr = 0; nfr < 4; nfr++) {
        const int c0 = wc * 32 + nfr * 8 + tig * 2;
        b2h[nfr] = pack_h2(e_b2[c0], e_b2[c0 + 1]);
    }

    // Phase-A lane geometry: 16 lanes per row, fixed 4-word column chunk
    const int wordpos = (lane & 15) * 4;     // words wordpos..wordpos+3
    const int rsel    = lane >> 4;           // 0 or 1 (row within pair)
    // hoisted w1d chunk for this lane's columns (3 k-rows x 4 words)
    uint32_t w1dc[3][4];
#pragma unroll
    for (int k = 0; k < 3; k++)
#pragma unroll
        for (int j = 0; j < 4; j++) {
            int c = (wordpos + j) * 2;
            w1dc[k][j] = pack_h2(e_w1[(262 + k) * 128 + c],
                                 e_w1[(262 + k) * 128 + c + 1]);
        }

    // one-time: B = W2^T fp16 plane
    for (int idx = tid; idx < 8192; idx += 256) {
        int n = idx >> 6, p = idx & 63, k0 = p << 1;
        B[n * PWS + p] = pack_h2(e_w2[k0 * 128 + n], e_w2[(k0 + 1) * 128 + n]);
    }

    // tile-invariant ldmatrix addresses
    uint32_t aaddr[4], baddr[4];
    {
        uint32_t A_s = (uint32_t)__cvta_generic_to_shared(A);
        uint32_t B_s = (uint32_t)__cvta_generic_to_shared(B);
        int lsub = lane >> 3;
#pragma unroll
        for (int mf = 0; mf < 4; mf++) {
            int arow = wr * 64 + mf * 16 + (lsub & 1) * 8 + (lane & 7);
            aaddr[mf] = A_s + arow * (PWS * 4) + (lsub >> 1) * 16;
        }
        int bsub = lsub & 1;
#pragma unroll
        for (int nfr = 0; nfr < 4; nfr++) {
            int brow = wc * 32 + nfr * 8 + (lane & 7);
            baddr[nfr] = B_s + brow * (PWS * 4) + bsub * 16;
        }
    }

    for (int tile = blockIdx.x; tile < EDGE_NTILES; tile += gridDim.x) {
        __syncthreads();
        const int e0 = tile * TILE_M;
        if (tid < 128) {
            int e = e0 + tid;
            int s = ei[e];
            srcs[tid] = s;
            dsts[tid] = ei[Ee + e];
            gs[tid]   = e2g[e];
            atomicAdd(&g_cnt[s], 1);
        }
        for (int i = tid; i < 384; i += 256) fds[i] = frac_diff[e0 * 3 + i];
        __syncthreads();

        // Phase A: line-coalesced gather + h2 combine + silu
#pragma unroll
        for (int it = 0; it < 8; it++) {
            const int m = wid * 16 + it * 2 + rsel;
            const int sA = srcs[m], dAi = dsts[m], gA = gs[m];
            const __half2 f0h = __float2half2_rn(fds[m * 3 + 0]);
            const __half2 f1h = __float2half2_rn(fds[m * 3 + 1]);
            const __half2 f2h = __float2half2_rn(fds[m * 3 + 2]);
            uint4 pa = *(const uint4*)(g_Pa16 + sA * 64 + wordpos);
            uint4 pb = *(const uint4*)(g_Pb16 + dAi * 64 + wordpos);
            uint4 qb = *(const uint4*)(g_Qb16 + gA * 64 + wordpos);
            uint32_t paw[4] = {pa.x, pa.y, pa.z, pa.w};
            uint32_t pbw[4] = {pb.x, pb.y, pb.z, pb.w};
            uint32_t qbw[4] = {qb.x, qb.y, qb.z, qb.w};
            uint32_t ow[4];
#pragma unroll
            for (int j = 0; j < 4; j++) {
                __half2 x = __hadd2(h2bits(paw[j]), h2bits(pbw[j]));
                x = __hadd2(x, h2bits(qbw[j]));
                x = __hfma2(f0h, h2bits(w1dc[0][j]), x);
                x = __hfma2(f1h, h2bits(w1dc[1][j]), x);
                x = __hfma2(f2h, h2bits(w1dc[2][j]), x);
                ow[j] = bitsh2(silu_h2(x));
            }
            uint4 outw;
            outw.x = ow[0]; outw.y = ow[1]; outw.z = ow[2]; outw.w = ow[3];
            *(uint4*)(A + m * PWS + wordpos) = outw;
        }
        __syncthreads();

        // MMA: ldmatrix fragments, 4 m-frags x 4 n-frags per warp
        float acc[4][4][4];
#pragma unroll
        for (int mf = 0; mf < 4; mf++)
#pragma unroll
            for (int nfr = 0; nfr < 4; nfr++)
#pragma unroll
                for (int q = 0; q < 4; q++) acc[mf][nfr][q] = 0.0f;

#pragma unroll
        for (int ks = 0; ks < 8; ks++) {
            uint32_t b[4][2];
#pragma unroll
            for (int nfr = 0; nfr < 4; nfr++)
                ldsm_x2(b[nfr], baddr[nfr] + ks * 32);
#pragma unroll
            for (int mf = 0; mf < 4; mf++) {
                uint32_t a[4];
                ldsm_x4(a, aaddr[mf] + ks * 32);
#pragma unroll
                for (int nfr = 0; nfr < 4; nfr++)
                    mma16816h(acc[mf][nfr], a, b[nfr]);
            }
        }

        // Epilogue: h2 bias+silu, shfl-pair, red.v2.f16x2 into g_agg16
        const bool evn = ((tig & 1) == 0);
#pragma unroll
        for (int mf = 0; mf < 4; mf++) {
            const int m1 = wr * 64 + mf * 16 + gid;
            uint32_t* agg1 = g_agg16 + srcs[m1] * 64;
            uint32_t* agg2 = g_agg16 + srcs[m1 + 8] * 64;
#pragma unroll
            for (int nfr = 0; nfr < 4; nfr++) {
                const int c0 = wc * 32 + nfr * 8 + tig * 2;
                __half2 hA = __floats2half2_rn(acc[mf][nfr][0], acc[mf][nfr][1]);
                __half2 hB = __floats2half2_rn(acc[mf][nfr][2], acc[mf][nfr][3]);
                hA = silu_h2(__hadd2(hA, h2bits(b2h[nfr])));
                hB = silu_h2(__hadd2(hB, h2bits(b2h[nfr])));
                uint32_t wA = bitsh2(hA), wB = bitsh2(hB);
                uint32_t tA = __shfl_xor_sync(0xFFFFFFFFu, wA, 1);
                uint32_t tB = __shfl_xor_sync(0xFFFFFFFFu, wB, 1);
                if (evn) red2_h2(agg1 + (c0 >> 1), wA, tA);           // row m1
                else     red2_h2(agg2 + ((c0 - 2) >> 1), tB, wB);     // row m1+8
            }
        }
    }
}

// ---------------------------------------------------------------------------
// Kernel 4: node model + residual, persistent. 128 rows/tile.
// ldmatrix fragment loads for both GEMMs.
// ---------------------------------------------------------------------------
#define N_B1   0
#define N_B2   8704
#define N_A    17408
#define N_NB2  26112
#define N_CINV 26240
#define NODE_SMEM_BYTES ((N_CINV + 128) * 4)   // 105,472 B
#define NODE_NTILES ((Nn + 127) / 128)          // 391

__launch_bounds__(512, 1)
__global__ void node_out_kernel(const float* __restrict__ nf,
                                const float* __restrict__ n_w1,
                                const float* __restrict__ n_w2,
                                const float* __restrict__ n_b2,
                                float* __restrict__ out)
{
    uint32_t* smw = (uint32_t*)dyn_smem;
    uint32_t* B1  = smw + N_B1;
    uint32_t* B2  = smw + N_B2;
    uint32_t* A   = smw + N_A;
    float*    NB2 = (float*)(smw + N_NB2);
    uint32_t* cinvh = smw + N_CINV;

    const int tid  = threadIdx.x;
    const int wid  = tid >> 5;
    const int lane = tid & 31;
    const int gid  = lane >> 2;
    const int tig  = lane & 3;

    if (tid < 128) NB2[tid] = n_b2[tid];
    for (int idx = tid; idx < 8192; idx += 512) {
        int n = idx >> 6, p = idx & 63, k0 = p << 1;
        B1[n * PWS + p] = pack_h2(n_w1[(128 + k0) * 128 + n],
                                  n_w1[(129 + k0) * 128 + n]);
        B2[n * PWS + p] = pack_h2(n_w2[k0 * 128 + n],
                                  n_w2[(k0 + 1) * 128 + n]);
    }

    const int rg  = wid >> 1;
    const int nfh = wid & 1;
    const int m1  = rg * 16 + gid;
    const int m2  = m1 + 8;

    // tile-invariant ldmatrix addresses
    uint32_t aaddr, b1addr, b2addr;
    const uint32_t jstride = 8u * (PWS * 4);
    {
        int lsub = lane >> 3;
        int arow = rg * 16 + (lsub & 1) * 8 + (lane & 7);
        aaddr = (uint32_t)__cvta_generic_to_shared(A)
              + arow * (PWS * 4) + (lsub >> 1) * 16;
        int brow = nfh * 64 + (lane & 7);
        uint32_t boff = brow * (PWS * 4) + (lsub & 1) * 16;
        b1addr = (uint32_t)__cvta_generic_to_shared(B1) + boff;
        b2addr = (uint32_t)__cvta_generic_to_shared(B2) + boff;
    }

    for (int tile = blockIdx.x; tile < NODE_NTILES; tile += gridDim.x) {
        const int row0 = tile * 128;
        __syncthreads();
        if (tid < 128) {
            int row = row0 + tid;
            float ci = (row < Nn) ? 1.0f / fmaxf((float)g_cnt[row], 1.0f) : 0.0f;
            cinvh[tid] = pack_h2(ci, ci);
        }
        __syncthreads();

        for (int idx = tid; idx < 8192; idx += 512) {
            int m = idx >> 6, p = idx & 63;
            int row = row0 + m;
            uint32_t w = 0u;
            if (row < Nn) {
                uint32_t av = g_agg16[row * 64 + p];
                w = bitsh2(__hmul2(h2bits(av), h2bits(cinvh[m])));
            }
            A[m * PWS + p] = w;
        }
        __syncthreads();

        float acc[8][4];
#pragma unroll
        for (int j = 0; j < 8; j++)
#pragma unroll
            for (int q = 0; q < 4; q++) acc[j][q] = 0.0f;
#pragma unroll
        for (int ks = 0; ks < 8; ks++) {
            uint32_t a[4];
            ldsm_x4(a, aaddr + ks * 32);
#pragma unroll
            for (int j = 0; j < 8; j++) {
                uint32_t b[2];
                ldsm_x2(b, b1addr + j * jstride + ks * 32);
                mma16816h(acc[j], a, b);
            }
        }
        __syncthreads();

        const int row1 = row0 + m1, row2 = row0 + m2;
#pragma unroll
        for (int j = 0; j < 8; j++) {
            const int col = (nfh * 8 + j) * 8 + tig * 2;
            const int p = col >> 1;
            float2 pc1 = make_float2(0.0f, 0.0f), pc2 = make_float2(0.0f, 0.0f);
            if (row1 < Nn) pc1 = *(const float2*)(g_Pc + row1 * 128 + col);
            if (row2 < Nn) pc2 = *(const float2*)(g_Pc + row2 * 128 + col);
            A[m1 * PWS + p] = pack_h2(silu_f(acc[j][0] + pc1.x),
                                      silu_f(acc[j][1] + pc1.y));
            A[m2 * PWS + p] = pack_h2(silu_f(acc[j][2] + pc2.x),
                                      silu_f(acc[j][3] + pc2.y));
        }
        __syncthreads();

        float acc2[8][4];
#pragma unroll
        for (int j = 0; j < 8; j++)
#pragma unroll
            for (int q = 0; q < 4; q++) acc2[j][q] = 0.0f;
#pragma unroll
        for (int ks = 0; ks < 8; ks++) {
            uint32_t a[4];
            ldsm_x4(a, aaddr + ks * 32);
#pragma unroll
            for (int j = 0; j < 8; j++) {
                uint32_t b[2];
                ldsm_x2(b, b2addr + j * jstride + ks * 32);
                mma16816h(acc2[j], a, b);
            }
        }

#pragma unroll
        for (int j = 0; j < 8; j++) {
            const int col = (nfh * 8 + j) * 8 + tig * 2;
            float b0 = NB2[col], b1 = NB2[col + 1];
            if (row1 < Nn) {
                const float2 x = *(const float2*)(nf + row1 * 128 + col);
                *(float2*)(out + row1 * 128 + col) =
                    make_float2(x.x + silu_f(acc2[j][0] + b0),
                                x.y + silu_f(acc2[j][1] + b1));
            }
            if (row2 < Nn) {
                const float2 x = *(const float2*)(nf + row2 * 128 + col);
                *(float2*)(out + row2 * 128 + col) =
                    make_float2(x.x + silu_f(acc2[j][2] + b0),
                                x.y + silu_f(acc2[j][3] + b1));
            }
        }
    }
}

// ---------------------------------------------------------------------------
extern "C" void kernel_launch(void* const* d_in, const int* in_sizes, int n_in,
                              void* d_out, int out_size)
{
    (void)in_sizes; (void)n_in; (void)out_size;
    const float* nf   = (const float*)d_in[0];
    const float* lat  = (const float*)d_in[2];
    const float* fd   = (const float*)d_in[3];
    const int*   ei   = (const int*)d_in[4];
    const int*   e2g  = (const int*)d_in[5];
    const float* e_w1 = (const float*)d_in[6];
    const float* e_b1 = (const float*)d_in[7];
    const float* e_w2 = (const float*)d_in[8];
    const float* e_b2 = (const float*)d_in[9];
    const float* n_w1 = (const float*)d_in[10];
    const float* n_b1 = (const float*)d_in[11];
    const float* n_w2 = (const float*)d_in[12];
    const float* n_b2 = (const float*)d_in[13];
    float* out = (float*)d_out;

    cudaFuncSetAttribute(prep_node_kernel,
                         cudaFuncAttributeMaxDynamicSharedMemorySize,
                         PREP_SMEM_BYTES);
    cudaFuncSetAttribute(edge_kernel,
                         cudaFuncAttributeMaxDynamicSharedMemorySize,
                         EDGE_SMEM_BYTES);
    cudaFuncSetAttribute(node_out_kernel,
                         cudaFuncAttributeMaxDynamicSharedMemorySize,
                         NODE_SMEM_BYTES);

    prep_node_kernel<<<148, 512, PREP_SMEM_BYTES>>>(nf, e_w1, n_w1, n_b1);
    prep_graph_kernel<<<Gg, 64>>>(lat, e_w1, e_b1);
    edge_kernel<<<296, 256, EDGE_SMEM_BYTES>>>(fd, ei, e2g, e_w1, e_w2, e_b2);
    node_out_kernel<<<148, 512, NODE_SMEM_BYTES>>>(nf, n_w1, n_w2, n_b2, out);
}